// round 4
// baseline (speedup 1.0000x reference)
#include <cuda_runtime.h>

#define NB 2
#define LQS 2048
#define LKS 2048
#define DM 1024
#define NH 16
#define HD 64

typedef unsigned long long u64;

// Scratch: Q/K/V in (n, h, l, dd) layout
__device__ float g_q[NB * NH * LQS * HD];
__device__ float g_k[NB * NH * LKS * HD];
__device__ float g_v[NB * NH * LKS * HD];
__device__ float g_scale[8];
__device__ int   g_len[8];

// ---- packed f32x2 helpers (attention) ------------------------------------
__device__ __forceinline__ u64 bcast2(float x) {
    u64 r; asm("mov.b64 %0, {%1,%1};" : "=l"(r) : "f"(x)); return r;
}
__device__ __forceinline__ void unpack2(u64 v, float& x, float& y) {
    asm("mov.b64 {%0,%1}, %2;" : "=f"(x), "=f"(y) : "l"(v));
}
__device__ __forceinline__ void ffma2(u64& d, u64 a, u64 b) {
    asm("fma.rn.f32x2 %0, %1, %2, %0;" : "+l"(d) : "l"(a), "l"(b));
}
__device__ __forceinline__ void fmul2(u64& d, u64 a) {
    asm("mul.rn.f32x2 %0, %0, %1;" : "+l"(d) : "l"(a));
}

// ---- tf32 mma helpers -----------------------------------------------------
__device__ __forceinline__ unsigned f2tf(float v) {
    unsigned r; asm("cvt.rna.tf32.f32 %0, %1;" : "=r"(r) : "f"(v)); return r;
}
__device__ __forceinline__ void mma_tf32(float d[4], const unsigned a[4],
                                         const unsigned b[2]) {
    asm volatile(
        "mma.sync.aligned.m16n8k8.row.col.f32.tf32.tf32.f32 "
        "{%0,%1,%2,%3}, {%4,%5,%6,%7}, {%8,%9}, {%0,%1,%2,%3};"
        : "+f"(d[0]), "+f"(d[1]), "+f"(d[2]), "+f"(d[3])
        : "r"(a[0]), "r"(a[1]), "r"(a[2]), "r"(a[3]), "r"(b[0]), "r"(b[1]));
}

// ---------------------------------------------------------------------------
// Count valid keys per batch
// ---------------------------------------------------------------------------
__global__ void count_kernel(const int* __restrict__ pad) {
    int n = blockIdx.x;
    __shared__ int cnt;
    if (threadIdx.x == 0) cnt = 0;
    __syncthreads();
    int c = 0;
    for (int i = threadIdx.x; i < LKS; i += blockDim.x)
        if (pad[n * LKS + i] == 0) c++;
    atomicAdd(&cnt, c);
    __syncthreads();
    if (threadIdx.x == 0) {
        g_len[n] = cnt;
        g_scale[n] = rsqrtf((float)cnt);
    }
}

// ---------------------------------------------------------------------------
// Projection GEMM via tf32 mma.sync: Y = X @ W^T.
// Block tile 128x128x32, 256 thr = 8 warps (4m x 2n), warp tile 32x64.
// Smem holds tf32-converted operands; pad-36 stride -> conflict-free frags.
// ---------------------------------------------------------------------------
#define PKP 36
__global__ void __launch_bounds__(256) proj_mma(
    const float* __restrict__ X, const float* __restrict__ W,
    float* __restrict__ Y) {
    __shared__ unsigned As[128][PKP];
    __shared__ unsigned Bs[128][PKP];

    const int bm = blockIdx.y * 128;
    const int bn = blockIdx.x * 128;
    const int tid = threadIdx.x;
    const int lane = tid & 31;
    const int wid = tid >> 5;
    const int wm = (wid & 3) * 32;   // warp m offset
    const int wn = (wid >> 2) * 64;  // warp n offset

    float d[2][8][4];
#pragma unroll
    for (int mi = 0; mi < 2; mi++)
#pragma unroll
        for (int ni = 0; ni < 8; ni++)
#pragma unroll
            for (int q = 0; q < 4; q++) d[mi][ni][q] = 0.f;

    const int lrow = tid >> 3;        // 0..31 (base row for loads)
    const int lc4 = (tid & 7) * 4;    // float4 col offset 0..28

    for (int k0 = 0; k0 < DM; k0 += 32) {
#pragma unroll
        for (int q = 0; q < 4; q++) {
            int row = lrow + q * 32;
            float4 xv = *(const float4*)&X[(size_t)(bm + row) * DM + k0 + lc4];
            float4 wv = *(const float4*)&W[(size_t)(bn + row) * DM + k0 + lc4];
            As[row][lc4 + 0] = f2tf(xv.x); As[row][lc4 + 1] = f2tf(xv.y);
            As[row][lc4 + 2] = f2tf(xv.z); As[row][lc4 + 3] = f2tf(xv.w);
            Bs[row][lc4 + 0] = f2tf(wv.x); Bs[row][lc4 + 1] = f2tf(wv.y);
            Bs[row][lc4 + 2] = f2tf(wv.z); Bs[row][lc4 + 3] = f2tf(wv.w);
        }
        __syncthreads();

        const int r = lane >> 2, c = lane & 3;
#pragma unroll
        for (int kk = 0; kk < 32; kk += 8) {
            unsigned a[2][4], b[8][2];
#pragma unroll
            for (int mi = 0; mi < 2; mi++) {
                int rb = wm + mi * 16;
                a[mi][0] = As[rb + r][kk + c];
                a[mi][1] = As[rb + r + 8][kk + c];
                a[mi][2] = As[rb + r][kk + c + 4];
                a[mi][3] = As[rb + r + 8][kk + c + 4];
            }
#pragma unroll
            for (int ni = 0; ni < 8; ni++) {
                int cb = wn + ni * 8;
                b[ni][0] = Bs[cb + r][kk + c];
                b[ni][1] = Bs[cb + r][kk + c + 4];
            }
#pragma unroll
            for (int mi = 0; mi < 2; mi++)
#pragma unroll
                for (int ni = 0; ni < 8; ni++)
                    mma_tf32(d[mi][ni], a[mi], b[ni]);
        }
        __syncthreads();
    }

    // epilogue: scatter C fragments to (n, h, l, dd)
#pragma unroll
    for (int mi = 0; mi < 2; mi++) {
#pragma unroll
        for (int ni = 0; ni < 8; ni++) {
            int m0 = bm + wm + mi * 16 + (lane >> 2);
            int col = bn + wn + ni * 8 + (lane & 3) * 2;
            int n = m0 >> 11;
            int h = col >> 6;
            int dd = col & 63;
            int l0 = m0 & (LQS - 1);
            float* y0 = &Y[((size_t)((n * NH + h) * LQS) + l0) * HD + dd];
            float* y1 = &Y[((size_t)((n * NH + h) * LQS) + l0 + 8) * HD + dd];
            *(float2*)y0 = make_float2(d[mi][ni][0], d[mi][ni][1]);
            *(float2*)y1 = make_float2(d[mi][ni][2], d[mi][ni][3]);
        }
    }
}

// ---------------------------------------------------------------------------
// Flash attention (fp32 scalar/f32x2) — unchanged from R3 passing version.
// ---------------------------------------------------------------------------
__global__ void __launch_bounds__(256) attn_kernel(
    const int* __restrict__ pad, float* __restrict__ out) {
    extern __shared__ float smdyn[];
    float (*Qs)[68] = (float(*)[68])smdyn;
    float (*Ks)[68] = (float(*)[68])(smdyn + 64 * 68);
    float (*Vs)[68] = (float(*)[68])(smdyn + 2 * 64 * 68);
    __shared__ int pm[64];

    const int qt = blockIdx.x;
    const int h = blockIdx.y;
    const int n = blockIdx.z;
    const int tid = threadIdx.x;
    const int r0 = (tid >> 4) * 4;
    const int c0 = (tid & 15) * 4;

    const float* qbase = g_q + ((size_t)(n * NH + h) * LQS + qt * 64) * HD;
    for (int idx = tid; idx < 64 * 64; idx += 256) {
        int r = idx >> 6, dd = idx & 63;
        Qs[dd][r] = qbase[r * HD + dd];
    }

    const float sc = g_scale[n];
    const int len = g_len[n];
    const int ktmax = min(qt, (len - 1) >> 6);

    float mrow[4], lrow[4];
    u64 O[4][2];
#pragma unroll
    for (int i = 0; i < 4; i++) {
        mrow[i] = -1e30f; lrow[i] = 0.f;
        O[i][0] = 0ull; O[i][1] = 0ull;
    }

    for (int kt = 0; kt <= ktmax; kt++) {
        const float* kbase = g_k + ((size_t)(n * NH + h) * LKS + kt * 64) * HD;
        const float* vbase = g_v + ((size_t)(n * NH + h) * LKS + kt * 64) * HD;
        __syncthreads();
        for (int idx = tid; idx < 64 * 64; idx += 256) {
            int r = idx >> 6, dd = idx & 63;
            Ks[dd][r] = kbase[r * HD + dd];
            Vs[r][dd] = vbase[r * HD + dd];
        }
        if (tid < 64) pm[tid] = pad[n * LKS + kt * 64 + tid];
        __syncthreads();

        u64 Sp[4][2];
#pragma unroll
        for (int i = 0; i < 4; i++) { Sp[i][0] = 0ull; Sp[i][1] = 0ull; }
#pragma unroll 4
        for (int kk = 0; kk < 64; kk++) {
            float4 qv = *(const float4*)&Qs[kk][r0];
            ulonglong2 kv = *(const ulonglong2*)&Ks[kk][c0];
            u64 q0 = bcast2(qv.x), q1 = bcast2(qv.y),
                q2 = bcast2(qv.z), q3 = bcast2(qv.w);
            ffma2(Sp[0][0], q0, kv.x); ffma2(Sp[0][1], q0, kv.y);
            ffma2(Sp[1][0], q1, kv.x); ffma2(Sp[1][1], q1, kv.y);
            ffma2(Sp[2][0], q2, kv.x); ffma2(Sp[2][1], q2, kv.y);
            ffma2(Sp[3][0], q3, kv.x); ffma2(Sp[3][1], q3, kv.y);
        }
        float S[4][4];
#pragma unroll
        for (int i = 0; i < 4; i++) {
            unpack2(Sp[i][0], S[i][0], S[i][1]);
            unpack2(Sp[i][1], S[i][2], S[i][3]);
        }

        const int qg0 = qt * 64 + r0;
        const int kg0 = kt * 64 + c0;
        float tmax[4];
#pragma unroll
        for (int i = 0; i < 4; i++) {
            tmax[i] = -1e30f;
#pragma unroll
            for (int j = 0; j < 4; j++) {
                bool masked = (kg0 + j > qg0 + i) || (pm[c0 + j] != 0);
                float v = masked ? -1e30f : S[i][j] * sc;
                S[i][j] = v;
                tmax[i] = fmaxf(tmax[i], v);
            }
        }
#pragma unroll
        for (int off = 8; off >= 1; off >>= 1)
#pragma unroll
            for (int i = 0; i < 4; i++)
                tmax[i] = fmaxf(tmax[i],
                    __shfl_xor_sync(0xffffffffu, tmax[i], off, 16));

        float alpha[4], rsum[4];
#pragma unroll
        for (int i = 0; i < 4; i++) {
            float nm = fmaxf(mrow[i], tmax[i]);
            alpha[i] = __expf(mrow[i] - nm);
            mrow[i] = nm;
            float s_ = 0.f;
#pragma unroll
            for (int j = 0; j < 4; j++) {
                float p = __expf(S[i][j] - nm);
                S[i][j] = p;
                s_ += p;
            }
            rsum[i] = s_;
        }
#pragma unroll
        for (int off = 8; off >= 1; off >>= 1)
#pragma unroll
            for (int i = 0; i < 4; i++)
                rsum[i] += __shfl_xor_sync(0xffffffffu, rsum[i], off, 16);
#pragma unroll
        for (int i = 0; i < 4; i++) {
            lrow[i] = lrow[i] * alpha[i] + rsum[i];
            u64 ap = bcast2(alpha[i]);
            fmul2(O[i][0], ap);
            fmul2(O[i][1], ap);
        }

        __syncthreads();
#pragma unroll
        for (int j = 0; j < 4; j++)
#pragma unroll
            for (int i = 0; i < 4; i++)
                Ks[c0 + j][r0 + i] = S[i][j];
        __syncthreads();

#pragma unroll 4
        for (int kk = 0; kk < 64; kk++) {
            float4 pv = *(const float4*)&Ks[kk][r0];
            ulonglong2 vv = *(const ulonglong2*)&Vs[kk][c0];
            u64 p0 = bcast2(pv.x), p1 = bcast2(pv.y),
                p2 = bcast2(pv.z), p3 = bcast2(pv.w);
            ffma2(O[0][0], p0, vv.x); ffma2(O[0][1], p0, vv.y);
            ffma2(O[1][0], p1, vv.x); ffma2(O[1][1], p1, vv.y);
            ffma2(O[2][0], p2, vv.x); ffma2(O[2][1], p2, vv.y);
            ffma2(O[3][0], p3, vv.x); ffma2(O[3][1], p3, vv.y);
        }
    }

#pragma unroll
    for (int i = 0; i < 4; i++) {
        float inv = 1.f / lrow[i];
        int qg = qt * 64 + r0 + i;
        float* op = out + ((size_t)n * LQS + qg) * DM + h * HD + c0;
        float o0, o1, o2, o3;
        unpack2(O[i][0], o0, o1);
        unpack2(O[i][1], o2, o3);
        op[0] = o0 * inv;
        op[1] = o1 * inv;
        op[2] = o2 * inv;
        op[3] = o3 * inv;
    }
}

// ---------------------------------------------------------------------------
extern "C" void kernel_launch(void* const* d_in, const int* in_sizes, int n_in,
                              void* d_out, int out_size) {
    const float* query = (const float*)d_in[0];
    const float* key   = (const float*)d_in[1];
    const float* Wq    = (const float*)d_in[2];
    const float* Wk    = (const float*)d_in[3];
    const float* Wv    = (const float*)d_in[4];
    const int* pad     = (const int*)d_in[6];   // bool -> int32
    float* out = (float*)d_out;

    const int attn_smem = 3 * 64 * 68 * 4;  // 52224 B
    cudaFuncSetAttribute(attn_kernel,
                         cudaFuncAttributeMaxDynamicSharedMemorySize, attn_smem);

    void *pq, *pk, *pv;
    cudaGetSymbolAddress(&pq, g_q);
    cudaGetSymbolAddress(&pk, g_k);
    cudaGetSymbolAddress(&pv, g_v);

    count_kernel<<<NB, 256>>>(pad);

    dim3 pg(DM / 128, (NB * LQS) / 128);  // (8, 32)
    proj_mma<<<pg, 256>>>(query, Wq, (float*)pq);
    proj_mma<<<pg, 256>>>(key,   Wk, (float*)pk);
    proj_mma<<<pg, 256>>>(key,   Wv, (float*)pv);

    dim3 ag(LQS / 64, NH, NB);  // (32, 16, 2)
    attn_kernel<<<ag, 256, attn_smem>>>(pad, out);
}

// round 5
// speedup vs baseline: 1.6686x; 1.6686x over previous
#include <cuda_runtime.h>

#define NB 2
#define LQS 2048
#define LKS 2048
#define DM 1024
#define NH 16
#define HD 64

// Scratch: Q/K/V in (n, h, l, dd) layout
__device__ float g_q[NB * NH * LQS * HD];
__device__ float g_k[NB * NH * LKS * HD];
__device__ float g_v[NB * NH * LKS * HD];
__device__ float g_scale[8];
__device__ int   g_len[8];

// ---- tf32 mma helpers -----------------------------------------------------
__device__ __forceinline__ unsigned f2tf(float v) {
    unsigned r; asm("cvt.rna.tf32.f32 %0, %1;" : "=r"(r) : "f"(v)); return r;
}
__device__ __forceinline__ void mma_tf32(float d[4], const unsigned a[4],
                                         const unsigned b[2]) {
    asm volatile(
        "mma.sync.aligned.m16n8k8.row.col.f32.tf32.tf32.f32 "
        "{%0,%1,%2,%3}, {%4,%5,%6,%7}, {%8,%9}, {%0,%1,%2,%3};"
        : "+f"(d[0]), "+f"(d[1]), "+f"(d[2]), "+f"(d[3])
        : "r"(a[0]), "r"(a[1]), "r"(a[2]), "r"(a[3]), "r"(b[0]), "r"(b[1]));
}

// ---------------------------------------------------------------------------
// Count valid keys per batch
// ---------------------------------------------------------------------------
__global__ void count_kernel(const int* __restrict__ pad) {
    int n = blockIdx.x;
    __shared__ int cnt;
    if (threadIdx.x == 0) cnt = 0;
    __syncthreads();
    int c = 0;
    for (int i = threadIdx.x; i < LKS; i += blockDim.x)
        if (pad[n * LKS + i] == 0) c++;
    atomicAdd(&cnt, c);
    __syncthreads();
    if (threadIdx.x == 0) {
        g_len[n] = cnt;
        g_scale[n] = rsqrtf((float)cnt);
    }
}

// ---------------------------------------------------------------------------
// Projection GEMM via tf32 mma.sync: Y = X @ W^T (unchanged from R4).
// ---------------------------------------------------------------------------
#define PKP 36
__global__ void __launch_bounds__(256) proj_mma(
    const float* __restrict__ X, const float* __restrict__ W,
    float* __restrict__ Y) {
    __shared__ unsigned As[128][PKP];
    __shared__ unsigned Bs[128][PKP];

    const int bm = blockIdx.y * 128;
    const int bn = blockIdx.x * 128;
    const int tid = threadIdx.x;
    const int lane = tid & 31;
    const int wid = tid >> 5;
    const int wm = (wid & 3) * 32;
    const int wn = (wid >> 2) * 64;

    float d[2][8][4];
#pragma unroll
    for (int mi = 0; mi < 2; mi++)
#pragma unroll
        for (int ni = 0; ni < 8; ni++)
#pragma unroll
            for (int q = 0; q < 4; q++) d[mi][ni][q] = 0.f;

    const int lrow = tid >> 3;
    const int lc4 = (tid & 7) * 4;

    for (int k0 = 0; k0 < DM; k0 += 32) {
#pragma unroll
        for (int q = 0; q < 4; q++) {
            int row = lrow + q * 32;
            float4 xv = *(const float4*)&X[(size_t)(bm + row) * DM + k0 + lc4];
            float4 wv = *(const float4*)&W[(size_t)(bn + row) * DM + k0 + lc4];
            As[row][lc4 + 0] = f2tf(xv.x); As[row][lc4 + 1] = f2tf(xv.y);
            As[row][lc4 + 2] = f2tf(xv.z); As[row][lc4 + 3] = f2tf(xv.w);
            Bs[row][lc4 + 0] = f2tf(wv.x); Bs[row][lc4 + 1] = f2tf(wv.y);
            Bs[row][lc4 + 2] = f2tf(wv.z); Bs[row][lc4 + 3] = f2tf(wv.w);
        }
        __syncthreads();

        const int r = lane >> 2, c = lane & 3;
#pragma unroll
        for (int kk = 0; kk < 32; kk += 8) {
            unsigned a[2][4], b[8][2];
#pragma unroll
            for (int mi = 0; mi < 2; mi++) {
                int rb = wm + mi * 16;
                a[mi][0] = As[rb + r][kk + c];
                a[mi][1] = As[rb + r + 8][kk + c];
                a[mi][2] = As[rb + r][kk + c + 4];
                a[mi][3] = As[rb + r + 8][kk + c + 4];
            }
#pragma unroll
            for (int ni = 0; ni < 8; ni++) {
                int cb = wn + ni * 8;
                b[ni][0] = Bs[cb + r][kk + c];
                b[ni][1] = Bs[cb + r][kk + c + 4];
            }
#pragma unroll
            for (int mi = 0; mi < 2; mi++)
#pragma unroll
                for (int ni = 0; ni < 8; ni++)
                    mma_tf32(d[mi][ni], a[mi], b[ni]);
        }
        __syncthreads();
    }

#pragma unroll
    for (int mi = 0; mi < 2; mi++) {
#pragma unroll
        for (int ni = 0; ni < 8; ni++) {
            int m0 = bm + wm + mi * 16 + (lane >> 2);
            int col = bn + wn + ni * 8 + (lane & 3) * 2;
            int n = m0 >> 11;
            int h = col >> 6;
            int dd = col & 63;
            int l0 = m0 & (LQS - 1);
            float* y0 = &Y[((size_t)((n * NH + h) * LQS) + l0) * HD + dd];
            float* y1 = &Y[((size_t)((n * NH + h) * LQS) + l0 + 8) * HD + dd];
            *(float2*)y0 = make_float2(d[mi][ni][0], d[mi][ni][1]);
            *(float2*)y1 = make_float2(d[mi][ni][2], d[mi][ni][3]);
        }
    }
}

// ---------------------------------------------------------------------------
// Flash attention via tf32 mma: block = (64-q tile, head, batch), 128 thr,
// 4 warps; warp owns 16 q rows. Smem tf32 tiles, pad-68 stride.
// ---------------------------------------------------------------------------
#define AP 68
__global__ void __launch_bounds__(128) attn_mma(
    const int* __restrict__ pad, float* __restrict__ out) {
    extern __shared__ unsigned smu[];
    unsigned (*Qs)[AP] = (unsigned(*)[AP])smu;               // [q][d]
    unsigned (*Ks)[AP] = (unsigned(*)[AP])(smu + 64 * AP);   // [key][d]
    unsigned (*Vt)[AP] = (unsigned(*)[AP])(smu + 2 * 64 * AP); // [d][key]
    unsigned (*Ps)[AP] = (unsigned(*)[AP])(smu + 3 * 64 * AP); // [q][key]
    __shared__ int pm[64];

    const int qt = blockIdx.x;
    const int h = blockIdx.y;
    const int n = blockIdx.z;
    const int tid = threadIdx.x;
    const int lane = tid & 31;
    const int w = tid >> 5;
    const int wq0 = w * 16;
    const int r = lane >> 2;
    const int c = lane & 3;

    // stage Q (tf32)
    const float* qbase = g_q + ((size_t)(n * NH + h) * LQS + qt * 64) * HD;
    for (int it = 0; it < 8; it++) {
        int e4 = tid + it * 128;           // float4 index
        int q = e4 >> 4, d4 = (e4 & 15) * 4;
        float4 v = *(const float4*)&qbase[q * HD + d4];
        Qs[q][d4 + 0] = f2tf(v.x); Qs[q][d4 + 1] = f2tf(v.y);
        Qs[q][d4 + 2] = f2tf(v.z); Qs[q][d4 + 3] = f2tf(v.w);
    }

    const float sc = g_scale[n];
    const int len = g_len[n];
    const int ktmax = min(qt, (len - 1) >> 6);

    const int row0 = qt * 64 + wq0 + r;   // global q row for c0,c1
    const int row1 = row0 + 8;            // for c2,c3

    float m0 = -1e30f, m1 = -1e30f, l0 = 0.f, l1 = 0.f;
    float o[8][4];
#pragma unroll
    for (int ni = 0; ni < 8; ni++)
#pragma unroll
        for (int q = 0; q < 4; q++) o[ni][q] = 0.f;

    for (int kt = 0; kt <= ktmax; kt++) {
        const float* kbase = g_k + ((size_t)(n * NH + h) * LKS + kt * 64) * HD;
        const float* vbase = g_v + ((size_t)(n * NH + h) * LKS + kt * 64) * HD;
        __syncthreads();   // prev iteration done with Ks/Vt
        for (int it = 0; it < 8; it++) {
            int e4 = tid + it * 128;
            int k = e4 >> 4, d4 = (e4 & 15) * 4;
            float4 kv = *(const float4*)&kbase[k * HD + d4];
            float4 vv = *(const float4*)&vbase[k * HD + d4];
            Ks[k][d4 + 0] = f2tf(kv.x); Ks[k][d4 + 1] = f2tf(kv.y);
            Ks[k][d4 + 2] = f2tf(kv.z); Ks[k][d4 + 3] = f2tf(kv.w);
            Vt[d4 + 0][k] = f2tf(vv.x); Vt[d4 + 1][k] = f2tf(vv.y);
            Vt[d4 + 2][k] = f2tf(vv.z); Vt[d4 + 3][k] = f2tf(vv.w);
        }
        if (tid < 64) pm[tid] = pad[n * LKS + kt * 64 + tid];
        __syncthreads();

        // S = Q K^T : warp tile 16x64
        float s[8][4];
#pragma unroll
        for (int ni = 0; ni < 8; ni++)
#pragma unroll
            for (int q = 0; q < 4; q++) s[ni][q] = 0.f;
#pragma unroll
        for (int kk = 0; kk < 64; kk += 8) {
            unsigned a[4];
            a[0] = Qs[wq0 + r][kk + c];
            a[1] = Qs[wq0 + r + 8][kk + c];
            a[2] = Qs[wq0 + r][kk + c + 4];
            a[3] = Qs[wq0 + r + 8][kk + c + 4];
#pragma unroll
            for (int ni = 0; ni < 8; ni++) {
                unsigned b[2];
                b[0] = Ks[ni * 8 + r][kk + c];
                b[1] = Ks[ni * 8 + r][kk + c + 4];
                mma_tf32(s[ni], a, b);
            }
        }

        // mask + scale + online softmax on fragments
        float tmax0 = -1e30f, tmax1 = -1e30f;
#pragma unroll
        for (int ni = 0; ni < 8; ni++) {
            int kg = kt * 64 + ni * 8 + c * 2;
            bool pm0 = pm[ni * 8 + c * 2] != 0;
            bool pm1 = pm[ni * 8 + c * 2 + 1] != 0;
            float v0 = (kg > row0 || pm0) ? -1e30f : s[ni][0] * sc;
            float v1 = (kg + 1 > row0 || pm1) ? -1e30f : s[ni][1] * sc;
            float v2 = (kg > row1 || pm0) ? -1e30f : s[ni][2] * sc;
            float v3 = (kg + 1 > row1 || pm1) ? -1e30f : s[ni][3] * sc;
            s[ni][0] = v0; s[ni][1] = v1; s[ni][2] = v2; s[ni][3] = v3;
            tmax0 = fmaxf(tmax0, fmaxf(v0, v1));
            tmax1 = fmaxf(tmax1, fmaxf(v2, v3));
        }
        tmax0 = fmaxf(tmax0, __shfl_xor_sync(0xffffffffu, tmax0, 1));
        tmax0 = fmaxf(tmax0, __shfl_xor_sync(0xffffffffu, tmax0, 2));
        tmax1 = fmaxf(tmax1, __shfl_xor_sync(0xffffffffu, tmax1, 1));
        tmax1 = fmaxf(tmax1, __shfl_xor_sync(0xffffffffu, tmax1, 2));

        float nm0 = fmaxf(m0, tmax0), nm1 = fmaxf(m1, tmax1);
        float a0 = __expf(m0 - nm0), a1 = __expf(m1 - nm1);
        m0 = nm0; m1 = nm1;

        float rs0 = 0.f, rs1 = 0.f;
#pragma unroll
        for (int ni = 0; ni < 8; ni++) {
            float p0 = __expf(s[ni][0] - nm0);
            float p1 = __expf(s[ni][1] - nm0);
            float p2 = __expf(s[ni][2] - nm1);
            float p3 = __expf(s[ni][3] - nm1);
            rs0 += p0 + p1; rs1 += p2 + p3;
            // stage P (tf32), 8B stores
            uint2 lo = make_uint2(f2tf(p0), f2tf(p1));
            uint2 hi = make_uint2(f2tf(p2), f2tf(p3));
            *(uint2*)&Ps[wq0 + r][ni * 8 + c * 2] = lo;
            *(uint2*)&Ps[wq0 + r + 8][ni * 8 + c * 2] = hi;
#pragma unroll
            for (int q = 0; q < 2; q++) { o[ni][q] *= a0; o[ni][q + 2] *= a1; }
        }
        rs0 += __shfl_xor_sync(0xffffffffu, rs0, 1);
        rs0 += __shfl_xor_sync(0xffffffffu, rs0, 2);
        rs1 += __shfl_xor_sync(0xffffffffu, rs1, 1);
        rs1 += __shfl_xor_sync(0xffffffffu, rs1, 2);
        l0 = l0 * a0 + rs0;
        l1 = l1 * a1 + rs1;

        __syncwarp();

        // O += P V  (A = P rows of this warp only; B = Vt)
#pragma unroll
        for (int kk = 0; kk < 64; kk += 8) {
            unsigned a[4];
            a[0] = Ps[wq0 + r][kk + c];
            a[1] = Ps[wq0 + r + 8][kk + c];
            a[2] = Ps[wq0 + r][kk + c + 4];
            a[3] = Ps[wq0 + r + 8][kk + c + 4];
#pragma unroll
            for (int ni = 0; ni < 8; ni++) {
                unsigned b[2];
                b[0] = Vt[ni * 8 + r][kk + c];
                b[1] = Vt[ni * 8 + r][kk + c + 4];
                mma_tf32(o[ni], a, b);
            }
        }
    }

    // epilogue: normalize, write out (n, l, h*64+dd)
    float inv0 = 1.f / l0, inv1 = 1.f / l1;
#pragma unroll
    for (int ni = 0; ni < 8; ni++) {
        int dcol = h * HD + ni * 8 + c * 2;
        float* y0 = out + ((size_t)n * LQS + row0) * DM + dcol;
        float* y1 = out + ((size_t)n * LQS + row1) * DM + dcol;
        *(float2*)y0 = make_float2(o[ni][0] * inv0, o[ni][1] * inv0);
        *(float2*)y1 = make_float2(o[ni][2] * inv1, o[ni][3] * inv1);
    }
}

// ---------------------------------------------------------------------------
extern "C" void kernel_launch(void* const* d_in, const int* in_sizes, int n_in,
                              void* d_out, int out_size) {
    const float* query = (const float*)d_in[0];
    const float* key   = (const float*)d_in[1];
    const float* Wq    = (const float*)d_in[2];
    const float* Wk    = (const float*)d_in[3];
    const float* Wv    = (const float*)d_in[4];
    const int* pad     = (const int*)d_in[6];   // bool -> int32
    float* out = (float*)d_out;

    const int attn_smem = 4 * 64 * AP * 4;  // 69632 B
    cudaFuncSetAttribute(attn_mma,
                         cudaFuncAttributeMaxDynamicSharedMemorySize, attn_smem);

    void *pq, *pk, *pv;
    cudaGetSymbolAddress(&pq, g_q);
    cudaGetSymbolAddress(&pk, g_k);
    cudaGetSymbolAddress(&pv, g_v);

    count_kernel<<<NB, 256>>>(pad);

    dim3 pg(DM / 128, (NB * LQS) / 128);  // (8, 32)
    proj_mma<<<pg, 256>>>(query, Wq, (float*)pq);
    proj_mma<<<pg, 256>>>(key,   Wk, (float*)pk);
    proj_mma<<<pg, 256>>>(key,   Wv, (float*)pv);

    dim3 ag(LQS / 64, NH, NB);  // (32, 16, 2)
    attn_mma<<<ag, 128, attn_smem>>>(pad, out);
}

// round 6
// speedup vs baseline: 3.0143x; 1.8064x over previous
#include <cuda_runtime.h>

#define NB 2
#define LQS 2048
#define LKS 2048
#define DM 1024
#define NH 16
#define HD 64

// Scratch: Q/K/V in (n, h, l, dd) layout
__device__ float g_q[NB * NH * LQS * HD];
__device__ float g_k[NB * NH * LKS * HD];
__device__ float g_v[NB * NH * LKS * HD];
__device__ float g_scale[8];
__device__ int   g_len[8];

// ---- tf32 mma helpers -----------------------------------------------------
__device__ __forceinline__ unsigned f2tf(float v) {
    unsigned r; asm("cvt.rna.tf32.f32 %0, %1;" : "=r"(r) : "f"(v)); return r;
}
__device__ __forceinline__ void mma_tf32(float d[4], const unsigned a[4],
                                         const unsigned b[2]) {
    asm volatile(
        "mma.sync.aligned.m16n8k8.row.col.f32.tf32.tf32.f32 "
        "{%0,%1,%2,%3}, {%4,%5,%6,%7}, {%8,%9}, {%0,%1,%2,%3};"
        : "+f"(d[0]), "+f"(d[1]), "+f"(d[2]), "+f"(d[3])
        : "r"(a[0]), "r"(a[1]), "r"(a[2]), "r"(a[3]), "r"(b[0]), "r"(b[1]));
}
__device__ __forceinline__ void cp16(void* dst, const void* src) {
    unsigned d = (unsigned)__cvta_generic_to_shared(dst);
    asm volatile("cp.async.cg.shared.global [%0], [%1], 16;" :: "r"(d), "l"(src));
}
#define CP_COMMIT() asm volatile("cp.async.commit_group;" ::: "memory")
#define CP_WAIT_ALL() asm volatile("cp.async.wait_group 0;" ::: "memory")

// ---------------------------------------------------------------------------
// Count valid keys per batch
// ---------------------------------------------------------------------------
__global__ void count_kernel(const int* __restrict__ pad) {
    int n = blockIdx.x;
    __shared__ int cnt;
    if (threadIdx.x == 0) cnt = 0;
    __syncthreads();
    int c = 0;
    for (int i = threadIdx.x; i < LKS; i += blockDim.x)
        if (pad[n * LKS + i] == 0) c++;
    atomicAdd(&cnt, c);
    __syncthreads();
    if (threadIdx.x == 0) {
        g_len[n] = cnt;
        g_scale[n] = rsqrtf((float)cnt);
    }
}

// ---------------------------------------------------------------------------
// Fused projection GEMMs via tf32 mma + cp.async double buffering.
// blockIdx.z selects (X, W, Y): 0=(query,Wq,gq) 1=(key,Wk,gk) 2=(key,Wv,gv).
// Block tile 128x128x32, 256 thr = 8 warps (4m x 2n). Smem holds raw fp32;
// tf32 conversion happens at fragment load. One syncthreads per k-tile.
// ---------------------------------------------------------------------------
#define PKP 36
__global__ void __launch_bounds__(256) proj_mma(
    const float* __restrict__ query, const float* __restrict__ key,
    const float* __restrict__ Wq, const float* __restrict__ Wk,
    const float* __restrict__ Wv,
    float* __restrict__ gq, float* __restrict__ gk, float* __restrict__ gv) {
    extern __shared__ float sm[];
    float (*As)[128][PKP] = (float(*)[128][PKP])sm;                 // [2][128][PKP]
    float (*Bs)[128][PKP] = (float(*)[128][PKP])(sm + 2 * 128 * PKP);

    const int z = blockIdx.z;
    const float* X = (z == 0) ? query : key;
    const float* W = (z == 0) ? Wq : (z == 1) ? Wk : Wv;
    float* Y = (z == 0) ? gq : (z == 1) ? gk : gv;

    const int bm = blockIdx.y * 128;
    const int bn = blockIdx.x * 128;
    const int tid = threadIdx.x;
    const int lane = tid & 31;
    const int wid = tid >> 5;
    const int wm = (wid & 3) * 32;
    const int wn = (wid >> 2) * 64;

    float d[2][8][4];
#pragma unroll
    for (int mi = 0; mi < 2; mi++)
#pragma unroll
        for (int ni = 0; ni < 8; ni++)
#pragma unroll
            for (int q = 0; q < 4; q++) d[mi][ni][q] = 0.f;

    const int lrow = tid >> 3;        // 0..31
    const int lc4 = (tid & 7) * 4;    // 0,4,...,28

    // prefetch tile 0
#pragma unroll
    for (int q = 0; q < 4; q++) {
        int row = lrow + q * 32;
        cp16(&As[0][row][lc4], &X[(size_t)(bm + row) * DM + lc4]);
        cp16(&Bs[0][row][lc4], &W[(size_t)(bn + row) * DM + lc4]);
    }
    CP_COMMIT();

    const int nt = DM / 32;           // 32 tiles
    const int r = lane >> 2, c = lane & 3;

    for (int t = 0; t < nt; t++) {
        const int cur = t & 1;
        CP_WAIT_ALL();
        __syncthreads();
        if (t + 1 < nt) {
            const int nxt = cur ^ 1;
            const int k0 = (t + 1) * 32;
#pragma unroll
            for (int q = 0; q < 4; q++) {
                int row = lrow + q * 32;
                cp16(&As[nxt][row][lc4], &X[(size_t)(bm + row) * DM + k0 + lc4]);
                cp16(&Bs[nxt][row][lc4], &W[(size_t)(bn + row) * DM + k0 + lc4]);
            }
            CP_COMMIT();
        }
#pragma unroll
        for (int kk = 0; kk < 32; kk += 8) {
            unsigned a[2][4], b[8][2];
#pragma unroll
            for (int mi = 0; mi < 2; mi++) {
                int rb = wm + mi * 16;
                a[mi][0] = f2tf(As[cur][rb + r][kk + c]);
                a[mi][1] = f2tf(As[cur][rb + r + 8][kk + c]);
                a[mi][2] = f2tf(As[cur][rb + r][kk + c + 4]);
                a[mi][3] = f2tf(As[cur][rb + r + 8][kk + c + 4]);
            }
#pragma unroll
            for (int ni = 0; ni < 8; ni++) {
                int cb = wn + ni * 8;
                b[ni][0] = f2tf(Bs[cur][cb + r][kk + c]);
                b[ni][1] = f2tf(Bs[cur][cb + r][kk + c + 4]);
            }
#pragma unroll
            for (int mi = 0; mi < 2; mi++)
#pragma unroll
                for (int ni = 0; ni < 8; ni++)
                    mma_tf32(d[mi][ni], a[mi], b[ni]);
        }
    }

    // epilogue: scatter C fragments to (n, h, l, dd)
#pragma unroll
    for (int mi = 0; mi < 2; mi++) {
#pragma unroll
        for (int ni = 0; ni < 8; ni++) {
            int m0 = bm + wm + mi * 16 + (lane >> 2);
            int col = bn + wn + ni * 8 + (lane & 3) * 2;
            int n = m0 >> 11;
            int h = col >> 6;
            int dd = col & 63;
            int l0 = m0 & (LQS - 1);
            float* y0 = &Y[((size_t)((n * NH + h) * LQS) + l0) * HD + dd];
            float* y1 = &Y[((size_t)((n * NH + h) * LQS) + l0 + 8) * HD + dd];
            *(float2*)y0 = make_float2(d[mi][ni][0], d[mi][ni][1]);
            *(float2*)y1 = make_float2(d[mi][ni][2], d[mi][ni][3]);
        }
    }
}

// ---------------------------------------------------------------------------
// Flash attention via tf32 mma (unchanged from R5 passing version).
// ---------------------------------------------------------------------------
#define AP 68
__global__ void __launch_bounds__(128) attn_mma(
    const int* __restrict__ pad, float* __restrict__ out) {
    extern __shared__ unsigned smu[];
    unsigned (*Qs)[AP] = (unsigned(*)[AP])smu;                 // [q][d]
    unsigned (*Ks)[AP] = (unsigned(*)[AP])(smu + 64 * AP);     // [key][d]
    unsigned (*Vt)[AP] = (unsigned(*)[AP])(smu + 2 * 64 * AP); // [d][key]
    unsigned (*Ps)[AP] = (unsigned(*)[AP])(smu + 3 * 64 * AP); // [q][key]
    __shared__ int pm[64];

    const int qt = blockIdx.x;
    const int h = blockIdx.y;
    const int n = blockIdx.z;
    const int tid = threadIdx.x;
    const int lane = tid & 31;
    const int w = tid >> 5;
    const int wq0 = w * 16;
    const int r = lane >> 2;
    const int c = lane & 3;

    const float* qbase = g_q + ((size_t)(n * NH + h) * LQS + qt * 64) * HD;
    for (int it = 0; it < 8; it++) {
        int e4 = tid + it * 128;
        int q = e4 >> 4, d4 = (e4 & 15) * 4;
        float4 v = *(const float4*)&qbase[q * HD + d4];
        Qs[q][d4 + 0] = f2tf(v.x); Qs[q][d4 + 1] = f2tf(v.y);
        Qs[q][d4 + 2] = f2tf(v.z); Qs[q][d4 + 3] = f2tf(v.w);
    }

    const float sc = g_scale[n];
    const int len = g_len[n];
    const int ktmax = min(qt, (len - 1) >> 6);

    const int row0 = qt * 64 + wq0 + r;
    const int row1 = row0 + 8;

    float m0 = -1e30f, m1 = -1e30f, l0 = 0.f, l1 = 0.f;
    float o[8][4];
#pragma unroll
    for (int ni = 0; ni < 8; ni++)
#pragma unroll
        for (int q = 0; q < 4; q++) o[ni][q] = 0.f;

    for (int kt = 0; kt <= ktmax; kt++) {
        const float* kbase = g_k + ((size_t)(n * NH + h) * LKS + kt * 64) * HD;
        const float* vbase = g_v + ((size_t)(n * NH + h) * LKS + kt * 64) * HD;
        __syncthreads();
        for (int it = 0; it < 8; it++) {
            int e4 = tid + it * 128;
            int k = e4 >> 4, d4 = (e4 & 15) * 4;
            float4 kv = *(const float4*)&kbase[k * HD + d4];
            float4 vv = *(const float4*)&vbase[k * HD + d4];
            Ks[k][d4 + 0] = f2tf(kv.x); Ks[k][d4 + 1] = f2tf(kv.y);
            Ks[k][d4 + 2] = f2tf(kv.z); Ks[k][d4 + 3] = f2tf(kv.w);
            Vt[d4 + 0][k] = f2tf(vv.x); Vt[d4 + 1][k] = f2tf(vv.y);
            Vt[d4 + 2][k] = f2tf(vv.z); Vt[d4 + 3][k] = f2tf(vv.w);
        }
        if (tid < 64) pm[tid] = pad[n * LKS + kt * 64 + tid];
        __syncthreads();

        float s[8][4];
#pragma unroll
        for (int ni = 0; ni < 8; ni++)
#pragma unroll
            for (int q = 0; q < 4; q++) s[ni][q] = 0.f;
#pragma unroll
        for (int kk = 0; kk < 64; kk += 8) {
            unsigned a[4];
            a[0] = Qs[wq0 + r][kk + c];
            a[1] = Qs[wq0 + r + 8][kk + c];
            a[2] = Qs[wq0 + r][kk + c + 4];
            a[3] = Qs[wq0 + r + 8][kk + c + 4];
#pragma unroll
            for (int ni = 0; ni < 8; ni++) {
                unsigned b[2];
                b[0] = Ks[ni * 8 + r][kk + c];
                b[1] = Ks[ni * 8 + r][kk + c + 4];
                mma_tf32(s[ni], a, b);
            }
        }

        float tmax0 = -1e30f, tmax1 = -1e30f;
#pragma unroll
        for (int ni = 0; ni < 8; ni++) {
            int kg = kt * 64 + ni * 8 + c * 2;
            bool pm0 = pm[ni * 8 + c * 2] != 0;
            bool pm1 = pm[ni * 8 + c * 2 + 1] != 0;
            float v0 = (kg > row0 || pm0) ? -1e30f : s[ni][0] * sc;
            float v1 = (kg + 1 > row0 || pm1) ? -1e30f : s[ni][1] * sc;
            float v2 = (kg > row1 || pm0) ? -1e30f : s[ni][2] * sc;
            float v3 = (kg + 1 > row1 || pm1) ? -1e30f : s[ni][3] * sc;
            s[ni][0] = v0; s[ni][1] = v1; s[ni][2] = v2; s[ni][3] = v3;
            tmax0 = fmaxf(tmax0, fmaxf(v0, v1));
            tmax1 = fmaxf(tmax1, fmaxf(v2, v3));
        }
        tmax0 = fmaxf(tmax0, __shfl_xor_sync(0xffffffffu, tmax0, 1));
        tmax0 = fmaxf(tmax0, __shfl_xor_sync(0xffffffffu, tmax0, 2));
        tmax1 = fmaxf(tmax1, __shfl_xor_sync(0xffffffffu, tmax1, 1));
        tmax1 = fmaxf(tmax1, __shfl_xor_sync(0xffffffffu, tmax1, 2));

        float nm0 = fmaxf(m0, tmax0), nm1 = fmaxf(m1, tmax1);
        float a0 = __expf(m0 - nm0), a1 = __expf(m1 - nm1);
        m0 = nm0; m1 = nm1;

        float rs0 = 0.f, rs1 = 0.f;
#pragma unroll
        for (int ni = 0; ni < 8; ni++) {
            float p0 = __expf(s[ni][0] - nm0);
            float p1 = __expf(s[ni][1] - nm0);
            float p2 = __expf(s[ni][2] - nm1);
            float p3 = __expf(s[ni][3] - nm1);
            rs0 += p0 + p1; rs1 += p2 + p3;
            uint2 lo = make_uint2(f2tf(p0), f2tf(p1));
            uint2 hi = make_uint2(f2tf(p2), f2tf(p3));
            *(uint2*)&Ps[wq0 + r][ni * 8 + c * 2] = lo;
            *(uint2*)&Ps[wq0 + r + 8][ni * 8 + c * 2] = hi;
#pragma unroll
            for (int q = 0; q < 2; q++) { o[ni][q] *= a0; o[ni][q + 2] *= a1; }
        }
        rs0 += __shfl_xor_sync(0xffffffffu, rs0, 1);
        rs0 += __shfl_xor_sync(0xffffffffu, rs0, 2);
        rs1 += __shfl_xor_sync(0xffffffffu, rs1, 1);
        rs1 += __shfl_xor_sync(0xffffffffu, rs1, 2);
        l0 = l0 * a0 + rs0;
        l1 = l1 * a1 + rs1;

        __syncwarp();

#pragma unroll
        for (int kk = 0; kk < 64; kk += 8) {
            unsigned a[4];
            a[0] = Ps[wq0 + r][kk + c];
            a[1] = Ps[wq0 + r + 8][kk + c];
            a[2] = Ps[wq0 + r][kk + c + 4];
            a[3] = Ps[wq0 + r + 8][kk + c + 4];
#pragma unroll
            for (int ni = 0; ni < 8; ni++) {
                unsigned b[2];
                b[0] = Vt[ni * 8 + r][kk + c];
                b[1] = Vt[ni * 8 + r][kk + c + 4];
                mma_tf32(o[ni], a, b);
            }
        }
    }

    float inv0 = 1.f / l0, inv1 = 1.f / l1;
#pragma unroll
    for (int ni = 0; ni < 8; ni++) {
        int dcol = h * HD + ni * 8 + c * 2;
        float* y0 = out + ((size_t)n * LQS + row0) * DM + dcol;
        float* y1 = out + ((size_t)n * LQS + row1) * DM + dcol;
        *(float2*)y0 = make_float2(o[ni][0] * inv0, o[ni][1] * inv0);
        *(float2*)y1 = make_float2(o[ni][2] * inv1, o[ni][3] * inv1);
    }
}

// ---------------------------------------------------------------------------
extern "C" void kernel_launch(void* const* d_in, const int* in_sizes, int n_in,
                              void* d_out, int out_size) {
    const float* query = (const float*)d_in[0];
    const float* key   = (const float*)d_in[1];
    const float* Wq    = (const float*)d_in[2];
    const float* Wk    = (const float*)d_in[3];
    const float* Wv    = (const float*)d_in[4];
    const int* pad     = (const int*)d_in[6];   // bool -> int32
    float* out = (float*)d_out;

    const int proj_smem = 4 * 128 * PKP * 4;  // 73728 B
    cudaFuncSetAttribute(proj_mma,
                         cudaFuncAttributeMaxDynamicSharedMemorySize, proj_smem);
    const int attn_smem = 4 * 64 * AP * 4;    // 69632 B
    cudaFuncSetAttribute(attn_mma,
                         cudaFuncAttributeMaxDynamicSharedMemorySize, attn_smem);

    void *pq, *pk, *pv;
    cudaGetSymbolAddress(&pq, g_q);
    cudaGetSymbolAddress(&pk, g_k);
    cudaGetSymbolAddress(&pv, g_v);

    count_kernel<<<NB, 256>>>(pad);

    dim3 pg(DM / 128, (NB * LQS) / 128, 3);  // (8, 32, 3)
    proj_mma<<<pg, 256, proj_smem>>>(query, key, Wq, Wk, Wv,
                                     (float*)pq, (float*)pk, (float*)pv);

    dim3 ag(LQS / 64, NH, NB);  // (32, 16, 2)
    attn_mma<<<ag, 128, attn_smem>>>(pad, out);
}

// round 7
// speedup vs baseline: 3.0938x; 1.0264x over previous
#include <cuda_runtime.h>

#define NB 2
#define LQS 2048
#define LKS 2048
#define DM 1024
#define NH 16
#define HD 64

// Scratch: Q/K/V in (n, h, l, dd) layout
__device__ float g_q[NB * NH * LQS * HD];
__device__ float g_k[NB * NH * LKS * HD];
__device__ float g_v[NB * NH * LKS * HD];
__device__ float g_scale[8];
__device__ int   g_len[8];

// ---- tf32 mma helpers -----------------------------------------------------
__device__ __forceinline__ unsigned f2tf(float v) {
    unsigned r; asm("cvt.rna.tf32.f32 %0, %1;" : "=r"(r) : "f"(v)); return r;
}
__device__ __forceinline__ void mma_tf32(float d[4], const unsigned a[4],
                                         const unsigned b[2]) {
    asm volatile(
        "mma.sync.aligned.m16n8k8.row.col.f32.tf32.tf32.f32 "
        "{%0,%1,%2,%3}, {%4,%5,%6,%7}, {%8,%9}, {%0,%1,%2,%3};"
        : "+f"(d[0]), "+f"(d[1]), "+f"(d[2]), "+f"(d[3])
        : "r"(a[0]), "r"(a[1]), "r"(a[2]), "r"(a[3]), "r"(b[0]), "r"(b[1]));
}
__device__ __forceinline__ void cp16(void* dst, const void* src) {
    unsigned d = (unsigned)__cvta_generic_to_shared(dst);
    asm volatile("cp.async.cg.shared.global [%0], [%1], 16;" :: "r"(d), "l"(src));
}
#define CP_COMMIT() asm volatile("cp.async.commit_group;" ::: "memory")
#define CP_WAIT_ALL() asm volatile("cp.async.wait_group 0;" ::: "memory")

// ---------------------------------------------------------------------------
// Count valid keys per batch
// ---------------------------------------------------------------------------
__global__ void count_kernel(const int* __restrict__ pad) {
    int n = blockIdx.x;
    __shared__ int cnt;
    if (threadIdx.x == 0) cnt = 0;
    __syncthreads();
    int c = 0;
    for (int i = threadIdx.x; i < LKS; i += blockDim.x)
        if (pad[n * LKS + i] == 0) c++;
    atomicAdd(&cnt, c);
    __syncthreads();
    if (threadIdx.x == 0) {
        g_len[n] = cnt;
        g_scale[n] = rsqrtf((float)cnt);
    }
}

// ---------------------------------------------------------------------------
// Fused projection GEMMs via tf32 mma + cp.async double buffering (R6).
// ---------------------------------------------------------------------------
#define PKP 36
__global__ void __launch_bounds__(256) proj_mma(
    const float* __restrict__ query, const float* __restrict__ key,
    const float* __restrict__ Wq, const float* __restrict__ Wk,
    const float* __restrict__ Wv,
    float* __restrict__ gq, float* __restrict__ gk, float* __restrict__ gv) {
    extern __shared__ float sm[];
    float (*As)[128][PKP] = (float(*)[128][PKP])sm;
    float (*Bs)[128][PKP] = (float(*)[128][PKP])(sm + 2 * 128 * PKP);

    const int z = blockIdx.z;
    const float* X = (z == 0) ? query : key;
    const float* W = (z == 0) ? Wq : (z == 1) ? Wk : Wv;
    float* Y = (z == 0) ? gq : (z == 1) ? gk : gv;

    const int bm = blockIdx.y * 128;
    const int bn = blockIdx.x * 128;
    const int tid = threadIdx.x;
    const int lane = tid & 31;
    const int wid = tid >> 5;
    const int wm = (wid & 3) * 32;
    const int wn = (wid >> 2) * 64;

    float d[2][8][4];
#pragma unroll
    for (int mi = 0; mi < 2; mi++)
#pragma unroll
        for (int ni = 0; ni < 8; ni++)
#pragma unroll
            for (int q = 0; q < 4; q++) d[mi][ni][q] = 0.f;

    const int lrow = tid >> 3;
    const int lc4 = (tid & 7) * 4;

#pragma unroll
    for (int q = 0; q < 4; q++) {
        int row = lrow + q * 32;
        cp16(&As[0][row][lc4], &X[(size_t)(bm + row) * DM + lc4]);
        cp16(&Bs[0][row][lc4], &W[(size_t)(bn + row) * DM + lc4]);
    }
    CP_COMMIT();

    const int nt = DM / 32;
    const int r = lane >> 2, c = lane & 3;

    for (int t = 0; t < nt; t++) {
        const int cur = t & 1;
        CP_WAIT_ALL();
        __syncthreads();
        if (t + 1 < nt) {
            const int nxt = cur ^ 1;
            const int k0 = (t + 1) * 32;
#pragma unroll
            for (int q = 0; q < 4; q++) {
                int row = lrow + q * 32;
                cp16(&As[nxt][row][lc4], &X[(size_t)(bm + row) * DM + k0 + lc4]);
                cp16(&Bs[nxt][row][lc4], &W[(size_t)(bn + row) * DM + k0 + lc4]);
            }
            CP_COMMIT();
        }
#pragma unroll
        for (int kk = 0; kk < 32; kk += 8) {
            unsigned a[2][4], b[8][2];
#pragma unroll
            for (int mi = 0; mi < 2; mi++) {
                int rb = wm + mi * 16;
                a[mi][0] = f2tf(As[cur][rb + r][kk + c]);
                a[mi][1] = f2tf(As[cur][rb + r + 8][kk + c]);
                a[mi][2] = f2tf(As[cur][rb + r][kk + c + 4]);
                a[mi][3] = f2tf(As[cur][rb + r + 8][kk + c + 4]);
            }
#pragma unroll
            for (int ni = 0; ni < 8; ni++) {
                int cb = wn + ni * 8;
                b[ni][0] = f2tf(Bs[cur][cb + r][kk + c]);
                b[ni][1] = f2tf(Bs[cur][cb + r][kk + c + 4]);
            }
#pragma unroll
            for (int mi = 0; mi < 2; mi++)
#pragma unroll
                for (int ni = 0; ni < 8; ni++)
                    mma_tf32(d[mi][ni], a[mi], b[ni]);
        }
    }

#pragma unroll
    for (int mi = 0; mi < 2; mi++) {
#pragma unroll
        for (int ni = 0; ni < 8; ni++) {
            int m0 = bm + wm + mi * 16 + (lane >> 2);
            int col = bn + wn + ni * 8 + (lane & 3) * 2;
            int n = m0 >> 11;
            int h = col >> 6;
            int dd = col & 63;
            int l0 = m0 & (LQS - 1);
            float* y0 = &Y[((size_t)((n * NH + h) * LQS) + l0) * HD + dd];
            float* y1 = &Y[((size_t)((n * NH + h) * LQS) + l0 + 8) * HD + dd];
            *(float2*)y0 = make_float2(d[mi][ni][0], d[mi][ni][1]);
            *(float2*)y1 = make_float2(d[mi][ni][2], d[mi][ni][3]);
        }
    }
}

// ---------------------------------------------------------------------------
// Flash attention via tf32 mma: block = (128-q tile, head, batch), 256 thr,
// 8 warps; each warp owns 16 q rows. K-tile = 64 keys.
// ---------------------------------------------------------------------------
#define AP 68
__global__ void __launch_bounds__(256) attn_mma(
    const int* __restrict__ pad, float* __restrict__ out) {
    extern __shared__ unsigned smu[];
    unsigned (*Qs)[AP] = (unsigned(*)[AP])smu;                  // [q=128][d]
    unsigned (*Ks)[AP] = (unsigned(*)[AP])(smu + 128 * AP);     // [key=64][d]
    unsigned (*Vt)[AP] = (unsigned(*)[AP])(smu + 192 * AP);     // [d=64][key]
    unsigned (*Ps)[AP] = (unsigned(*)[AP])(smu + 256 * AP);     // [q=128][key]
    __shared__ int pm[64];

    const int qt = blockIdx.x;
    const int h = blockIdx.y;
    const int n = blockIdx.z;
    const int tid = threadIdx.x;
    const int lane = tid & 31;
    const int w = tid >> 5;
    const int wq0 = w * 16;
    const int r = lane >> 2;
    const int c = lane & 3;

    // stage Q (tf32): 128x64 floats, 256 thr -> 8 float4 each
    const float* qbase = g_q + ((size_t)(n * NH + h) * LQS + qt * 128) * HD;
    for (int it = 0; it < 8; it++) {
        int e4 = tid + it * 256;
        int q = e4 >> 4, d4 = (e4 & 15) * 4;
        float4 v = *(const float4*)&qbase[q * HD + d4];
        Qs[q][d4 + 0] = f2tf(v.x); Qs[q][d4 + 1] = f2tf(v.y);
        Qs[q][d4 + 2] = f2tf(v.z); Qs[q][d4 + 3] = f2tf(v.w);
    }

    const float sc = g_scale[n];
    const int len = g_len[n];
    const int ktmax = min(2 * qt + 1, (len - 1) >> 6);

    const int row0 = qt * 128 + wq0 + r;
    const int row1 = row0 + 8;

    float m0 = -1e30f, m1 = -1e30f, l0 = 0.f, l1 = 0.f;
    float o[8][4];
#pragma unroll
    for (int ni = 0; ni < 8; ni++)
#pragma unroll
        for (int q = 0; q < 4; q++) o[ni][q] = 0.f;

    for (int kt = 0; kt <= ktmax; kt++) {
        const float* kbase = g_k + ((size_t)(n * NH + h) * LKS + kt * 64) * HD;
        const float* vbase = g_v + ((size_t)(n * NH + h) * LKS + kt * 64) * HD;
        __syncthreads();   // prev iteration done with Ks/Vt/Ps
        // 64x64 K + V: 256 thr -> 4 float4 each
        for (int it = 0; it < 4; it++) {
            int e4 = tid + it * 256;
            int k = e4 >> 4, d4 = (e4 & 15) * 4;
            float4 kv = *(const float4*)&kbase[k * HD + d4];
            float4 vv = *(const float4*)&vbase[k * HD + d4];
            Ks[k][d4 + 0] = f2tf(kv.x); Ks[k][d4 + 1] = f2tf(kv.y);
            Ks[k][d4 + 2] = f2tf(kv.z); Ks[k][d4 + 3] = f2tf(kv.w);
            Vt[d4 + 0][k] = f2tf(vv.x); Vt[d4 + 1][k] = f2tf(vv.y);
            Vt[d4 + 2][k] = f2tf(vv.z); Vt[d4 + 3][k] = f2tf(vv.w);
        }
        if (tid < 64) pm[tid] = pad[n * LKS + kt * 64 + tid];
        __syncthreads();

        // S = Q K^T : warp tile 16x64
        float s[8][4];
#pragma unroll
        for (int ni = 0; ni < 8; ni++)
#pragma unroll
            for (int q = 0; q < 4; q++) s[ni][q] = 0.f;
#pragma unroll
        for (int kk = 0; kk < 64; kk += 8) {
            unsigned a[4];
            a[0] = Qs[wq0 + r][kk + c];
            a[1] = Qs[wq0 + r + 8][kk + c];
            a[2] = Qs[wq0 + r][kk + c + 4];
            a[3] = Qs[wq0 + r + 8][kk + c + 4];
#pragma unroll
            for (int ni = 0; ni < 8; ni++) {
                unsigned b[2];
                b[0] = Ks[ni * 8 + r][kk + c];
                b[1] = Ks[ni * 8 + r][kk + c + 4];
                mma_tf32(s[ni], a, b);
            }
        }

        // mask + scale + online softmax
        float tmax0 = -1e30f, tmax1 = -1e30f;
#pragma unroll
        for (int ni = 0; ni < 8; ni++) {
            int kg = kt * 64 + ni * 8 + c * 2;
            bool pmA = pm[ni * 8 + c * 2] != 0;
            bool pmB = pm[ni * 8 + c * 2 + 1] != 0;
            float v0 = (kg > row0 || pmA) ? -1e30f : s[ni][0] * sc;
            float v1 = (kg + 1 > row0 || pmB) ? -1e30f : s[ni][1] * sc;
            float v2 = (kg > row1 || pmA) ? -1e30f : s[ni][2] * sc;
            float v3 = (kg + 1 > row1 || pmB) ? -1e30f : s[ni][3] * sc;
            s[ni][0] = v0; s[ni][1] = v1; s[ni][2] = v2; s[ni][3] = v3;
            tmax0 = fmaxf(tmax0, fmaxf(v0, v1));
            tmax1 = fmaxf(tmax1, fmaxf(v2, v3));
        }
        tmax0 = fmaxf(tmax0, __shfl_xor_sync(0xffffffffu, tmax0, 1));
        tmax0 = fmaxf(tmax0, __shfl_xor_sync(0xffffffffu, tmax0, 2));
        tmax1 = fmaxf(tmax1, __shfl_xor_sync(0xffffffffu, tmax1, 1));
        tmax1 = fmaxf(tmax1, __shfl_xor_sync(0xffffffffu, tmax1, 2));

        float nm0 = fmaxf(m0, tmax0), nm1 = fmaxf(m1, tmax1);
        float a0 = __expf(m0 - nm0), a1 = __expf(m1 - nm1);
        m0 = nm0; m1 = nm1;

        float rs0 = 0.f, rs1 = 0.f;
#pragma unroll
        for (int ni = 0; ni < 8; ni++) {
            float p0 = __expf(s[ni][0] - nm0);
            float p1 = __expf(s[ni][1] - nm0);
            float p2 = __expf(s[ni][2] - nm1);
            float p3 = __expf(s[ni][3] - nm1);
            rs0 += p0 + p1; rs1 += p2 + p3;
            uint2 lo = make_uint2(f2tf(p0), f2tf(p1));
            uint2 hi = make_uint2(f2tf(p2), f2tf(p3));
            *(uint2*)&Ps[wq0 + r][ni * 8 + c * 2] = lo;
            *(uint2*)&Ps[wq0 + r + 8][ni * 8 + c * 2] = hi;
#pragma unroll
            for (int q = 0; q < 2; q++) { o[ni][q] *= a0; o[ni][q + 2] *= a1; }
        }
        rs0 += __shfl_xor_sync(0xffffffffu, rs0, 1);
        rs0 += __shfl_xor_sync(0xffffffffu, rs0, 2);
        rs1 += __shfl_xor_sync(0xffffffffu, rs1, 1);
        rs1 += __shfl_xor_sync(0xffffffffu, rs1, 2);
        l0 = l0 * a0 + rs0;
        l1 = l1 * a1 + rs1;

        __syncwarp();

        // O += P V
#pragma unroll
        for (int kk = 0; kk < 64; kk += 8) {
            unsigned a[4];
            a[0] = Ps[wq0 + r][kk + c];
            a[1] = Ps[wq0 + r + 8][kk + c];
            a[2] = Ps[wq0 + r][kk + c + 4];
            a[3] = Ps[wq0 + r + 8][kk + c + 4];
#pragma unroll
            for (int ni = 0; ni < 8; ni++) {
                unsigned b[2];
                b[0] = Vt[ni * 8 + r][kk + c];
                b[1] = Vt[ni * 8 + r][kk + c + 4];
                mma_tf32(o[ni], a, b);
            }
        }
    }

    // epilogue: normalize, write out (n, l, h*64+dd)
    float inv0 = 1.f / l0, inv1 = 1.f / l1;
#pragma unroll
    for (int ni = 0; ni < 8; ni++) {
        int dcol = h * HD + ni * 8 + c * 2;
        float* y0 = out + ((size_t)n * LQS + row0) * DM + dcol;
        float* y1 = out + ((size_t)n * LQS + row1) * DM + dcol;
        *(float2*)y0 = make_float2(o[ni][0] * inv0, o[ni][1] * inv0);
        *(float2*)y1 = make_float2(o[ni][2] * inv1, o[ni][3] * inv1);
    }
}

// ---------------------------------------------------------------------------
extern "C" void kernel_launch(void* const* d_in, const int* in_sizes, int n_in,
                              void* d_out, int out_size) {
    const float* query = (const float*)d_in[0];
    const float* key   = (const float*)d_in[1];
    const float* Wq    = (const float*)d_in[2];
    const float* Wk    = (const float*)d_in[3];
    const float* Wv    = (const float*)d_in[4];
    const int* pad     = (const int*)d_in[6];   // bool -> int32
    float* out = (float*)d_out;

    const int proj_smem = 4 * 128 * PKP * 4;  // 73728 B
    cudaFuncSetAttribute(proj_mma,
                         cudaFuncAttributeMaxDynamicSharedMemorySize, proj_smem);
    const int attn_smem = 384 * AP * 4;       // 104448 B
    cudaFuncSetAttribute(attn_mma,
                         cudaFuncAttributeMaxDynamicSharedMemorySize, attn_smem);

    void *pq, *pk, *pv;
    cudaGetSymbolAddress(&pq, g_q);
    cudaGetSymbolAddress(&pk, g_k);
    cudaGetSymbolAddress(&pv, g_v);

    count_kernel<<<NB, 256>>>(pad);

    dim3 pg(DM / 128, (NB * LQS) / 128, 3);  // (8, 32, 3)
    proj_mma<<<pg, 256, proj_smem>>>(query, key, Wq, Wk, Wv,
                                     (float*)pq, (float*)pk, (float*)pv);

    dim3 ag(LQS / 128, NH, NB);  // (16, 16, 2)
    attn_mma<<<ag, 256, attn_smem>>>(pad, out);
}

// round 8
// speedup vs baseline: 3.4240x; 1.1067x over previous
#include <cuda_runtime.h>

#define NB 2
#define LQS 2048
#define LKS 2048
#define DM 1024
#define NH 16
#define HD 64

// Scratch: Q/K/V in (n, h, l, dd) layout
__device__ float g_q[NB * NH * LQS * HD];
__device__ float g_k[NB * NH * LKS * HD];
__device__ float g_v[NB * NH * LKS * HD];
__device__ float g_scale[8];
__device__ int   g_len[8];

// ---- tf32 mma helpers -----------------------------------------------------
__device__ __forceinline__ unsigned f2tf(float v) {
    unsigned r; asm("cvt.rna.tf32.f32 %0, %1;" : "=r"(r) : "f"(v)); return r;
}
__device__ __forceinline__ void mma_tf32(float d[4], const unsigned a[4],
                                         const unsigned b[2]) {
    asm volatile(
        "mma.sync.aligned.m16n8k8.row.col.f32.tf32.tf32.f32 "
        "{%0,%1,%2,%3}, {%4,%5,%6,%7}, {%8,%9}, {%0,%1,%2,%3};"
        : "+f"(d[0]), "+f"(d[1]), "+f"(d[2]), "+f"(d[3])
        : "r"(a[0]), "r"(a[1]), "r"(a[2]), "r"(a[3]), "r"(b[0]), "r"(b[1]));
}
__device__ __forceinline__ void cp16(void* dst, const void* src) {
    unsigned d = (unsigned)__cvta_generic_to_shared(dst);
    asm volatile("cp.async.cg.shared.global [%0], [%1], 16;" :: "r"(d), "l"(src));
}
#define CP_COMMIT() asm volatile("cp.async.commit_group;" ::: "memory")
#define CP_WAIT_ALL() asm volatile("cp.async.wait_group 0;" ::: "memory")

// ---------------------------------------------------------------------------
// Count valid keys per batch
// ---------------------------------------------------------------------------
__global__ void count_kernel(const int* __restrict__ pad) {
    int n = blockIdx.x;
    __shared__ int cnt;
    if (threadIdx.x == 0) cnt = 0;
    __syncthreads();
    int c = 0;
    for (int i = threadIdx.x; i < LKS; i += blockDim.x)
        if (pad[n * LKS + i] == 0) c++;
    atomicAdd(&cnt, c);
    __syncthreads();
    if (threadIdx.x == 0) {
        g_len[n] = cnt;
        g_scale[n] = rsqrtf((float)cnt);
    }
}

// ---------------------------------------------------------------------------
// Fused projection GEMMs via tf32 mma + cp.async double buffering (R6).
// ---------------------------------------------------------------------------
#define PKP 36
__global__ void __launch_bounds__(256) proj_mma(
    const float* __restrict__ query, const float* __restrict__ key,
    const float* __restrict__ Wq, const float* __restrict__ Wk,
    const float* __restrict__ Wv,
    float* __restrict__ gq, float* __restrict__ gk, float* __restrict__ gv) {
    extern __shared__ float sm[];
    float (*As)[128][PKP] = (float(*)[128][PKP])sm;
    float (*Bs)[128][PKP] = (float(*)[128][PKP])(sm + 2 * 128 * PKP);

    const int z = blockIdx.z;
    const float* X = (z == 0) ? query : key;
    const float* W = (z == 0) ? Wq : (z == 1) ? Wk : Wv;
    float* Y = (z == 0) ? gq : (z == 1) ? gk : gv;

    const int bm = blockIdx.y * 128;
    const int bn = blockIdx.x * 128;
    const int tid = threadIdx.x;
    const int lane = tid & 31;
    const int wid = tid >> 5;
    const int wm = (wid & 3) * 32;
    const int wn = (wid >> 2) * 64;

    float d[2][8][4];
#pragma unroll
    for (int mi = 0; mi < 2; mi++)
#pragma unroll
        for (int ni = 0; ni < 8; ni++)
#pragma unroll
            for (int q = 0; q < 4; q++) d[mi][ni][q] = 0.f;

    const int lrow = tid >> 3;
    const int lc4 = (tid & 7) * 4;

#pragma unroll
    for (int q = 0; q < 4; q++) {
        int row = lrow + q * 32;
        cp16(&As[0][row][lc4], &X[(size_t)(bm + row) * DM + lc4]);
        cp16(&Bs[0][row][lc4], &W[(size_t)(bn + row) * DM + lc4]);
    }
    CP_COMMIT();

    const int nt = DM / 32;
    const int r = lane >> 2, c = lane & 3;

    for (int t = 0; t < nt; t++) {
        const int cur = t & 1;
        CP_WAIT_ALL();
        __syncthreads();
        if (t + 1 < nt) {
            const int nxt = cur ^ 1;
            const int k0 = (t + 1) * 32;
#pragma unroll
            for (int q = 0; q < 4; q++) {
                int row = lrow + q * 32;
                cp16(&As[nxt][row][lc4], &X[(size_t)(bm + row) * DM + k0 + lc4]);
                cp16(&Bs[nxt][row][lc4], &W[(size_t)(bn + row) * DM + k0 + lc4]);
            }
            CP_COMMIT();
        }
#pragma unroll
        for (int kk = 0; kk < 32; kk += 8) {
            unsigned a[2][4], b[8][2];
#pragma unroll
            for (int mi = 0; mi < 2; mi++) {
                int rb = wm + mi * 16;
                a[mi][0] = f2tf(As[cur][rb + r][kk + c]);
                a[mi][1] = f2tf(As[cur][rb + r + 8][kk + c]);
                a[mi][2] = f2tf(As[cur][rb + r][kk + c + 4]);
                a[mi][3] = f2tf(As[cur][rb + r + 8][kk + c + 4]);
            }
#pragma unroll
            for (int ni = 0; ni < 8; ni++) {
                int cb = wn + ni * 8;
                b[ni][0] = f2tf(Bs[cur][cb + r][kk + c]);
                b[ni][1] = f2tf(Bs[cur][cb + r][kk + c + 4]);
            }
#pragma unroll
            for (int mi = 0; mi < 2; mi++)
#pragma unroll
                for (int ni = 0; ni < 8; ni++)
                    mma_tf32(d[mi][ni], a[mi], b[ni]);
        }
    }

#pragma unroll
    for (int mi = 0; mi < 2; mi++) {
#pragma unroll
        for (int ni = 0; ni < 8; ni++) {
            int m0 = bm + wm + mi * 16 + (lane >> 2);
            int col = bn + wn + ni * 8 + (lane & 3) * 2;
            int n = m0 >> 11;
            int h = col >> 6;
            int dd = col & 63;
            int l0 = m0 & (LQS - 1);
            float* y0 = &Y[((size_t)((n * NH + h) * LQS) + l0) * HD + dd];
            float* y1 = &Y[((size_t)((n * NH + h) * LQS) + l0 + 8) * HD + dd];
            *(float2*)y0 = make_float2(d[mi][ni][0], d[mi][ni][1]);
            *(float2*)y1 = make_float2(d[mi][ni][2], d[mi][ni][3]);
        }
    }
}

// ---------------------------------------------------------------------------
// Flash attention via tf32 mma + cp.async double-buffered K/V.
// block = (128-q tile, head, batch), 256 thr, 8 warps (16 q rows each).
// K/V staged raw fp32; tf32 cvt at fragment load. V read with swapped
// indices (no transpose store). Padding handled as suffix: key >= len.
// ---------------------------------------------------------------------------
#define QS 68       // stride (words) for Qs/Ks/Ps: conflict-free row-frag loads
#define VS 72       // stride for Vs: conflict-free col-frag loads
#define SM_Q 0                       // Qs[128][QS] tf32
#define SM_K (SM_Q + 128 * QS)       // Ksf[2][64][QS] f32
#define SM_V (SM_K + 2 * 64 * QS)    // Vsf[2][64][VS] f32
#define SM_P (SM_V + 2 * 64 * VS)    // Ps[128][QS] tf32
#define SM_TOT (SM_P + 128 * QS)     // words

__global__ void __launch_bounds__(256) attn_mma(float* __restrict__ out) {
    extern __shared__ unsigned smu[];
    unsigned (*Qs)[QS] = (unsigned(*)[QS])(smu + SM_Q);
    float (*Ksf)[64][QS] = (float(*)[64][QS])(smu + SM_K);
    float (*Vsf)[64][VS] = (float(*)[64][VS])(smu + SM_V);
    unsigned (*Ps)[QS] = (unsigned(*)[QS])(smu + SM_P);

    const int qt = blockIdx.x;
    const int h = blockIdx.y;
    const int n = blockIdx.z;
    const int tid = threadIdx.x;
    const int lane = tid & 31;
    const int w = tid >> 5;
    const int wq0 = w * 16;
    const int r = lane >> 2;
    const int c = lane & 3;

    // stage Q (tf32): 128x64, 256 thr -> 8 float4 each
    const float* qbase = g_q + ((size_t)(n * NH + h) * LQS + qt * 128) * HD;
#pragma unroll
    for (int it = 0; it < 8; it++) {
        int e4 = tid + it * 256;
        int q = e4 >> 4, d4 = (e4 & 15) * 4;
        float4 v = *(const float4*)&qbase[q * HD + d4];
        Qs[q][d4 + 0] = f2tf(v.x); Qs[q][d4 + 1] = f2tf(v.y);
        Qs[q][d4 + 2] = f2tf(v.z); Qs[q][d4 + 3] = f2tf(v.w);
    }

    const float sc = g_scale[n];
    const int len = g_len[n];
    const int ktmax = min(2 * qt + 1, (len - 1) >> 6);

    const int row0 = qt * 128 + wq0 + r;
    const int row1 = row0 + 8;

    const float* kb0 = g_k + ((size_t)(n * NH + h) * LKS) * HD;
    const float* vb0 = g_v + ((size_t)(n * NH + h) * LKS) * HD;
    const int lk = tid >> 4;            // 0..15 (key row base for cp)
    const int ld4 = (tid & 15) * 4;     // d offset

    // prefetch tile 0
#pragma unroll
    for (int it = 0; it < 4; it++) {
        int k = lk + it * 16;
        cp16(&Ksf[0][k][ld4], &kb0[(size_t)k * HD + ld4]);
        cp16(&Vsf[0][k][ld4], &vb0[(size_t)k * HD + ld4]);
    }
    CP_COMMIT();

    float m0 = -1e30f, m1 = -1e30f, l0 = 0.f, l1 = 0.f;
    float o[8][4];
#pragma unroll
    for (int ni = 0; ni < 8; ni++)
#pragma unroll
        for (int q = 0; q < 4; q++) o[ni][q] = 0.f;

    for (int kt = 0; kt <= ktmax; kt++) {
        const int cur = kt & 1;
        CP_WAIT_ALL();
        __syncthreads();   // buf cur ready; all warps done with buf cur^1
        if (kt + 1 <= ktmax) {
            const int nxt = cur ^ 1;
            const size_t koff = (size_t)(kt + 1) * 64 * HD;
#pragma unroll
            for (int it = 0; it < 4; it++) {
                int k = lk + it * 16;
                cp16(&Ksf[nxt][k][ld4], &kb0[koff + (size_t)k * HD + ld4]);
                cp16(&Vsf[nxt][k][ld4], &vb0[koff + (size_t)k * HD + ld4]);
            }
            CP_COMMIT();
        }

        // S = Q K^T : warp tile 16x64
        float s[8][4];
#pragma unroll
        for (int ni = 0; ni < 8; ni++)
#pragma unroll
            for (int q = 0; q < 4; q++) s[ni][q] = 0.f;
#pragma unroll
        for (int kk = 0; kk < 64; kk += 8) {
            unsigned a[4];
            a[0] = Qs[wq0 + r][kk + c];
            a[1] = Qs[wq0 + r + 8][kk + c];
            a[2] = Qs[wq0 + r][kk + c + 4];
            a[3] = Qs[wq0 + r + 8][kk + c + 4];
#pragma unroll
            for (int ni = 0; ni < 8; ni++) {
                unsigned b[2];
                b[0] = f2tf(Ksf[cur][ni * 8 + r][kk + c]);
                b[1] = f2tf(Ksf[cur][ni * 8 + r][kk + c + 4]);
                mma_tf32(s[ni], a, b);
            }
        }

        // mask (causal + suffix padding) + scale + online softmax
        float tmax0 = -1e30f, tmax1 = -1e30f;
#pragma unroll
        for (int ni = 0; ni < 8; ni++) {
            int kg = kt * 64 + ni * 8 + c * 2;
            bool mA = (kg >= len);
            bool mB = (kg + 1 >= len);
            float v0 = (kg > row0 || mA) ? -1e30f : s[ni][0] * sc;
            float v1 = (kg + 1 > row0 || mB) ? -1e30f : s[ni][1] * sc;
            float v2 = (kg > row1 || mA) ? -1e30f : s[ni][2] * sc;
            float v3 = (kg + 1 > row1 || mB) ? -1e30f : s[ni][3] * sc;
            s[ni][0] = v0; s[ni][1] = v1; s[ni][2] = v2; s[ni][3] = v3;
            tmax0 = fmaxf(tmax0, fmaxf(v0, v1));
            tmax1 = fmaxf(tmax1, fmaxf(v2, v3));
        }
        tmax0 = fmaxf(tmax0, __shfl_xor_sync(0xffffffffu, tmax0, 1));
        tmax0 = fmaxf(tmax0, __shfl_xor_sync(0xffffffffu, tmax0, 2));
        tmax1 = fmaxf(tmax1, __shfl_xor_sync(0xffffffffu, tmax1, 1));
        tmax1 = fmaxf(tmax1, __shfl_xor_sync(0xffffffffu, tmax1, 2));

        float nm0 = fmaxf(m0, tmax0), nm1 = fmaxf(m1, tmax1);
        float a0 = __expf(m0 - nm0), a1 = __expf(m1 - nm1);
        m0 = nm0; m1 = nm1;

        float rs0 = 0.f, rs1 = 0.f;
#pragma unroll
        for (int ni = 0; ni < 8; ni++) {
            float p0 = __expf(s[ni][0] - nm0);
            float p1 = __expf(s[ni][1] - nm0);
            float p2 = __expf(s[ni][2] - nm1);
            float p3 = __expf(s[ni][3] - nm1);
            rs0 += p0 + p1; rs1 += p2 + p3;
            uint2 lo = make_uint2(f2tf(p0), f2tf(p1));
            uint2 hi = make_uint2(f2tf(p2), f2tf(p3));
            *(uint2*)&Ps[wq0 + r][ni * 8 + c * 2] = lo;
            *(uint2*)&Ps[wq0 + r + 8][ni * 8 + c * 2] = hi;
#pragma unroll
            for (int q = 0; q < 2; q++) { o[ni][q] *= a0; o[ni][q + 2] *= a1; }
        }
        rs0 += __shfl_xor_sync(0xffffffffu, rs0, 1);
        rs0 += __shfl_xor_sync(0xffffffffu, rs0, 2);
        rs1 += __shfl_xor_sync(0xffffffffu, rs1, 1);
        rs1 += __shfl_xor_sync(0xffffffffu, rs1, 2);
        l0 = l0 * a0 + rs0;
        l1 = l1 * a1 + rs1;

        __syncwarp();

        // O += P V  (B = V[key][d] via swapped indices, cvt at load)
#pragma unroll
        for (int kk = 0; kk < 64; kk += 8) {
            unsigned a[4];
            a[0] = Ps[wq0 + r][kk + c];
            a[1] = Ps[wq0 + r + 8][kk + c];
            a[2] = Ps[wq0 + r][kk + c + 4];
            a[3] = Ps[wq0 + r + 8][kk + c + 4];
#pragma unroll
            for (int ni = 0; ni < 8; ni++) {
                unsigned b[2];
                b[0] = f2tf(Vsf[cur][kk + c][ni * 8 + r]);
                b[1] = f2tf(Vsf[cur][kk + c + 4][ni * 8 + r]);
                mma_tf32(o[ni], a, b);
            }
        }
    }

    // epilogue: normalize, write out (n, l, h*64+dd)
    float inv0 = 1.f / l0, inv1 = 1.f / l1;
#pragma unroll
    for (int ni = 0; ni < 8; ni++) {
        int dcol = h * HD + ni * 8 + c * 2;
        float* y0 = out + ((size_t)n * LQS + row0) * DM + dcol;
        float* y1 = out + ((size_t)n * LQS + row1) * DM + dcol;
        *(float2*)y0 = make_float2(o[ni][0] * inv0, o[ni][1] * inv0);
        *(float2*)y1 = make_float2(o[ni][2] * inv1, o[ni][3] * inv1);
    }
}

// ---------------------------------------------------------------------------
extern "C" void kernel_launch(void* const* d_in, const int* in_sizes, int n_in,
                              void* d_out, int out_size) {
    const float* query = (const float*)d_in[0];
    const float* key   = (const float*)d_in[1];
    const float* Wq    = (const float*)d_in[2];
    const float* Wk    = (const float*)d_in[3];
    const float* Wv    = (const float*)d_in[4];
    const int* pad     = (const int*)d_in[6];   // bool -> int32
    float* out = (float*)d_out;

    const int proj_smem = 4 * 128 * PKP * 4;  // 73728 B
    cudaFuncSetAttribute(proj_mma,
                         cudaFuncAttributeMaxDynamicSharedMemorySize, proj_smem);
    const int attn_smem = SM_TOT * 4;         // 141312 B
    cudaFuncSetAttribute(attn_mma,
                         cudaFuncAttributeMaxDynamicSharedMemorySize, attn_smem);

    void *pq, *pk, *pv;
    cudaGetSymbolAddress(&pq, g_q);
    cudaGetSymbolAddress(&pk, g_k);
    cudaGetSymbolAddress(&pv, g_v);

    count_kernel<<<NB, 256>>>(pad);

    dim3 pg(DM / 128, (NB * LQS) / 128, 3);  // (8, 32, 3)
    proj_mma<<<pg, 256, proj_smem>>>(query, key, Wq, Wk, Wv,
                                     (float*)pq, (float*)pk, (float*)pv);

    dim3 ag(LQS / 128, NH, NB);  // (16, 16, 2)
    attn_mma<<<ag, 256, attn_smem>>>(out);
}

// round 9
// speedup vs baseline: 4.3152x; 1.2603x over previous
#include <cuda_runtime.h>
#include <cuda_fp16.h>

#define NB 2
#define LQS 2048
#define LKS 2048
#define DM 1024
#define NH 16
#define HD 64

// Scratch: Q/K in (n, h, l, dd) fp16; V in (n, h, dd, l) fp16 (transposed)
__device__ __half g_q[NB * NH * LQS * HD];
__device__ __half g_k[NB * NH * LKS * HD];
__device__ __half g_v[NB * NH * LKS * HD];
__device__ float g_scale[8];
__device__ int   g_len[8];

// ---- mma helpers ----------------------------------------------------------
__device__ __forceinline__ unsigned f2tf(float v) {
    unsigned r; asm("cvt.rna.tf32.f32 %0, %1;" : "=r"(r) : "f"(v)); return r;
}
__device__ __forceinline__ void mma_tf32(float d[4], const unsigned a[4],
                                         const unsigned b[2]) {
    asm volatile(
        "mma.sync.aligned.m16n8k8.row.col.f32.tf32.tf32.f32 "
        "{%0,%1,%2,%3}, {%4,%5,%6,%7}, {%8,%9}, {%0,%1,%2,%3};"
        : "+f"(d[0]), "+f"(d[1]), "+f"(d[2]), "+f"(d[3])
        : "r"(a[0]), "r"(a[1]), "r"(a[2]), "r"(a[3]), "r"(b[0]), "r"(b[1]));
}
__device__ __forceinline__ void mma_f16(float d[4], const unsigned a[4],
                                        const unsigned b[2]) {
    asm volatile(
        "mma.sync.aligned.m16n8k16.row.col.f32.f16.f16.f32 "
        "{%0,%1,%2,%3}, {%4,%5,%6,%7}, {%8,%9}, {%0,%1,%2,%3};"
        : "+f"(d[0]), "+f"(d[1]), "+f"(d[2]), "+f"(d[3])
        : "r"(a[0]), "r"(a[1]), "r"(a[2]), "r"(a[3]), "r"(b[0]), "r"(b[1]));
}
__device__ __forceinline__ void cp16(void* dst, const void* src) {
    unsigned d = (unsigned)__cvta_generic_to_shared(dst);
    asm volatile("cp.async.cg.shared.global [%0], [%1], 16;" :: "r"(d), "l"(src));
}
#define CP_COMMIT() asm volatile("cp.async.commit_group;" ::: "memory")
#define CP_WAIT_ALL() asm volatile("cp.async.wait_group 0;" ::: "memory")

// ---------------------------------------------------------------------------
// Count valid keys per batch
// ---------------------------------------------------------------------------
__global__ void count_kernel(const int* __restrict__ pad) {
    int n = blockIdx.x;
    __shared__ int cnt;
    if (threadIdx.x == 0) cnt = 0;
    __syncthreads();
    int c = 0;
    for (int i = threadIdx.x; i < LKS; i += blockDim.x)
        if (pad[n * LKS + i] == 0) c++;
    atomicAdd(&cnt, c);
    __syncthreads();
    if (threadIdx.x == 0) {
        g_len[n] = cnt;
        g_scale[n] = rsqrtf((float)cnt);
    }
}

// ---------------------------------------------------------------------------
// Fused projection GEMMs, tf32 mma + cp.async double buffering.
// Epilogue converts to fp16; V (z==2) is stored TRANSPOSED (n,h,dd,l).
// ---------------------------------------------------------------------------
#define PKP 36
__global__ void __launch_bounds__(256) proj_mma(
    const float* __restrict__ query, const float* __restrict__ key,
    const float* __restrict__ Wq, const float* __restrict__ Wk,
    const float* __restrict__ Wv,
    __half* __restrict__ gq, __half* __restrict__ gk, __half* __restrict__ gv) {
    extern __shared__ float sm[];
    float (*As)[128][PKP] = (float(*)[128][PKP])sm;
    float (*Bs)[128][PKP] = (float(*)[128][PKP])(sm + 2 * 128 * PKP);

    const int z = blockIdx.z;
    const float* X = (z == 0) ? query : key;
    const float* W = (z == 0) ? Wq : (z == 1) ? Wk : Wv;

    const int bm = blockIdx.y * 128;
    const int bn = blockIdx.x * 128;
    const int tid = threadIdx.x;
    const int lane = tid & 31;
    const int wid = tid >> 5;
    const int wm = (wid & 3) * 32;
    const int wn = (wid >> 2) * 64;

    float d[2][8][4];
#pragma unroll
    for (int mi = 0; mi < 2; mi++)
#pragma unroll
        for (int ni = 0; ni < 8; ni++)
#pragma unroll
            for (int q = 0; q < 4; q++) d[mi][ni][q] = 0.f;

    const int lrow = tid >> 3;
    const int lc4 = (tid & 7) * 4;

#pragma unroll
    for (int q = 0; q < 4; q++) {
        int row = lrow + q * 32;
        cp16(&As[0][row][lc4], &X[(size_t)(bm + row) * DM + lc4]);
        cp16(&Bs[0][row][lc4], &W[(size_t)(bn + row) * DM + lc4]);
    }
    CP_COMMIT();

    const int nt = DM / 32;
    const int r = lane >> 2, c = lane & 3;

    for (int t = 0; t < nt; t++) {
        const int cur = t & 1;
        CP_WAIT_ALL();
        __syncthreads();
        if (t + 1 < nt) {
            const int nxt = cur ^ 1;
            const int k0 = (t + 1) * 32;
#pragma unroll
            for (int q = 0; q < 4; q++) {
                int row = lrow + q * 32;
                cp16(&As[nxt][row][lc4], &X[(size_t)(bm + row) * DM + k0 + lc4]);
                cp16(&Bs[nxt][row][lc4], &W[(size_t)(bn + row) * DM + k0 + lc4]);
            }
            CP_COMMIT();
        }
#pragma unroll
        for (int kk = 0; kk < 32; kk += 8) {
            unsigned a[2][4], b[8][2];
#pragma unroll
            for (int mi = 0; mi < 2; mi++) {
                int rb = wm + mi * 16;
                a[mi][0] = f2tf(As[cur][rb + r][kk + c]);
                a[mi][1] = f2tf(As[cur][rb + r + 8][kk + c]);
                a[mi][2] = f2tf(As[cur][rb + r][kk + c + 4]);
                a[mi][3] = f2tf(As[cur][rb + r + 8][kk + c + 4]);
            }
#pragma unroll
            for (int ni = 0; ni < 8; ni++) {
                int cb = wn + ni * 8;
                b[ni][0] = f2tf(Bs[cur][cb + r][kk + c]);
                b[ni][1] = f2tf(Bs[cur][cb + r][kk + c + 4]);
            }
#pragma unroll
            for (int mi = 0; mi < 2; mi++)
#pragma unroll
                for (int ni = 0; ni < 8; ni++)
                    mma_tf32(d[mi][ni], a[mi], b[ni]);
        }
    }

#pragma unroll
    for (int mi = 0; mi < 2; mi++) {
#pragma unroll
        for (int ni = 0; ni < 8; ni++) {
            int m0 = bm + wm + mi * 16 + (lane >> 2);
            int col = bn + wn + ni * 8 + (lane & 3) * 2;
            int n = m0 >> 11;
            int h = col >> 6;
            int dd = col & 63;
            int l0 = m0 & (LQS - 1);
            __half h0 = __float2half_rn(d[mi][ni][0]);
            __half h1 = __float2half_rn(d[mi][ni][1]);
            __half h2 = __float2half_rn(d[mi][ni][2]);
            __half h3 = __float2half_rn(d[mi][ni][3]);
            if (z == 2) {
                // V transposed: (n, h, dd, l)
                size_t base = ((size_t)(n * NH + h) * HD + dd) * LKS;
                gv[base + l0] = h0;
                gv[base + LKS + l0] = h1;        // dd+1
                gv[base + l0 + 8] = h2;
                gv[base + LKS + l0 + 8] = h3;
            } else {
                __half* Y = (z == 0) ? gq : gk;
                __half* y0 = &Y[((size_t)((n * NH + h) * LQS) + l0) * HD + dd];
                __half* y1 = &Y[((size_t)((n * NH + h) * LQS) + l0 + 8) * HD + dd];
                *(__half2*)y0 = __halves2half2(h0, h1);
                *(__half2*)y1 = __halves2half2(h2, h3);
            }
        }
    }
}

// ---------------------------------------------------------------------------
// Flash attention via fp16 mma m16n8k16 + cp.async double-buffered K/V.
// block = (128-q tile, head, batch), 256 thr, 8 warps (16 q rows each).
// Q/K smem [l][d] fp16, V smem [d][l] fp16, P smem [q][key] fp16.
// Stride 72 halves -> conflict-free packed-pair fragment loads.
// ---------------------------------------------------------------------------
#define HS 72       // halves per row
#define SMH_Q 0                        // Qs[128][HS]
#define SMH_K (SMH_Q + 128 * HS)       // Ks[2][64][HS]
#define SMH_V (SMH_K + 2 * 64 * HS)    // Vt[2][64][HS]
#define SMH_P (SMH_V + 2 * 64 * HS)    // Ps[128][HS]
#define SMH_TOT (SMH_P + 128 * HS)     // halves (36864 -> 73728 B)

__global__ void __launch_bounds__(256) attn_mma(float* __restrict__ out) {
    extern __shared__ __half smh[];
    __half (*Qs)[HS] = (__half(*)[HS])(smh + SMH_Q);
    __half (*Ks)[64][HS] = (__half(*)[64][HS])(smh + SMH_K);
    __half (*Vt)[64][HS] = (__half(*)[64][HS])(smh + SMH_V);
    __half (*Ps)[HS] = (__half(*)[HS])(smh + SMH_P);

    const int qt = blockIdx.x;
    const int h = blockIdx.y;
    const int n = blockIdx.z;
    const int tid = threadIdx.x;
    const int lane = tid & 31;
    const int w = tid >> 5;
    const int wq0 = w * 16;
    const int r = lane >> 2;
    const int c = lane & 3;

    // stage Q: 128 rows x 128B; 256 thr -> 4 x 16B each
    const __half* qbase = g_q + ((size_t)(n * NH + h) * LQS + qt * 128) * HD;
#pragma unroll
    for (int it = 0; it < 4; it++) {
        int e = tid + it * 256;          // 16B unit index (1024 total)
        int q = e >> 3, u = e & 7;
        uint4 v = *(const uint4*)&qbase[q * HD + u * 8];
        *(uint4*)&Qs[q][u * 8] = v;
    }

    const float sc = g_scale[n];
    const int len = g_len[n];
    const int ktmax = min(2 * qt + 1, (len - 1) >> 6);

    const int row0 = qt * 128 + wq0 + r;
    const int row1 = row0 + 8;

    const __half* kb0 = g_k + ((size_t)(n * NH + h) * LKS) * HD;   // [l][d]
    const __half* vb0 = g_v + ((size_t)(n * NH + h) * HD) * LKS;   // [d][l]
    const int lr = tid >> 2;            // 0..63 (row)
    const int ls = (tid & 3) * 16;      // half offset within row (2 x 16B)

    // prefetch tile 0
    cp16(&Ks[0][lr][ls], &kb0[(size_t)lr * HD + ls]);
    cp16(&Ks[0][lr][ls + 8], &kb0[(size_t)lr * HD + ls + 8]);
    cp16(&Vt[0][lr][ls], &vb0[(size_t)lr * LKS + ls]);
    cp16(&Vt[0][lr][ls + 8], &vb0[(size_t)lr * LKS + ls + 8]);
    CP_COMMIT();

    float m0 = -1e30f, m1 = -1e30f, l0 = 0.f, l1 = 0.f;
    float o[8][4];
#pragma unroll
    for (int ni = 0; ni < 8; ni++)
#pragma unroll
        for (int q = 0; q < 4; q++) o[ni][q] = 0.f;

    for (int kt = 0; kt <= ktmax; kt++) {
        const int cur = kt & 1;
        CP_WAIT_ALL();
        __syncthreads();
        if (kt + 1 <= ktmax) {
            const int nxt = cur ^ 1;
            const size_t ko = (size_t)(kt + 1) * 64;
            cp16(&Ks[nxt][lr][ls], &kb0[(ko + lr) * HD + ls]);
            cp16(&Ks[nxt][lr][ls + 8], &kb0[(ko + lr) * HD + ls + 8]);
            cp16(&Vt[nxt][lr][ls], &vb0[(size_t)lr * LKS + ko + ls]);
            cp16(&Vt[nxt][lr][ls + 8], &vb0[(size_t)lr * LKS + ko + ls + 8]);
            CP_COMMIT();
        }

        // S = Q K^T : warp tile 16x64, fp16 k16 mma (4 k-steps)
        float s[8][4];
#pragma unroll
        for (int ni = 0; ni < 8; ni++)
#pragma unroll
            for (int q = 0; q < 4; q++) s[ni][q] = 0.f;
#pragma unroll
        for (int kk = 0; kk < 64; kk += 16) {
            unsigned a[4];
            a[0] = *(const unsigned*)&Qs[wq0 + r][kk + 2 * c];
            a[1] = *(const unsigned*)&Qs[wq0 + r + 8][kk + 2 * c];
            a[2] = *(const unsigned*)&Qs[wq0 + r][kk + 2 * c + 8];
            a[3] = *(const unsigned*)&Qs[wq0 + r + 8][kk + 2 * c + 8];
#pragma unroll
            for (int ni = 0; ni < 8; ni++) {
                unsigned b[2];
                b[0] = *(const unsigned*)&Ks[cur][ni * 8 + r][kk + 2 * c];
                b[1] = *(const unsigned*)&Ks[cur][ni * 8 + r][kk + 2 * c + 8];
                mma_f16(s[ni], a, b);
            }
        }

        // mask (causal + suffix padding) + scale + online softmax
        float tmax0 = -1e30f, tmax1 = -1e30f;
#pragma unroll
        for (int ni = 0; ni < 8; ni++) {
            int kg = kt * 64 + ni * 8 + c * 2;
            bool mA = (kg >= len);
            bool mB = (kg + 1 >= len);
            float v0 = (kg > row0 || mA) ? -1e30f : s[ni][0] * sc;
            float v1 = (kg + 1 > row0 || mB) ? -1e30f : s[ni][1] * sc;
            float v2 = (kg > row1 || mA) ? -1e30f : s[ni][2] * sc;
            float v3 = (kg + 1 > row1 || mB) ? -1e30f : s[ni][3] * sc;
            s[ni][0] = v0; s[ni][1] = v1; s[ni][2] = v2; s[ni][3] = v3;
            tmax0 = fmaxf(tmax0, fmaxf(v0, v1));
            tmax1 = fmaxf(tmax1, fmaxf(v2, v3));
        }
        tmax0 = fmaxf(tmax0, __shfl_xor_sync(0xffffffffu, tmax0, 1));
        tmax0 = fmaxf(tmax0, __shfl_xor_sync(0xffffffffu, tmax0, 2));
        tmax1 = fmaxf(tmax1, __shfl_xor_sync(0xffffffffu, tmax1, 1));
        tmax1 = fmaxf(tmax1, __shfl_xor_sync(0xffffffffu, tmax1, 2));

        float nm0 = fmaxf(m0, tmax0), nm1 = fmaxf(m1, tmax1);
        float a0 = __expf(m0 - nm0), a1 = __expf(m1 - nm1);
        m0 = nm0; m1 = nm1;

        float rs0 = 0.f, rs1 = 0.f;
#pragma unroll
        for (int ni = 0; ni < 8; ni++) {
            float p0 = __expf(s[ni][0] - nm0);
            float p1 = __expf(s[ni][1] - nm0);
            float p2 = __expf(s[ni][2] - nm1);
            float p3 = __expf(s[ni][3] - nm1);
            rs0 += p0 + p1; rs1 += p2 + p3;
            *(__half2*)&Ps[wq0 + r][ni * 8 + 2 * c] = __halves2half2(
                __float2half_rn(p0), __float2half_rn(p1));
            *(__half2*)&Ps[wq0 + r + 8][ni * 8 + 2 * c] = __halves2half2(
                __float2half_rn(p2), __float2half_rn(p3));
#pragma unroll
            for (int q = 0; q < 2; q++) { o[ni][q] *= a0; o[ni][q + 2] *= a1; }
        }
        rs0 += __shfl_xor_sync(0xffffffffu, rs0, 1);
        rs0 += __shfl_xor_sync(0xffffffffu, rs0, 2);
        rs1 += __shfl_xor_sync(0xffffffffu, rs1, 1);
        rs1 += __shfl_xor_sync(0xffffffffu, rs1, 2);
        l0 = l0 * a0 + rs0;
        l1 = l1 * a1 + rs1;

        __syncwarp();

        // O += P V : A = P[q][key], B = Vt[d][key] (col-major over key)
#pragma unroll
        for (int kk = 0; kk < 64; kk += 16) {
            unsigned a[4];
            a[0] = *(const unsigned*)&Ps[wq0 + r][kk + 2 * c];
            a[1] = *(const unsigned*)&Ps[wq0 + r + 8][kk + 2 * c];
            a[2] = *(const unsigned*)&Ps[wq0 + r][kk + 2 * c + 8];
            a[3] = *(const unsigned*)&Ps[wq0 + r + 8][kk + 2 * c + 8];
#pragma unroll
            for (int ni = 0; ni < 8; ni++) {
                unsigned b[2];
                b[0] = *(const unsigned*)&Vt[cur][ni * 8 + r][kk + 2 * c];
                b[1] = *(const unsigned*)&Vt[cur][ni * 8 + r][kk + 2 * c + 8];
                mma_f16(o[ni], a, b);
            }
        }
    }

    // epilogue: normalize, write out (n, l, h*64+dd) fp32
    float inv0 = 1.f / l0, inv1 = 1.f / l1;
#pragma unroll
    for (int ni = 0; ni < 8; ni++) {
        int dcol = h * HD + ni * 8 + c * 2;
        float* y0 = out + ((size_t)n * LQS + row0) * DM + dcol;
        float* y1 = out + ((size_t)n * LQS + row1) * DM + dcol;
        *(float2*)y0 = make_float2(o[ni][0] * inv0, o[ni][1] * inv0);
        *(float2*)y1 = make_float2(o[ni][2] * inv1, o[ni][3] * inv1);
    }
}

// ---------------------------------------------------------------------------
extern "C" void kernel_launch(void* const* d_in, const int* in_sizes, int n_in,
                              void* d_out, int out_size) {
    const float* query = (const float*)d_in[0];
    const float* key   = (const float*)d_in[1];
    const float* Wq    = (const float*)d_in[2];
    const float* Wk    = (const float*)d_in[3];
    const float* Wv    = (const float*)d_in[4];
    const int* pad     = (const int*)d_in[6];   // bool -> int32
    float* out = (float*)d_out;

    const int proj_smem = 4 * 128 * PKP * 4;  // 73728 B
    cudaFuncSetAttribute(proj_mma,
                         cudaFuncAttributeMaxDynamicSharedMemorySize, proj_smem);
    const int attn_smem = SMH_TOT * 2;        // 73728 B
    cudaFuncSetAttribute(attn_mma,
                         cudaFuncAttributeMaxDynamicSharedMemorySize, attn_smem);

    void *pq, *pk, *pv;
    cudaGetSymbolAddress(&pq, g_q);
    cudaGetSymbolAddress(&pk, g_k);
    cudaGetSymbolAddress(&pv, g_v);

    count_kernel<<<NB, 256>>>(pad);

    dim3 pg(DM / 128, (NB * LQS) / 128, 3);  // (8, 32, 3)
    proj_mma<<<pg, 256, proj_smem>>>(query, key, Wq, Wk, Wv,
                                     (__half*)pq, (__half*)pk, (__half*)pv);

    dim3 ag(LQS / 128, NH, NB);  // (16, 16, 2)
    attn_mma<<<ag, 256, attn_smem>>>(out);
}

// round 10
// speedup vs baseline: 4.4306x; 1.0267x over previous
#include <cuda_runtime.h>
#include <cuda_fp16.h>

#define NB 2
#define LQS 2048
#define LKS 2048
#define DM 1024
#define NH 16
#define HD 64

// Scratch: Q/K in (n, h, l, dd) fp16; V in (n, h, dd, l) fp16 (transposed)
__device__ __half g_q[NB * NH * LQS * HD];
__device__ __half g_k[NB * NH * LKS * HD];
__device__ __half g_v[NB * NH * LKS * HD];
__device__ float g_scale[8];
__device__ int   g_len[8];

// ---- mma helpers ----------------------------------------------------------
__device__ __forceinline__ unsigned f2tf(float v) {
    unsigned r; asm("cvt.rna.tf32.f32 %0, %1;" : "=r"(r) : "f"(v)); return r;
}
__device__ __forceinline__ void mma_tf32(float d[4], const unsigned a[4],
                                         const unsigned b[2]) {
    asm volatile(
        "mma.sync.aligned.m16n8k8.row.col.f32.tf32.tf32.f32 "
        "{%0,%1,%2,%3}, {%4,%5,%6,%7}, {%8,%9}, {%0,%1,%2,%3};"
        : "+f"(d[0]), "+f"(d[1]), "+f"(d[2]), "+f"(d[3])
        : "r"(a[0]), "r"(a[1]), "r"(a[2]), "r"(a[3]), "r"(b[0]), "r"(b[1]));
}
__device__ __forceinline__ void mma_f16(float d[4], const unsigned a[4],
                                        const unsigned b[2]) {
    asm volatile(
        "mma.sync.aligned.m16n8k16.row.col.f32.f16.f16.f32 "
        "{%0,%1,%2,%3}, {%4,%5,%6,%7}, {%8,%9}, {%0,%1,%2,%3};"
        : "+f"(d[0]), "+f"(d[1]), "+f"(d[2]), "+f"(d[3])
        : "r"(a[0]), "r"(a[1]), "r"(a[2]), "r"(a[3]), "r"(b[0]), "r"(b[1]));
}
__device__ __forceinline__ unsigned packh2(float lo, float hi) {
    __half2 h = __floats2half2_rn(lo, hi);
    return *(unsigned*)&h;
}
__device__ __forceinline__ void cp16(void* dst, const void* src) {
    unsigned d = (unsigned)__cvta_generic_to_shared(dst);
    asm volatile("cp.async.cg.shared.global [%0], [%1], 16;" :: "r"(d), "l"(src));
}
#define CP_COMMIT() asm volatile("cp.async.commit_group;" ::: "memory")
#define CP_WAIT_ALL() asm volatile("cp.async.wait_group 0;" ::: "memory")

// ---------------------------------------------------------------------------
// Count valid keys per batch
// ---------------------------------------------------------------------------
__global__ void count_kernel(const int* __restrict__ pad) {
    int n = blockIdx.x;
    __shared__ int cnt;
    if (threadIdx.x == 0) cnt = 0;
    __syncthreads();
    int c = 0;
    for (int i = threadIdx.x; i < LKS; i += blockDim.x)
        if (pad[n * LKS + i] == 0) c++;
    atomicAdd(&cnt, c);
    __syncthreads();
    if (threadIdx.x == 0) {
        g_len[n] = cnt;
        g_scale[n] = rsqrtf((float)cnt);
    }
}

// ---------------------------------------------------------------------------
// Fused projection GEMMs, tf32 mma + cp.async double buffering (R9).
// Epilogue converts to fp16; V (z==2) stored TRANSPOSED (n,h,dd,l).
// ---------------------------------------------------------------------------
#define PKP 36
__global__ void __launch_bounds__(256) proj_mma(
    const float* __restrict__ query, const float* __restrict__ key,
    const float* __restrict__ Wq, const float* __restrict__ Wk,
    const float* __restrict__ Wv,
    __half* __restrict__ gq, __half* __restrict__ gk, __half* __restrict__ gv) {
    extern __shared__ float sm[];
    float (*As)[128][PKP] = (float(*)[128][PKP])sm;
    float (*Bs)[128][PKP] = (float(*)[128][PKP])(sm + 2 * 128 * PKP);

    const int z = blockIdx.z;
    const float* X = (z == 0) ? query : key;
    const float* W = (z == 0) ? Wq : (z == 1) ? Wk : Wv;

    const int bm = blockIdx.y * 128;
    const int bn = blockIdx.x * 128;
    const int tid = threadIdx.x;
    const int lane = tid & 31;
    const int wid = tid >> 5;
    const int wm = (wid & 3) * 32;
    const int wn = (wid >> 2) * 64;

    float d[2][8][4];
#pragma unroll
    for (int mi = 0; mi < 2; mi++)
#pragma unroll
        for (int ni = 0; ni < 8; ni++)
#pragma unroll
            for (int q = 0; q < 4; q++) d[mi][ni][q] = 0.f;

    const int lrow = tid >> 3;
    const int lc4 = (tid & 7) * 4;

#pragma unroll
    for (int q = 0; q < 4; q++) {
        int row = lrow + q * 32;
        cp16(&As[0][row][lc4], &X[(size_t)(bm + row) * DM + lc4]);
        cp16(&Bs[0][row][lc4], &W[(size_t)(bn + row) * DM + lc4]);
    }
    CP_COMMIT();

    const int nt = DM / 32;
    const int r = lane >> 2, c = lane & 3;

    for (int t = 0; t < nt; t++) {
        const int cur = t & 1;
        CP_WAIT_ALL();
        __syncthreads();
        if (t + 1 < nt) {
            const int nxt = cur ^ 1;
            const int k0 = (t + 1) * 32;
#pragma unroll
            for (int q = 0; q < 4; q++) {
                int row = lrow + q * 32;
                cp16(&As[nxt][row][lc4], &X[(size_t)(bm + row) * DM + k0 + lc4]);
                cp16(&Bs[nxt][row][lc4], &W[(size_t)(bn + row) * DM + k0 + lc4]);
            }
            CP_COMMIT();
        }
#pragma unroll
        for (int kk = 0; kk < 32; kk += 8) {
            unsigned a[2][4], b[8][2];
#pragma unroll
            for (int mi = 0; mi < 2; mi++) {
                int rb = wm + mi * 16;
                a[mi][0] = f2tf(As[cur][rb + r][kk + c]);
                a[mi][1] = f2tf(As[cur][rb + r + 8][kk + c]);
                a[mi][2] = f2tf(As[cur][rb + r][kk + c + 4]);
                a[mi][3] = f2tf(As[cur][rb + r + 8][kk + c + 4]);
            }
#pragma unroll
            for (int ni = 0; ni < 8; ni++) {
                int cb = wn + ni * 8;
                b[ni][0] = f2tf(Bs[cur][cb + r][kk + c]);
                b[ni][1] = f2tf(Bs[cur][cb + r][kk + c + 4]);
            }
#pragma unroll
            for (int mi = 0; mi < 2; mi++)
#pragma unroll
                for (int ni = 0; ni < 8; ni++)
                    mma_tf32(d[mi][ni], a[mi], b[ni]);
        }
    }

#pragma unroll
    for (int mi = 0; mi < 2; mi++) {
#pragma unroll
        for (int ni = 0; ni < 8; ni++) {
            int m0 = bm + wm + mi * 16 + (lane >> 2);
            int col = bn + wn + ni * 8 + (lane & 3) * 2;
            int n = m0 >> 11;
            int h = col >> 6;
            int dd = col & 63;
            int l0 = m0 & (LQS - 1);
            __half h0 = __float2half_rn(d[mi][ni][0]);
            __half h1 = __float2half_rn(d[mi][ni][1]);
            __half h2 = __float2half_rn(d[mi][ni][2]);
            __half h3 = __float2half_rn(d[mi][ni][3]);
            if (z == 2) {
                size_t base = ((size_t)(n * NH + h) * HD + dd) * LKS;
                gv[base + l0] = h0;
                gv[base + LKS + l0] = h1;
                gv[base + l0 + 8] = h2;
                gv[base + LKS + l0 + 8] = h3;
            } else {
                __half* Y = (z == 0) ? gq : gk;
                __half* y0 = &Y[((size_t)((n * NH + h) * LQS) + l0) * HD + dd];
                __half* y1 = &Y[((size_t)((n * NH + h) * LQS) + l0 + 8) * HD + dd];
                *(__half2*)y0 = __halves2half2(h0, h1);
                *(__half2*)y1 = __halves2half2(h2, h3);
            }
        }
    }
}

// ---------------------------------------------------------------------------
// Flash attention, fp16 mma m16n8k16, cp.async double-buffered K/V,
// Q fragments and P held in REGISTERS (no P smem, no Q reload).
// block = (128-q tile, head, batch), 256 thr, 8 warps (16 q rows each).
// ---------------------------------------------------------------------------
#define HS 72       // halves per row
#define SMH_Q 0                        // Qs[128][HS] (staging only)
#define SMH_K (SMH_Q + 128 * HS)       // Ks[2][64][HS]
#define SMH_V (SMH_K + 2 * 64 * HS)    // Vt[2][64][HS]
#define SMH_TOT (SMH_V + 2 * 64 * HS)  // halves (27648 -> 55296 B)

__global__ void __launch_bounds__(256) attn_mma(float* __restrict__ out) {
    extern __shared__ __half smh[];
    __half (*Qs)[HS] = (__half(*)[HS])(smh + SMH_Q);
    __half (*Ks)[64][HS] = (__half(*)[64][HS])(smh + SMH_K);
    __half (*Vt)[64][HS] = (__half(*)[64][HS])(smh + SMH_V);

    const int qt = blockIdx.x;
    const int h = blockIdx.y;
    const int n = blockIdx.z;
    const int tid = threadIdx.x;
    const int lane = tid & 31;
    const int w = tid >> 5;
    const int wq0 = w * 16;
    const int r = lane >> 2;
    const int c = lane & 3;

    // stage Q to smem (once)
    const __half* qbase = g_q + ((size_t)(n * NH + h) * LQS + qt * 128) * HD;
#pragma unroll
    for (int it = 0; it < 4; it++) {
        int e = tid + it * 256;
        int q = e >> 3, u = e & 7;
        uint4 v = *(const uint4*)&qbase[q * HD + u * 8];
        *(uint4*)&Qs[q][u * 8] = v;
    }

    const float sc = g_scale[n];
    const int len = g_len[n];
    const int ktmax = min(2 * qt + 1, (len - 1) >> 6);

    const int row0 = qt * 128 + wq0 + r;
    const int row1 = row0 + 8;

    const __half* kb0 = g_k + ((size_t)(n * NH + h) * LKS) * HD;   // [l][d]
    const __half* vb0 = g_v + ((size_t)(n * NH + h) * HD) * LKS;   // [d][l]
    const int lr = tid >> 2;
    const int ls = (tid & 3) * 16;

    // prefetch K/V tile 0
    cp16(&Ks[0][lr][ls], &kb0[(size_t)lr * HD + ls]);
    cp16(&Ks[0][lr][ls + 8], &kb0[(size_t)lr * HD + ls + 8]);
    cp16(&Vt[0][lr][ls], &vb0[(size_t)lr * LKS + ls]);
    cp16(&Vt[0][lr][ls + 8], &vb0[(size_t)lr * LKS + ls + 8]);
    CP_COMMIT();

    // Q fragments -> registers (invariant over kt)
    __syncthreads();
    unsigned qa[4][4];
#pragma unroll
    for (int j = 0; j < 4; j++) {
        int kk = j * 16;
        qa[j][0] = *(const unsigned*)&Qs[wq0 + r][kk + 2 * c];
        qa[j][1] = *(const unsigned*)&Qs[wq0 + r + 8][kk + 2 * c];
        qa[j][2] = *(const unsigned*)&Qs[wq0 + r][kk + 2 * c + 8];
        qa[j][3] = *(const unsigned*)&Qs[wq0 + r + 8][kk + 2 * c + 8];
    }

    float m0 = -1e30f, m1 = -1e30f, l0 = 0.f, l1 = 0.f;
    float o[8][4];
#pragma unroll
    for (int ni = 0; ni < 8; ni++)
#pragma unroll
        for (int q = 0; q < 4; q++) o[ni][q] = 0.f;

    for (int kt = 0; kt <= ktmax; kt++) {
        const int cur = kt & 1;
        CP_WAIT_ALL();
        __syncthreads();
        if (kt + 1 <= ktmax) {
            const int nxt = cur ^ 1;
            const size_t ko = (size_t)(kt + 1) * 64;
            cp16(&Ks[nxt][lr][ls], &kb0[(ko + lr) * HD + ls]);
            cp16(&Ks[nxt][lr][ls + 8], &kb0[(ko + lr) * HD + ls + 8]);
            cp16(&Vt[nxt][lr][ls], &vb0[(size_t)lr * LKS + ko + ls]);
            cp16(&Vt[nxt][lr][ls + 8], &vb0[(size_t)lr * LKS + ko + ls + 8]);
            CP_COMMIT();
        }

        // S = Q K^T
        float s[8][4];
#pragma unroll
        for (int ni = 0; ni < 8; ni++)
#pragma unroll
            for (int q = 0; q < 4; q++) s[ni][q] = 0.f;
#pragma unroll
        for (int j = 0; j < 4; j++) {
            int kk = j * 16;
#pragma unroll
            for (int ni = 0; ni < 8; ni++) {
                unsigned b[2];
                b[0] = *(const unsigned*)&Ks[cur][ni * 8 + r][kk + 2 * c];
                b[1] = *(const unsigned*)&Ks[cur][ni * 8 + r][kk + 2 * c + 8];
                mma_f16(s[ni], qa[j], b);
            }
        }

        // mask + scale + online softmax (P stays in registers)
        float tmax0 = -1e30f, tmax1 = -1e30f;
#pragma unroll
        for (int ni = 0; ni < 8; ni++) {
            int kg = kt * 64 + ni * 8 + c * 2;
            bool mA = (kg >= len);
            bool mB = (kg + 1 >= len);
            float v0 = (kg > row0 || mA) ? -1e30f : s[ni][0] * sc;
            float v1 = (kg + 1 > row0 || mB) ? -1e30f : s[ni][1] * sc;
            float v2 = (kg > row1 || mA) ? -1e30f : s[ni][2] * sc;
            float v3 = (kg + 1 > row1 || mB) ? -1e30f : s[ni][3] * sc;
            s[ni][0] = v0; s[ni][1] = v1; s[ni][2] = v2; s[ni][3] = v3;
            tmax0 = fmaxf(tmax0, fmaxf(v0, v1));
            tmax1 = fmaxf(tmax1, fmaxf(v2, v3));
        }
        tmax0 = fmaxf(tmax0, __shfl_xor_sync(0xffffffffu, tmax0, 1));
        tmax0 = fmaxf(tmax0, __shfl_xor_sync(0xffffffffu, tmax0, 2));
        tmax1 = fmaxf(tmax1, __shfl_xor_sync(0xffffffffu, tmax1, 1));
        tmax1 = fmaxf(tmax1, __shfl_xor_sync(0xffffffffu, tmax1, 2));

        float nm0 = fmaxf(m0, tmax0), nm1 = fmaxf(m1, tmax1);
        float a0 = __expf(m0 - nm0), a1 = __expf(m1 - nm1);
        m0 = nm0; m1 = nm1;

        float rs0 = 0.f, rs1 = 0.f;
#pragma unroll
        for (int ni = 0; ni < 8; ni++) {
            float p0 = __expf(s[ni][0] - nm0);
            float p1 = __expf(s[ni][1] - nm0);
            float p2 = __expf(s[ni][2] - nm1);
            float p3 = __expf(s[ni][3] - nm1);
            rs0 += p0 + p1; rs1 += p2 + p3;
            s[ni][0] = p0; s[ni][1] = p1; s[ni][2] = p2; s[ni][3] = p3;
#pragma unroll
            for (int q = 0; q < 2; q++) { o[ni][q] *= a0; o[ni][q + 2] *= a1; }
        }
        rs0 += __shfl_xor_sync(0xffffffffu, rs0, 1);
        rs0 += __shfl_xor_sync(0xffffffffu, rs0, 2);
        rs1 += __shfl_xor_sync(0xffffffffu, rs1, 1);
        rs1 += __shfl_xor_sync(0xffffffffu, rs1, 2);
        l0 = l0 * a0 + rs0;
        l1 = l1 * a1 + rs1;

        // O += P V : P C-frags map directly onto A-frags (no smem roundtrip)
#pragma unroll
        for (int j = 0; j < 4; j++) {
            unsigned pa[4];
            pa[0] = packh2(s[2 * j][0], s[2 * j][1]);
            pa[1] = packh2(s[2 * j][2], s[2 * j][3]);
            pa[2] = packh2(s[2 * j + 1][0], s[2 * j + 1][1]);
            pa[3] = packh2(s[2 * j + 1][2], s[2 * j + 1][3]);
            int kk = j * 16;
#pragma unroll
            for (int ni = 0; ni < 8; ni++) {
                unsigned b[2];
                b[0] = *(const unsigned*)&Vt[cur][ni * 8 + r][kk + 2 * c];
                b[1] = *(const unsigned*)&Vt[cur][ni * 8 + r][kk + 2 * c + 8];
                mma_f16(o[ni], pa, b);
            }
        }
    }

    // epilogue: normalize, write out (n, l, h*64+dd) fp32
    float inv0 = 1.f / l0, inv1 = 1.f / l1;
#pragma unroll
    for (int ni = 0; ni < 8; ni++) {
        int dcol = h * HD + ni * 8 + c * 2;
        float* y0 = out + ((size_t)n * LQS + row0) * DM + dcol;
        float* y1 = out + ((size_t)n * LQS + row1) * DM + dcol;
        *(float2*)y0 = make_float2(o[ni][0] * inv0, o[ni][1] * inv0);
        *(float2*)y1 = make_float2(o[ni][2] * inv1, o[ni][3] * inv1);
    }
}

// ---------------------------------------------------------------------------
extern "C" void kernel_launch(void* const* d_in, const int* in_sizes, int n_in,
                              void* d_out, int out_size) {
    const float* query = (const float*)d_in[0];
    const float* key   = (const float*)d_in[1];
    const float* Wq    = (const float*)d_in[2];
    const float* Wk    = (const float*)d_in[3];
    const float* Wv    = (const float*)d_in[4];
    const int* pad     = (const int*)d_in[6];   // bool -> int32
    float* out = (float*)d_out;

    const int proj_smem = 4 * 128 * PKP * 4;  // 73728 B
    cudaFuncSetAttribute(proj_mma,
                         cudaFuncAttributeMaxDynamicSharedMemorySize, proj_smem);
    const int attn_smem = SMH_TOT * 2;        // 55296 B
    cudaFuncSetAttribute(attn_mma,
                         cudaFuncAttributeMaxDynamicSharedMemorySize, attn_smem);

    void *pq, *pk, *pv;
    cudaGetSymbolAddress(&pq, g_q);
    cudaGetSymbolAddress(&pk, g_k);
    cudaGetSymbolAddress(&pv, g_v);

    count_kernel<<<NB, 256>>>(pad);

    dim3 pg(DM / 128, (NB * LQS) / 128, 3);  // (8, 32, 3)
    proj_mma<<<pg, 256, proj_smem>>>(query, key, Wq, Wk, Wv,
                                     (__half*)pq, (__half*)pk, (__half*)pv);

    dim3 ag(LQS / 128, NH, NB);  // (16, 16, 2)
    attn_mma<<<ag, 256, attn_smem>>>(out);
}

// round 12
// speedup vs baseline: 4.8336x; 1.0909x over previous
#include <cuda_runtime.h>
#include <cuda_fp16.h>

#define NB 2
#define LQS 2048
#define LKS 2048
#define DM 1024
#define NH 16
#define HD 64

// Scratch: Q/K in (n, h, l, dd) fp16; V in (n, h, dd, l) fp16 (transposed)
__device__ __half g_q[NB * NH * LQS * HD];
__device__ __half g_k[NB * NH * LKS * HD];
__device__ __half g_v[NB * NH * LKS * HD];
__device__ float g_scale[8];
__device__ int   g_len[8];

// ---- mma helpers ----------------------------------------------------------
__device__ __forceinline__ unsigned f2tf(float v) {
    unsigned r; asm("cvt.rna.tf32.f32 %0, %1;" : "=r"(r) : "f"(v)); return r;
}
__device__ __forceinline__ void mma_tf32(float d[4], const unsigned a[4],
                                         const unsigned b[2]) {
    asm volatile(
        "mma.sync.aligned.m16n8k8.row.col.f32.tf32.tf32.f32 "
        "{%0,%1,%2,%3}, {%4,%5,%6,%7}, {%8,%9}, {%0,%1,%2,%3};"
        : "+f"(d[0]), "+f"(d[1]), "+f"(d[2]), "+f"(d[3])
        : "r"(a[0]), "r"(a[1]), "r"(a[2]), "r"(a[3]), "r"(b[0]), "r"(b[1]));
}
__device__ __forceinline__ void mma_f16(float d[4], const unsigned a[4],
                                        const unsigned b[2]) {
    asm volatile(
        "mma.sync.aligned.m16n8k16.row.col.f32.f16.f16.f32 "
        "{%0,%1,%2,%3}, {%4,%5,%6,%7}, {%8,%9}, {%0,%1,%2,%3};"
        : "+f"(d[0]), "+f"(d[1]), "+f"(d[2]), "+f"(d[3])
        : "r"(a[0]), "r"(a[1]), "r"(a[2]), "r"(a[3]), "r"(b[0]), "r"(b[1]));
}
__device__ __forceinline__ unsigned packh2(float lo, float hi) {
    __half2 h = __floats2half2_rn(lo, hi);
    return *(unsigned*)&h;
}
__device__ __forceinline__ void cp16(void* dst, const void* src) {
    unsigned d = (unsigned)__cvta_generic_to_shared(dst);
    asm volatile("cp.async.cg.shared.global [%0], [%1], 16;" :: "r"(d), "l"(src));
}
#define CP_COMMIT() asm volatile("cp.async.commit_group;" ::: "memory")
#define CP_WAIT_ALL() asm volatile("cp.async.wait_group 0;" ::: "memory")

// ---------------------------------------------------------------------------
// Count valid keys per batch
// ---------------------------------------------------------------------------
__global__ void count_kernel(const int* __restrict__ pad) {
    int n = blockIdx.x;
    __shared__ int cnt;
    if (threadIdx.x == 0) cnt = 0;
    __syncthreads();
    int c = 0;
    for (int i = threadIdx.x; i < LKS; i += blockDim.x)
        if (pad[n * LKS + i] == 0) c++;
    atomicAdd(&cnt, c);
    __syncthreads();
    if (threadIdx.x == 0) {
        g_len[n] = cnt;
        g_scale[n] = rsqrtf((float)cnt);
    }
}

// ---------------------------------------------------------------------------
// Fused projection GEMMs, tf32 mma + cp.async double buffering (R9).
// Epilogue converts to fp16; V (z==2) stored TRANSPOSED (n,h,dd,l).
// ---------------------------------------------------------------------------
#define PKP 36
__global__ void __launch_bounds__(256) proj_mma(
    const float* __restrict__ query, const float* __restrict__ key,
    const float* __restrict__ Wq, const float* __restrict__ Wk,
    const float* __restrict__ Wv,
    __half* __restrict__ gq, __half* __restrict__ gk, __half* __restrict__ gv) {
    extern __shared__ float sm[];
    float (*As)[128][PKP] = (float(*)[128][PKP])sm;
    float (*Bs)[128][PKP] = (float(*)[128][PKP])(sm + 2 * 128 * PKP);

    const int z = blockIdx.z;
    const float* X = (z == 0) ? query : key;
    const float* W = (z == 0) ? Wq : (z == 1) ? Wk : Wv;

    const int bm = blockIdx.y * 128;
    const int bn = blockIdx.x * 128;
    const int tid = threadIdx.x;
    const int lane = tid & 31;
    const int wid = tid >> 5;
    const int wm = (wid & 3) * 32;
    const int wn = (wid >> 2) * 64;

    float d[2][8][4];
#pragma unroll
    for (int mi = 0; mi < 2; mi++)
#pragma unroll
        for (int ni = 0; ni < 8; ni++)
#pragma unroll
            for (int q = 0; q < 4; q++) d[mi][ni][q] = 0.f;

    const int lrow = tid >> 3;
    const int lc4 = (tid & 7) * 4;

#pragma unroll
    for (int q = 0; q < 4; q++) {
        int row = lrow + q * 32;
        cp16(&As[0][row][lc4], &X[(size_t)(bm + row) * DM + lc4]);
        cp16(&Bs[0][row][lc4], &W[(size_t)(bn + row) * DM + lc4]);
    }
    CP_COMMIT();

    const int nt = DM / 32;
    const int r = lane >> 2, c = lane & 3;

    for (int t = 0; t < nt; t++) {
        const int cur = t & 1;
        CP_WAIT_ALL();
        __syncthreads();
        if (t + 1 < nt) {
            const int nxt = cur ^ 1;
            const int k0 = (t + 1) * 32;
#pragma unroll
            for (int q = 0; q < 4; q++) {
                int row = lrow + q * 32;
                cp16(&As[nxt][row][lc4], &X[(size_t)(bm + row) * DM + k0 + lc4]);
                cp16(&Bs[nxt][row][lc4], &W[(size_t)(bn + row) * DM + k0 + lc4]);
            }
            CP_COMMIT();
        }
#pragma unroll
        for (int kk = 0; kk < 32; kk += 8) {
            unsigned a[2][4], b[8][2];
#pragma unroll
            for (int mi = 0; mi < 2; mi++) {
                int rb = wm + mi * 16;
                a[mi][0] = f2tf(As[cur][rb + r][kk + c]);
                a[mi][1] = f2tf(As[cur][rb + r + 8][kk + c]);
                a[mi][2] = f2tf(As[cur][rb + r][kk + c + 4]);
                a[mi][3] = f2tf(As[cur][rb + r + 8][kk + c + 4]);
            }
#pragma unroll
            for (int ni = 0; ni < 8; ni++) {
                int cb = wn + ni * 8;
                b[ni][0] = f2tf(Bs[cur][cb + r][kk + c]);
                b[ni][1] = f2tf(Bs[cur][cb + r][kk + c + 4]);
            }
#pragma unroll
            for (int mi = 0; mi < 2; mi++)
#pragma unroll
                for (int ni = 0; ni < 8; ni++)
                    mma_tf32(d[mi][ni], a[mi], b[ni]);
        }
    }

#pragma unroll
    for (int mi = 0; mi < 2; mi++) {
#pragma unroll
        for (int ni = 0; ni < 8; ni++) {
            int m0 = bm + wm + mi * 16 + (lane >> 2);
            int col = bn + wn + ni * 8 + (lane & 3) * 2;
            int n = m0 >> 11;
            int h = col >> 6;
            int dd = col & 63;
            int l0 = m0 & (LQS - 1);
            __half h0 = __float2half_rn(d[mi][ni][0]);
            __half h1 = __float2half_rn(d[mi][ni][1]);
            __half h2 = __float2half_rn(d[mi][ni][2]);
            __half h3 = __float2half_rn(d[mi][ni][3]);
            if (z == 2) {
                size_t base = ((size_t)(n * NH + h) * HD + dd) * LKS;
                gv[base + l0] = h0;
                gv[base + LKS + l0] = h1;
                gv[base + l0 + 8] = h2;
                gv[base + LKS + l0 + 8] = h3;
            } else {
                __half* Y = (z == 0) ? gq : gk;
                __half* y0 = &Y[((size_t)((n * NH + h) * LQS) + l0) * HD + dd];
                __half* y1 = &Y[((size_t)((n * NH + h) * LQS) + l0 + 8) * HD + dd];
                *(__half2*)y0 = __halves2half2(h0, h1);
                *(__half2*)y1 = __halves2half2(h2, h3);
            }
        }
    }
}

// ---------------------------------------------------------------------------
// Flash attention, fp16 mma m16n8k16, cp.async double-buffered K/V,
// register-resident Q fragments and P. Each block processes the q-tile PAIR
// (bx, 15-bx): per-block work = 34 K-tiles for every block (perfect balance).
// Base-2 softmax (exp2f, scale folded into logits).
// ---------------------------------------------------------------------------
#define HS 72       // halves per row
#define SMH_Q 0                        // Qs[128][HS] (staging only)
#define SMH_K (SMH_Q + 128 * HS)       // Ks[2][64][HS]
#define SMH_V (SMH_K + 2 * 64 * HS)    // Vt[2][64][HS]
#define SMH_TOT (SMH_V + 2 * 64 * HS)  // halves (27648 -> 55296 B)
#define LOG2E 1.4426950408889634f

__global__ void __launch_bounds__(256) attn_mma(float* __restrict__ out) {
    extern __shared__ __half smh[];
    __half (*Qs)[HS] = (__half(*)[HS])(smh + SMH_Q);
    __half (*Ks)[64][HS] = (__half(*)[64][HS])(smh + SMH_K);
    __half (*Vt)[64][HS] = (__half(*)[64][HS])(smh + SMH_V);

    const int bx = blockIdx.x;          // 0..7
    const int h = blockIdx.y;
    const int n = blockIdx.z;
    const int tid = threadIdx.x;
    const int lane = tid & 31;
    const int w = tid >> 5;
    const int wq0 = w * 16;
    const int r = lane >> 2;
    const int c = lane & 3;

    const float sc2 = g_scale[n] * LOG2E;   // base-2 logit scale
    const int len = g_len[n];

    const __half* kb0 = g_k + ((size_t)(n * NH + h) * LKS) * HD;   // [l][d]
    const __half* vb0 = g_v + ((size_t)(n * NH + h) * HD) * LKS;   // [d][l]
    const int lr = tid >> 2;
    const int ls = (tid & 3) * 16;

#pragma unroll 1
    for (int pass = 0; pass < 2; pass++) {
        const int qt = pass == 0 ? bx : 15 - bx;
        const int ktmax = min(2 * qt + 1, (len - 1) >> 6);
        const int row0 = qt * 128 + wq0 + r;
        const int row1 = row0 + 8;

        // guard Qs reuse across passes
        __syncthreads();
        // stage Q to smem
        const __half* qbase =
            g_q + ((size_t)(n * NH + h) * LQS + qt * 128) * HD;
#pragma unroll
        for (int it = 0; it < 4; it++) {
            int e = tid + it * 256;
            int q = e >> 3, u = e & 7;
            uint4 v = *(const uint4*)&qbase[q * HD + u * 8];
            *(uint4*)&Qs[q][u * 8] = v;
        }

        // prefetch K/V tile 0
        cp16(&Ks[0][lr][ls], &kb0[(size_t)lr * HD + ls]);
        cp16(&Ks[0][lr][ls + 8], &kb0[(size_t)lr * HD + ls + 8]);
        cp16(&Vt[0][lr][ls], &vb0[(size_t)lr * LKS + ls]);
        cp16(&Vt[0][lr][ls + 8], &vb0[(size_t)lr * LKS + ls + 8]);
        CP_COMMIT();

        __syncthreads();
        // Q fragments -> registers
        unsigned qa[4][4];
#pragma unroll
        for (int j = 0; j < 4; j++) {
            int kk = j * 16;
            qa[j][0] = *(const unsigned*)&Qs[wq0 + r][kk + 2 * c];
            qa[j][1] = *(const unsigned*)&Qs[wq0 + r + 8][kk + 2 * c];
            qa[j][2] = *(const unsigned*)&Qs[wq0 + r][kk + 2 * c + 8];
            qa[j][3] = *(const unsigned*)&Qs[wq0 + r + 8][kk + 2 * c + 8];
        }

        float m0 = -1e30f, m1 = -1e30f, l0 = 0.f, l1 = 0.f;
        float o[8][4];
#pragma unroll
        for (int ni = 0; ni < 8; ni++)
#pragma unroll
            for (int q = 0; q < 4; q++) o[ni][q] = 0.f;

        for (int kt = 0; kt <= ktmax; kt++) {
            const int cur = kt & 1;
            CP_WAIT_ALL();
            __syncthreads();
            if (kt + 1 <= ktmax) {
                const int nxt = cur ^ 1;
                const size_t ko = (size_t)(kt + 1) * 64;
                cp16(&Ks[nxt][lr][ls], &kb0[(ko + lr) * HD + ls]);
                cp16(&Ks[nxt][lr][ls + 8], &kb0[(ko + lr) * HD + ls + 8]);
                cp16(&Vt[nxt][lr][ls], &vb0[(size_t)lr * LKS + ko + ls]);
                cp16(&Vt[nxt][lr][ls + 8], &vb0[(size_t)lr * LKS + ko + ls + 8]);
                CP_COMMIT();
            }

            // S = Q K^T
            float s[8][4];
#pragma unroll
            for (int ni = 0; ni < 8; ni++)
#pragma unroll
                for (int q = 0; q < 4; q++) s[ni][q] = 0.f;
#pragma unroll
            for (int j = 0; j < 4; j++) {
                int kk = j * 16;
#pragma unroll
                for (int ni = 0; ni < 8; ni++) {
                    unsigned b[2];
                    b[0] = *(const unsigned*)&Ks[cur][ni * 8 + r][kk + 2 * c];
                    b[1] = *(const unsigned*)&Ks[cur][ni * 8 + r][kk + 2 * c + 8];
                    mma_f16(s[ni], qa[j], b);
                }
            }

            // mask + base-2 scale + online softmax (registers only)
            float tmax0 = -1e30f, tmax1 = -1e30f;
#pragma unroll
            for (int ni = 0; ni < 8; ni++) {
                int kg = kt * 64 + ni * 8 + c * 2;
                bool mA = (kg >= len);
                bool mB = (kg + 1 >= len);
                float v0 = (kg > row0 || mA) ? -1e30f : s[ni][0] * sc2;
                float v1 = (kg + 1 > row0 || mB) ? -1e30f : s[ni][1] * sc2;
                float v2 = (kg > row1 || mA) ? -1e30f : s[ni][2] * sc2;
                float v3 = (kg + 1 > row1 || mB) ? -1e30f : s[ni][3] * sc2;
                s[ni][0] = v0; s[ni][1] = v1; s[ni][2] = v2; s[ni][3] = v3;
                tmax0 = fmaxf(tmax0, fmaxf(v0, v1));
                tmax1 = fmaxf(tmax1, fmaxf(v2, v3));
            }
            tmax0 = fmaxf(tmax0, __shfl_xor_sync(0xffffffffu, tmax0, 1));
            tmax0 = fmaxf(tmax0, __shfl_xor_sync(0xffffffffu, tmax0, 2));
            tmax1 = fmaxf(tmax1, __shfl_xor_sync(0xffffffffu, tmax1, 1));
            tmax1 = fmaxf(tmax1, __shfl_xor_sync(0xffffffffu, tmax1, 2));

            float nm0 = fmaxf(m0, tmax0), nm1 = fmaxf(m1, tmax1);
            float a0 = exp2f(m0 - nm0), a1 = exp2f(m1 - nm1);
            m0 = nm0; m1 = nm1;

            float rs0 = 0.f, rs1 = 0.f;
#pragma unroll
            for (int ni = 0; ni < 8; ni++) {
                float p0 = exp2f(s[ni][0] - nm0);
                float p1 = exp2f(s[ni][1] - nm0);
                float p2 = exp2f(s[ni][2] - nm1);
                float p3 = exp2f(s[ni][3] - nm1);
                rs0 += p0 + p1; rs1 += p2 + p3;
                s[ni][0] = p0; s[ni][1] = p1; s[ni][2] = p2; s[ni][3] = p3;
#pragma unroll
                for (int q = 0; q < 2; q++) { o[ni][q] *= a0; o[ni][q + 2] *= a1; }
            }
            rs0 += __shfl_xor_sync(0xffffffffu, rs0, 1);
            rs0 += __shfl_xor_sync(0xffffffffu, rs0, 2);
            rs1 += __shfl_xor_sync(0xffffffffu, rs1, 1);
            rs1 += __shfl_xor_sync(0xffffffffu, rs1, 2);
            l0 = l0 * a0 + rs0;
            l1 = l1 * a1 + rs1;

            // O += P V (P C-frags map directly onto A-frags)
#pragma unroll
            for (int j = 0; j < 4; j++) {
                unsigned pa[4];
                pa[0] = packh2(s[2 * j][0], s[2 * j][1]);
                pa[1] = packh2(s[2 * j][2], s[2 * j][3]);
                pa[2] = packh2(s[2 * j + 1][0], s[2 * j + 1][1]);
                pa[3] = packh2(s[2 * j + 1][2], s[2 * j + 1][3]);
                int kk = j * 16;
#pragma unroll
                for (int ni = 0; ni < 8; ni++) {
                    unsigned b[2];
                    b[0] = *(const unsigned*)&Vt[cur][ni * 8 + r][kk + 2 * c];
                    b[1] = *(const unsigned*)&Vt[cur][ni * 8 + r][kk + 2 * c + 8];
                    mma_f16(o[ni], pa, b);
                }
            }
        }

        // epilogue: normalize, write out (n, l, h*64+dd) fp32
        float inv0 = 1.f / l0, inv1 = 1.f / l1;
#pragma unroll
        for (int ni = 0; ni < 8; ni++) {
            int dcol = h * HD + ni * 8 + c * 2;
            float* y0 = out + ((size_t)n * LQS + row0) * DM + dcol;
            float* y1 = out + ((size_t)n * LQS + row1) * DM + dcol;
            *(float2*)y0 = make_float2(o[ni][0] * inv0, o[ni][1] * inv0);
            *(float2*)y1 = make_float2(o[ni][2] * inv1, o[ni][3] * inv1);
        }
    }
}

// ---------------------------------------------------------------------------
extern "C" void kernel_launch(void* const* d_in, const int* in_sizes, int n_in,
                              void* d_out, int out_size) {
    const float* query = (const float*)d_in[0];
    const float* key   = (const float*)d_in[1];
    const float* Wq    = (const float*)d_in[2];
    const float* Wk    = (const float*)d_in[3];
    const float* Wv    = (const float*)d_in[4];
    const int* pad     = (const int*)d_in[6];   // bool -> int32
    float* out = (float*)d_out;

    const int proj_smem = 4 * 128 * PKP * 4;  // 73728 B
    cudaFuncSetAttribute(proj_mma,
                         cudaFuncAttributeMaxDynamicSharedMemorySize, proj_smem);
    const int attn_smem = SMH_TOT * 2;        // 55296 B
    cudaFuncSetAttribute(attn_mma,
                         cudaFuncAttributeMaxDynamicSharedMemorySize, attn_smem);

    void *pq, *pk, *pv;
    cudaGetSymbolAddress(&pq, g_q);
    cudaGetSymbolAddress(&pk, g_k);
    cudaGetSymbolAddress(&pv, g_v);

    count_kernel<<<NB, 256>>>(pad);

    dim3 pg(DM / 128, (NB * LQS) / 128, 3);  // (8, 32, 3)
    proj_mma<<<pg, 256, proj_smem>>>(query, key, Wq, Wk, Wv,
                                     (__half*)pq, (__half*)pk, (__half*)pv);

    dim3 ag(8, NH, NB);  // 256 blocks, 34 K-tiles each
    attn_mma<<<ag, 256, attn_smem>>>(out);
}

// round 13
// speedup vs baseline: 4.8903x; 1.0117x over previous
#include <cuda_runtime.h>
#include <cuda_fp16.h>

#define NB 2
#define LQS 2048
#define LKS 2048
#define DM 1024
#define NH 16
#define HD 64

// Scratch: Q/K in (n, h, l, dd) fp16; V in (n, h, dd, l) fp16 (transposed)
__device__ __half g_q[NB * NH * LQS * HD];
__device__ __half g_k[NB * NH * LKS * HD];
__device__ __half g_v[NB * NH * LKS * HD];
__device__ float g_scale[8];
__device__ int   g_len[8];

// ---- mma helpers ----------------------------------------------------------
__device__ __forceinline__ void mma_f16(float d[4], const unsigned a[4],
                                        const unsigned b[2]) {
    asm volatile(
        "mma.sync.aligned.m16n8k16.row.col.f32.f16.f16.f32 "
        "{%0,%1,%2,%3}, {%4,%5,%6,%7}, {%8,%9}, {%0,%1,%2,%3};"
        : "+f"(d[0]), "+f"(d[1]), "+f"(d[2]), "+f"(d[3])
        : "r"(a[0]), "r"(a[1]), "r"(a[2]), "r"(a[3]), "r"(b[0]), "r"(b[1]));
}
__device__ __forceinline__ unsigned packh2(float lo, float hi) {
    __half2 h = __floats2half2_rn(lo, hi);
    return *(unsigned*)&h;
}
__device__ __forceinline__ void cp16(void* dst, const void* src) {
    unsigned d = (unsigned)__cvta_generic_to_shared(dst);
    asm volatile("cp.async.cg.shared.global [%0], [%1], 16;" :: "r"(d), "l"(src));
}
#define CP_COMMIT() asm volatile("cp.async.commit_group;" ::: "memory")
#define CP_WAIT_ALL() asm volatile("cp.async.wait_group 0;" ::: "memory")

// ---------------------------------------------------------------------------
// Fused projection GEMMs (fp16 mma m16n8k16) + cp.async double buffering.
// z in {0,1,2}: (X,W,Y) = (query,Wq,gq),(key,Wk,gk),(key,Wv,gv transposed).
// z==3 (block 0,0 only): count valid keys -> g_len/g_scale.
// ---------------------------------------------------------------------------
#define PKP 36
__global__ void __launch_bounds__(256) proj_mma(
    const float* __restrict__ query, const float* __restrict__ key,
    const float* __restrict__ Wq, const float* __restrict__ Wk,
    const float* __restrict__ Wv, const int* __restrict__ pad,
    __half* __restrict__ gq, __half* __restrict__ gk, __half* __restrict__ gv) {
    extern __shared__ float sm[];

    const int z = blockIdx.z;
    const int tid = threadIdx.x;

    if (z == 3) {
        if (blockIdx.x == 0 && blockIdx.y == 0) {
            __shared__ int cnt;
            for (int n = 0; n < NB; n++) {
                if (tid == 0) cnt = 0;
                __syncthreads();
                int c = 0;
                for (int i = tid; i < LKS; i += 256)
                    if (pad[n * LKS + i] == 0) c++;
                atomicAdd(&cnt, c);
                __syncthreads();
                if (tid == 0) {
                    g_len[n] = cnt;
                    g_scale[n] = rsqrtf((float)cnt);
                }
                __syncthreads();
            }
        }
        return;
    }

    float (*As)[128][PKP] = (float(*)[128][PKP])sm;
    float (*Bs)[128][PKP] = (float(*)[128][PKP])(sm + 2 * 128 * PKP);

    const float* X = (z == 0) ? query : key;
    const float* W = (z == 0) ? Wq : (z == 1) ? Wk : Wv;

    const int bm = blockIdx.y * 128;
    const int bn = blockIdx.x * 128;
    const int lane = tid & 31;
    const int wid = tid >> 5;
    const int wm = (wid & 3) * 32;
    const int wn = (wid >> 2) * 64;

    float d[2][8][4];
#pragma unroll
    for (int mi = 0; mi < 2; mi++)
#pragma unroll
        for (int ni = 0; ni < 8; ni++)
#pragma unroll
            for (int q = 0; q < 4; q++) d[mi][ni][q] = 0.f;

    const int lrow = tid >> 3;
    const int lc4 = (tid & 7) * 4;

#pragma unroll
    for (int q = 0; q < 4; q++) {
        int row = lrow + q * 32;
        cp16(&As[0][row][lc4], &X[(size_t)(bm + row) * DM + lc4]);
        cp16(&Bs[0][row][lc4], &W[(size_t)(bn + row) * DM + lc4]);
    }
    CP_COMMIT();

    const int nt = DM / 32;
    const int r = lane >> 2, c = lane & 3;

    for (int t = 0; t < nt; t++) {
        const int cur = t & 1;
        CP_WAIT_ALL();
        __syncthreads();
        if (t + 1 < nt) {
            const int nxt = cur ^ 1;
            const int k0 = (t + 1) * 32;
#pragma unroll
            for (int q = 0; q < 4; q++) {
                int row = lrow + q * 32;
                cp16(&As[nxt][row][lc4], &X[(size_t)(bm + row) * DM + k0 + lc4]);
                cp16(&Bs[nxt][row][lc4], &W[(size_t)(bn + row) * DM + k0 + lc4]);
            }
            CP_COMMIT();
        }
        // 2 fp16 k16-steps per 32-deep tile
#pragma unroll
        for (int kk = 0; kk < 32; kk += 16) {
            unsigned a[2][4], b[8][2];
#pragma unroll
            for (int mi = 0; mi < 2; mi++) {
                int rb = wm + mi * 16;
                float2 x0 = *(const float2*)&As[cur][rb + r][kk + 2 * c];
                float2 x1 = *(const float2*)&As[cur][rb + r + 8][kk + 2 * c];
                float2 x2 = *(const float2*)&As[cur][rb + r][kk + 2 * c + 8];
                float2 x3 = *(const float2*)&As[cur][rb + r + 8][kk + 2 * c + 8];
                a[mi][0] = packh2(x0.x, x0.y);
                a[mi][1] = packh2(x1.x, x1.y);
                a[mi][2] = packh2(x2.x, x2.y);
                a[mi][3] = packh2(x3.x, x3.y);
            }
#pragma unroll
            for (int ni = 0; ni < 8; ni++) {
                int cb = wn + ni * 8;
                float2 y0 = *(const float2*)&Bs[cur][cb + r][kk + 2 * c];
                float2 y1 = *(const float2*)&Bs[cur][cb + r][kk + 2 * c + 8];
                b[ni][0] = packh2(y0.x, y0.y);
                b[ni][1] = packh2(y1.x, y1.y);
            }
#pragma unroll
            for (int mi = 0; mi < 2; mi++)
#pragma unroll
                for (int ni = 0; ni < 8; ni++)
                    mma_f16(d[mi][ni], a[mi], b[ni]);
        }
    }

#pragma unroll
    for (int mi = 0; mi < 2; mi++) {
#pragma unroll
        for (int ni = 0; ni < 8; ni++) {
            int m0 = bm + wm + mi * 16 + (lane >> 2);
            int col = bn + wn + ni * 8 + (lane & 3) * 2;
            int n = m0 >> 11;
            int h = col >> 6;
            int dd = col & 63;
            int l0 = m0 & (LQS - 1);
            __half h0 = __float2half_rn(d[mi][ni][0]);
            __half h1 = __float2half_rn(d[mi][ni][1]);
            __half h2 = __float2half_rn(d[mi][ni][2]);
            __half h3 = __float2half_rn(d[mi][ni][3]);
            if (z == 2) {
                size_t base = ((size_t)(n * NH + h) * HD + dd) * LKS;
                gv[base + l0] = h0;
                gv[base + LKS + l0] = h1;
                gv[base + l0 + 8] = h2;
                gv[base + LKS + l0 + 8] = h3;
            } else {
                __half* Y = (z == 0) ? gq : gk;
                __half* y0 = &Y[((size_t)((n * NH + h) * LQS) + l0) * HD + dd];
                __half* y1 = &Y[((size_t)((n * NH + h) * LQS) + l0 + 8) * HD + dd];
                *(__half2*)y0 = __halves2half2(h0, h1);
                *(__half2*)y1 = __halves2half2(h2, h3);
            }
        }
    }
}

// ---------------------------------------------------------------------------
// Flash attention, fp16 mma, cp.async double-buffered K/V, register P/Q.
// Block processes q-tile pair (bx, 15-bx): 34 K-tiles/block, perfectly
// balanced. Base-2 softmax; fast paths for unmasked tiles and no-rescale.
// ---------------------------------------------------------------------------
#define HS 72       // halves per row
#define SMH_Q 0
#define SMH_K (SMH_Q + 128 * HS)
#define SMH_V (SMH_K + 2 * 64 * HS)
#define SMH_TOT (SMH_V + 2 * 64 * HS)
#define LOG2E 1.4426950408889634f

__global__ void __launch_bounds__(256) attn_mma(float* __restrict__ out) {
    extern __shared__ __half smh[];
    __half (*Qs)[HS] = (__half(*)[HS])(smh + SMH_Q);
    __half (*Ks)[64][HS] = (__half(*)[64][HS])(smh + SMH_K);
    __half (*Vt)[64][HS] = (__half(*)[64][HS])(smh + SMH_V);

    const int bx = blockIdx.x;
    const int h = blockIdx.y;
    const int n = blockIdx.z;
    const int tid = threadIdx.x;
    const int lane = tid & 31;
    const int w = tid >> 5;
    const int wq0 = w * 16;
    const int r = lane >> 2;
    const int c = lane & 3;

    const float sc2 = g_scale[n] * LOG2E;
    const int len = g_len[n];

    const __half* kb0 = g_k + ((size_t)(n * NH + h) * LKS) * HD;
    const __half* vb0 = g_v + ((size_t)(n * NH + h) * HD) * LKS;
    const int lr = tid >> 2;
    const int ls = (tid & 3) * 16;

#pragma unroll 1
    for (int pass = 0; pass < 2; pass++) {
        const int qt = pass == 0 ? bx : 15 - bx;
        const int ktmax = min(2 * qt + 1, (len - 1) >> 6);
        const int row0 = qt * 128 + wq0 + r;
        const int row1 = row0 + 8;
        const int wrow_min = qt * 128 + wq0;   // warp-uniform min q row

        __syncthreads();
        const __half* qbase =
            g_q + ((size_t)(n * NH + h) * LQS + qt * 128) * HD;
#pragma unroll
        for (int it = 0; it < 4; it++) {
            int e = tid + it * 256;
            int q = e >> 3, u = e & 7;
            uint4 v = *(const uint4*)&qbase[q * HD + u * 8];
            *(uint4*)&Qs[q][u * 8] = v;
        }

        cp16(&Ks[0][lr][ls], &kb0[(size_t)lr * HD + ls]);
        cp16(&Ks[0][lr][ls + 8], &kb0[(size_t)lr * HD + ls + 8]);
        cp16(&Vt[0][lr][ls], &vb0[(size_t)lr * LKS + ls]);
        cp16(&Vt[0][lr][ls + 8], &vb0[(size_t)lr * LKS + ls + 8]);
        CP_COMMIT();

        __syncthreads();
        unsigned qa[4][4];
#pragma unroll
        for (int j = 0; j < 4; j++) {
            int kk = j * 16;
            qa[j][0] = *(const unsigned*)&Qs[wq0 + r][kk + 2 * c];
            qa[j][1] = *(const unsigned*)&Qs[wq0 + r + 8][kk + 2 * c];
            qa[j][2] = *(const unsigned*)&Qs[wq0 + r][kk + 2 * c + 8];
            qa[j][3] = *(const unsigned*)&Qs[wq0 + r + 8][kk + 2 * c + 8];
        }

        float m0 = -1e30f, m1 = -1e30f, l0 = 0.f, l1 = 0.f;
        float o[8][4];
#pragma unroll
        for (int ni = 0; ni < 8; ni++)
#pragma unroll
            for (int q = 0; q < 4; q++) o[ni][q] = 0.f;

        for (int kt = 0; kt <= ktmax; kt++) {
            const int cur = kt & 1;
            CP_WAIT_ALL();
            __syncthreads();
            if (kt + 1 <= ktmax) {
                const int nxt = cur ^ 1;
                const size_t ko = (size_t)(kt + 1) * 64;
                cp16(&Ks[nxt][lr][ls], &kb0[(ko + lr) * HD + ls]);
                cp16(&Ks[nxt][lr][ls + 8], &kb0[(ko + lr) * HD + ls + 8]);
                cp16(&Vt[nxt][lr][ls], &vb0[(size_t)lr * LKS + ko + ls]);
                cp16(&Vt[nxt][lr][ls + 8], &vb0[(size_t)lr * LKS + ko + ls + 8]);
                CP_COMMIT();
            }

            // S = Q K^T
            float s[8][4];
#pragma unroll
            for (int ni = 0; ni < 8; ni++)
#pragma unroll
                for (int q = 0; q < 4; q++) s[ni][q] = 0.f;
#pragma unroll
            for (int j = 0; j < 4; j++) {
                int kk = j * 16;
#pragma unroll
                for (int ni = 0; ni < 8; ni++) {
                    unsigned b[2];
                    b[0] = *(const unsigned*)&Ks[cur][ni * 8 + r][kk + 2 * c];
                    b[1] = *(const unsigned*)&Ks[cur][ni * 8 + r][kk + 2 * c + 8];
                    mma_f16(s[ni], qa[j], b);
                }
            }

            // scale + mask (fast path for fully unmasked warp-tile)
            float tmax0 = -1e30f, tmax1 = -1e30f;
            const bool full = (kt * 64 + 63 <= wrow_min) && (kt * 64 + 63 < len);
            if (full) {
#pragma unroll
                for (int ni = 0; ni < 8; ni++) {
                    float v0 = s[ni][0] * sc2, v1 = s[ni][1] * sc2;
                    float v2 = s[ni][2] * sc2, v3 = s[ni][3] * sc2;
                    s[ni][0] = v0; s[ni][1] = v1; s[ni][2] = v2; s[ni][3] = v3;
                    tmax0 = fmaxf(tmax0, fmaxf(v0, v1));
                    tmax1 = fmaxf(tmax1, fmaxf(v2, v3));
                }
            } else {
#pragma unroll
                for (int ni = 0; ni < 8; ni++) {
                    int kg = kt * 64 + ni * 8 + c * 2;
                    bool mA = (kg >= len);
                    bool mB = (kg + 1 >= len);
                    float v0 = (kg > row0 || mA) ? -1e30f : s[ni][0] * sc2;
                    float v1 = (kg + 1 > row0 || mB) ? -1e30f : s[ni][1] * sc2;
                    float v2 = (kg > row1 || mA) ? -1e30f : s[ni][2] * sc2;
                    float v3 = (kg + 1 > row1 || mB) ? -1e30f : s[ni][3] * sc2;
                    s[ni][0] = v0; s[ni][1] = v1; s[ni][2] = v2; s[ni][3] = v3;
                    tmax0 = fmaxf(tmax0, fmaxf(v0, v1));
                    tmax1 = fmaxf(tmax1, fmaxf(v2, v3));
                }
            }
            tmax0 = fmaxf(tmax0, __shfl_xor_sync(0xffffffffu, tmax0, 1));
            tmax0 = fmaxf(tmax0, __shfl_xor_sync(0xffffffffu, tmax0, 2));
            tmax1 = fmaxf(tmax1, __shfl_xor_sync(0xffffffffu, tmax1, 1));
            tmax1 = fmaxf(tmax1, __shfl_xor_sync(0xffffffffu, tmax1, 2));

            float nm0 = fmaxf(m0, tmax0), nm1 = fmaxf(m1, tmax1);
            float a0 = exp2f(m0 - nm0), a1 = exp2f(m1 - nm1);
            m0 = nm0; m1 = nm1;

            float rs0 = 0.f, rs1 = 0.f;
#pragma unroll
            for (int ni = 0; ni < 8; ni++) {
                float p0 = exp2f(s[ni][0] - nm0);
                float p1 = exp2f(s[ni][1] - nm0);
                float p2 = exp2f(s[ni][2] - nm1);
                float p3 = exp2f(s[ni][3] - nm1);
                rs0 += p0 + p1; rs1 += p2 + p3;
                s[ni][0] = p0; s[ni][1] = p1; s[ni][2] = p2; s[ni][3] = p3;
            }
            if (a0 != 1.f || a1 != 1.f) {
#pragma unroll
                for (int ni = 0; ni < 8; ni++) {
                    o[ni][0] *= a0; o[ni][1] *= a0;
                    o[ni][2] *= a1; o[ni][3] *= a1;
                }
            }
            rs0 += __shfl_xor_sync(0xffffffffu, rs0, 1);
            rs0 += __shfl_xor_sync(0xffffffffu, rs0, 2);
            rs1 += __shfl_xor_sync(0xffffffffu, rs1, 1);
            rs1 += __shfl_xor_sync(0xffffffffu, rs1, 2);
            l0 = l0 * a0 + rs0;
            l1 = l1 * a1 + rs1;

            // O += P V
#pragma unroll
            for (int j = 0; j < 4; j++) {
                unsigned pa[4];
                pa[0] = packh2(s[2 * j][0], s[2 * j][1]);
                pa[1] = packh2(s[2 * j][2], s[2 * j][3]);
                pa[2] = packh2(s[2 * j + 1][0], s[2 * j + 1][1]);
                pa[3] = packh2(s[2 * j + 1][2], s[2 * j + 1][3]);
                int kk = j * 16;
#pragma unroll
                for (int ni = 0; ni < 8; ni++) {
                    unsigned b[2];
                    b[0] = *(const unsigned*)&Vt[cur][ni * 8 + r][kk + 2 * c];
                    b[1] = *(const unsigned*)&Vt[cur][ni * 8 + r][kk + 2 * c + 8];
                    mma_f16(o[ni], pa, b);
                }
            }
        }

        // epilogue
        float inv0 = 1.f / l0, inv1 = 1.f / l1;
#pragma unroll
        for (int ni = 0; ni < 8; ni++) {
            int dcol = h * HD + ni * 8 + c * 2;
            float* y0 = out + ((size_t)n * LQS + row0) * DM + dcol;
            float* y1 = out + ((size_t)n * LQS + row1) * DM + dcol;
            *(float2*)y0 = make_float2(o[ni][0] * inv0, o[ni][1] * inv0);
            *(float2*)y1 = make_float2(o[ni][2] * inv1, o[ni][3] * inv1);
        }
    }
}

// ---------------------------------------------------------------------------
extern "C" void kernel_launch(void* const* d_in, const int* in_sizes, int n_in,
                              void* d_out, int out_size) {
    const float* query = (const float*)d_in[0];
    const float* key   = (const float*)d_in[1];
    const float* Wq    = (const float*)d_in[2];
    const float* Wk    = (const float*)d_in[3];
    const float* Wv    = (const float*)d_in[4];
    const int* pad     = (const int*)d_in[6];   // bool -> int32
    float* out = (float*)d_out;

    const int proj_smem = 4 * 128 * PKP * 4;  // 73728 B
    cudaFuncSetAttribute(proj_mma,
                         cudaFuncAttributeMaxDynamicSharedMemorySize, proj_smem);
    const int attn_smem = SMH_TOT * 2;        // 55296 B
    cudaFuncSetAttribute(attn_mma,
                         cudaFuncAttributeMaxDynamicSharedMemorySize, attn_smem);

    void *pq, *pk, *pv;
    cudaGetSymbolAddress(&pq, g_q);
    cudaGetSymbolAddress(&pk, g_k);
    cudaGetSymbolAddress(&pv, g_v);

    dim3 pg(DM / 128, (NB * LQS) / 128, 4);  // z=3 slice does the count
    proj_mma<<<pg, 256, proj_smem>>>(query, key, Wq, Wk, Wv, pad,
                                     (__half*)pq, (__half*)pk, (__half*)pv);

    dim3 ag(8, NH, NB);  // 256 blocks, 34 K-tiles each
    attn_mma<<<ag, 256, attn_smem>>>(out);
}

// round 14
// speedup vs baseline: 7.9468x; 1.6250x over previous
#include <cuda_runtime.h>
#include <cuda_fp16.h>

#define NB 2
#define LQS 2048
#define LKS 2048
#define DM 1024
#define NH 16
#define HD 64

// fp16 copies of inputs (pre-converted once)
__device__ __half g_xq[NB * LQS * DM];
__device__ __half g_xk[NB * LKS * DM];
__device__ __half g_wqh[DM * DM];
__device__ __half g_wkh[DM * DM];
__device__ __half g_wvh[DM * DM];
// Scratch: Q/K in (n, h, l, dd) fp16; V in (n, h, dd, l) fp16 (transposed)
__device__ __half g_q[NB * NH * LQS * HD];
__device__ __half g_k[NB * NH * LKS * HD];
__device__ __half g_v[NB * NH * LKS * HD];
__device__ float g_scale[8];
__device__ int   g_len[8];

// ---- mma / ldmatrix helpers ------------------------------------------------
__device__ __forceinline__ void mma_f16(float d[4], const unsigned a[4],
                                        const unsigned b[2]) {
    asm volatile(
        "mma.sync.aligned.m16n8k16.row.col.f32.f16.f16.f32 "
        "{%0,%1,%2,%3}, {%4,%5,%6,%7}, {%8,%9}, {%0,%1,%2,%3};"
        : "+f"(d[0]), "+f"(d[1]), "+f"(d[2]), "+f"(d[3])
        : "r"(a[0]), "r"(a[1]), "r"(a[2]), "r"(a[3]), "r"(b[0]), "r"(b[1]));
}
__device__ __forceinline__ unsigned packh2(float lo, float hi) {
    __half2 h = __floats2half2_rn(lo, hi);
    return *(unsigned*)&h;
}
__device__ __forceinline__ void ldsm4(unsigned& r0, unsigned& r1,
                                      unsigned& r2, unsigned& r3,
                                      const void* p) {
    unsigned addr = (unsigned)__cvta_generic_to_shared(p);
    asm volatile(
        "ldmatrix.sync.aligned.m8n8.x4.shared.b16 {%0,%1,%2,%3}, [%4];"
        : "=r"(r0), "=r"(r1), "=r"(r2), "=r"(r3) : "r"(addr));
}
__device__ __forceinline__ void cp16(void* dst, const void* src) {
    unsigned d = (unsigned)__cvta_generic_to_shared(dst);
    asm volatile("cp.async.cg.shared.global [%0], [%1], 16;" :: "r"(d), "l"(src));
}
#define CP_COMMIT() asm volatile("cp.async.commit_group;" ::: "memory")
#define CP_WAIT_ALL() asm volatile("cp.async.wait_group 0;" ::: "memory")

// ---------------------------------------------------------------------------
// fp32 -> fp16 pre-conversion. grid (2048, 5); y selects tensor.
// ---------------------------------------------------------------------------
__global__ void __launch_bounds__(256) cvt_kernel(
    const float* __restrict__ q, const float* __restrict__ k,
    const float* __restrict__ wq, const float* __restrict__ wk,
    const float* __restrict__ wv) {
    const int y = blockIdx.y;
    const float* src = (y == 0) ? q : (y == 1) ? k : (y == 2) ? wq
                     : (y == 3) ? wk : wv;
    __half* dst = (y == 0) ? g_xq : (y == 1) ? g_xk : (y == 2) ? g_wqh
                : (y == 3) ? g_wkh : g_wvh;
    const int n = (y < 2) ? NB * LQS * DM : DM * DM;
    int i = (blockIdx.x * 256 + threadIdx.x) * 8;
    if (i >= n) return;
    float4 v0 = *(const float4*)(src + i);
    float4 v1 = *(const float4*)(src + i + 4);
    unsigned u0 = packh2(v0.x, v0.y), u1 = packh2(v0.z, v0.w);
    unsigned u2 = packh2(v1.x, v1.y), u3 = packh2(v1.z, v1.w);
    *(uint4*)(dst + i) = make_uint4(u0, u1, u2, u3);
}

// ---------------------------------------------------------------------------
// Fused projection GEMMs, fp16 end-to-end: fp16 smem tiles (K-depth 64),
// cp.async double buffering, ldmatrix fragment loads, fp16 mma.
// z in {0,1,2}: GEMMs; z==3 (block 0,0): count valid keys.
// ---------------------------------------------------------------------------
#define PS 72   // halves per smem row
__global__ void __launch_bounds__(256) proj_mma(const int* __restrict__ pad) {
    extern __shared__ __half smp[];

    const int z = blockIdx.z;
    const int tid = threadIdx.x;

    if (z == 3) {
        if (blockIdx.x == 0 && blockIdx.y == 0) {
            __shared__ int cnt;
            for (int n = 0; n < NB; n++) {
                if (tid == 0) cnt = 0;
                __syncthreads();
                int c = 0;
                for (int i = tid; i < LKS; i += 256)
                    if (pad[n * LKS + i] == 0) c++;
                atomicAdd(&cnt, c);
                __syncthreads();
                if (tid == 0) {
                    g_len[n] = cnt;
                    g_scale[n] = rsqrtf((float)cnt);
                }
                __syncthreads();
            }
        }
        return;
    }

    __half (*As)[128][PS] = (__half(*)[128][PS])smp;
    __half (*Bs)[128][PS] = (__half(*)[128][PS])(smp + 2 * 128 * PS);

    const __half* X = (z == 0) ? g_xq : g_xk;
    const __half* W = (z == 0) ? g_wqh : (z == 1) ? g_wkh : g_wvh;

    const int bm = blockIdx.y * 128;
    const int bn = blockIdx.x * 128;
    const int lane = tid & 31;
    const int wid = tid >> 5;
    const int wm = (wid & 3) * 32;
    const int wn = (wid >> 2) * 64;

    float d[2][8][4];
#pragma unroll
    for (int mi = 0; mi < 2; mi++)
#pragma unroll
        for (int ni = 0; ni < 8; ni++)
#pragma unroll
            for (int q = 0; q < 4; q++) d[mi][ni][q] = 0.f;

    // cp.async indexing: 1024 16B segments per tensor per tile
    // seg -> row = seg>>3, half-offset = (seg&7)*8
    // prefetch tile 0
#pragma unroll
    for (int it = 0; it < 4; it++) {
        int seg = tid + it * 256;
        int row = seg >> 3, o8 = (seg & 7) * 8;
        cp16(&As[0][row][o8], &X[(size_t)(bm + row) * DM + o8]);
        cp16(&Bs[0][row][o8], &W[(size_t)(bn + row) * DM + o8]);
    }
    CP_COMMIT();

    // ldmatrix lane addressing
    const int t8 = lane & 7, g = lane >> 3;
    const int a_ro = (g & 1) * 8 + t8, a_co = (g >> 1) * 8;
    const int b_ro = (g >> 1) * 8 + t8, b_co = (g & 1) * 8;

    const int nt = DM / 64;   // 16 tiles
    for (int t = 0; t < nt; t++) {
        const int cur = t & 1;
        CP_WAIT_ALL();
        __syncthreads();
        if (t + 1 < nt) {
            const int nxt = cur ^ 1;
            const int k0 = (t + 1) * 64;
#pragma unroll
            for (int it = 0; it < 4; it++) {
                int seg = tid + it * 256;
                int row = seg >> 3, o8 = (seg & 7) * 8;
                cp16(&As[nxt][row][o8], &X[(size_t)(bm + row) * DM + k0 + o8]);
                cp16(&Bs[nxt][row][o8], &W[(size_t)(bn + row) * DM + k0 + o8]);
            }
            CP_COMMIT();
        }
#pragma unroll
        for (int j = 0; j < 4; j++) {
            const int kk = j * 16;
            unsigned a[2][4], b[8][2];
#pragma unroll
            for (int mi = 0; mi < 2; mi++)
                ldsm4(a[mi][0], a[mi][1], a[mi][2], a[mi][3],
                      &As[cur][wm + mi * 16 + a_ro][kk + a_co]);
#pragma unroll
            for (int nb = 0; nb < 4; nb++)
                ldsm4(b[2 * nb][0], b[2 * nb][1], b[2 * nb + 1][0],
                      b[2 * nb + 1][1],
                      &Bs[cur][wn + nb * 16 + b_ro][kk + b_co]);
#pragma unroll
            for (int mi = 0; mi < 2; mi++)
#pragma unroll
                for (int ni = 0; ni < 8; ni++)
                    mma_f16(d[mi][ni], a[mi], b[ni]);
        }
    }

    // epilogue: scatter to (n,h,l,dd); V (z==2) transposed (n,h,dd,l)
#pragma unroll
    for (int mi = 0; mi < 2; mi++) {
#pragma unroll
        for (int ni = 0; ni < 8; ni++) {
            int m0 = bm + wm + mi * 16 + (lane >> 2);
            int col = bn + wn + ni * 8 + (lane & 3) * 2;
            int n = m0 >> 11;
            int h = col >> 6;
            int dd = col & 63;
            int l0 = m0 & (LQS - 1);
            __half h0 = __float2half_rn(d[mi][ni][0]);
            __half h1 = __float2half_rn(d[mi][ni][1]);
            __half h2 = __float2half_rn(d[mi][ni][2]);
            __half h3 = __float2half_rn(d[mi][ni][3]);
            if (z == 2) {
                size_t base = ((size_t)(n * NH + h) * HD + dd) * LKS;
                g_v[base + l0] = h0;
                g_v[base + LKS + l0] = h1;
                g_v[base + l0 + 8] = h2;
                g_v[base + LKS + l0 + 8] = h3;
            } else {
                __half* Y = (z == 0) ? g_q : g_k;
                __half* y0 = &Y[((size_t)((n * NH + h) * LQS) + l0) * HD + dd];
                __half* y1 = &Y[((size_t)((n * NH + h) * LQS) + l0 + 8) * HD + dd];
                *(__half2*)y0 = __halves2half2(h0, h1);
                *(__half2*)y1 = __halves2half2(h2, h3);
            }
        }
    }
}

// ---------------------------------------------------------------------------
// Flash attention: fp16 mma, cp.async double-buffered K/V, register P/Q,
// ldmatrix fragment loads. Block does q-tile pair (bx, 15-bx): 34 K-tiles
// per block (perfect balance). Base-2 softmax with fast paths.
// ---------------------------------------------------------------------------
#define HS 72
#define SMH_Q 0
#define SMH_K (SMH_Q + 128 * HS)
#define SMH_V (SMH_K + 2 * 64 * HS)
#define SMH_TOT (SMH_V + 2 * 64 * HS)
#define LOG2E 1.4426950408889634f

__global__ void __launch_bounds__(256) attn_mma(float* __restrict__ out) {
    extern __shared__ __half smh[];
    __half (*Qs)[HS] = (__half(*)[HS])(smh + SMH_Q);
    __half (*Ks)[64][HS] = (__half(*)[64][HS])(smh + SMH_K);
    __half (*Vt)[64][HS] = (__half(*)[64][HS])(smh + SMH_V);

    const int bx = blockIdx.x;
    const int h = blockIdx.y;
    const int n = blockIdx.z;
    const int tid = threadIdx.x;
    const int lane = tid & 31;
    const int w = tid >> 5;
    const int wq0 = w * 16;
    const int r = lane >> 2;
    const int c = lane & 3;
    const int t8 = lane & 7, g = lane >> 3;
    const int a_ro = (g & 1) * 8 + t8, a_co = (g >> 1) * 8;
    const int b_ro = (g >> 1) * 8 + t8, b_co = (g & 1) * 8;

    const float sc2 = g_scale[n] * LOG2E;
    const int len = g_len[n];

    const __half* kb0 = g_k + ((size_t)(n * NH + h) * LKS) * HD;
    const __half* vb0 = g_v + ((size_t)(n * NH + h) * HD) * LKS;
    const int lr = tid >> 2;
    const int ls = (tid & 3) * 16;

#pragma unroll 1
    for (int pass = 0; pass < 2; pass++) {
        const int qt = pass == 0 ? bx : 15 - bx;
        const int ktmax = min(2 * qt + 1, (len - 1) >> 6);
        const int row0 = qt * 128 + wq0 + r;
        const int row1 = row0 + 8;
        const int wrow_min = qt * 128 + wq0;

        __syncthreads();
        const __half* qbase =
            g_q + ((size_t)(n * NH + h) * LQS + qt * 128) * HD;
#pragma unroll
        for (int it = 0; it < 4; it++) {
            int e = tid + it * 256;
            int q = e >> 3, u = e & 7;
            uint4 v = *(const uint4*)&qbase[q * HD + u * 8];
            *(uint4*)&Qs[q][u * 8] = v;
        }

        cp16(&Ks[0][lr][ls], &kb0[(size_t)lr * HD + ls]);
        cp16(&Ks[0][lr][ls + 8], &kb0[(size_t)lr * HD + ls + 8]);
        cp16(&Vt[0][lr][ls], &vb0[(size_t)lr * LKS + ls]);
        cp16(&Vt[0][lr][ls + 8], &vb0[(size_t)lr * LKS + ls + 8]);
        CP_COMMIT();

        __syncthreads();
        unsigned qa[4][4];
#pragma unroll
        for (int j = 0; j < 4; j++)
            ldsm4(qa[j][0], qa[j][1], qa[j][2], qa[j][3],
                  &Qs[wq0 + a_ro][j * 16 + a_co]);

        float m0 = -1e30f, m1 = -1e30f, l0 = 0.f, l1 = 0.f;
        float o[8][4];
#pragma unroll
        for (int ni = 0; ni < 8; ni++)
#pragma unroll
            for (int q = 0; q < 4; q++) o[ni][q] = 0.f;

        for (int kt = 0; kt <= ktmax; kt++) {
            const int cur = kt & 1;
            CP_WAIT_ALL();
            __syncthreads();
            if (kt + 1 <= ktmax) {
                const int nxt = cur ^ 1;
                const size_t ko = (size_t)(kt + 1) * 64;
                cp16(&Ks[nxt][lr][ls], &kb0[(ko + lr) * HD + ls]);
                cp16(&Ks[nxt][lr][ls + 8], &kb0[(ko + lr) * HD + ls + 8]);
                cp16(&Vt[nxt][lr][ls], &vb0[(size_t)lr * LKS + ko + ls]);
                cp16(&Vt[nxt][lr][ls + 8], &vb0[(size_t)lr * LKS + ko + ls + 8]);
                CP_COMMIT();
            }

            // S = Q K^T
            float s[8][4];
#pragma unroll
            for (int ni = 0; ni < 8; ni++)
#pragma unroll
                for (int q = 0; q < 4; q++) s[ni][q] = 0.f;
#pragma unroll
            for (int j = 0; j < 4; j++) {
                const int kk = j * 16;
                unsigned b[8][2];
#pragma unroll
                for (int nb = 0; nb < 4; nb++)
                    ldsm4(b[2 * nb][0], b[2 * nb][1], b[2 * nb + 1][0],
                          b[2 * nb + 1][1],
                          &Ks[cur][nb * 16 + b_ro][kk + b_co]);
#pragma unroll
                for (int ni = 0; ni < 8; ni++)
                    mma_f16(s[ni], qa[j], b[ni]);
            }

            // scale + mask (fast path for fully unmasked warp-tile)
            float tmax0 = -1e30f, tmax1 = -1e30f;
            const bool full = (kt * 64 + 63 <= wrow_min) && (kt * 64 + 63 < len);
            if (full) {
#pragma unroll
                for (int ni = 0; ni < 8; ni++) {
                    float v0 = s[ni][0] * sc2, v1 = s[ni][1] * sc2;
                    float v2 = s[ni][2] * sc2, v3 = s[ni][3] * sc2;
                    s[ni][0] = v0; s[ni][1] = v1; s[ni][2] = v2; s[ni][3] = v3;
                    tmax0 = fmaxf(tmax0, fmaxf(v0, v1));
                    tmax1 = fmaxf(tmax1, fmaxf(v2, v3));
                }
            } else {
#pragma unroll
                for (int ni = 0; ni < 8; ni++) {
                    int kg = kt * 64 + ni * 8 + c * 2;
                    bool mA = (kg >= len);
                    bool mB = (kg + 1 >= len);
                    float v0 = (kg > row0 || mA) ? -1e30f : s[ni][0] * sc2;
                    float v1 = (kg + 1 > row0 || mB) ? -1e30f : s[ni][1] * sc2;
                    float v2 = (kg > row1 || mA) ? -1e30f : s[ni][2] * sc2;
                    float v3 = (kg + 1 > row1 || mB) ? -1e30f : s[ni][3] * sc2;
                    s[ni][0] = v0; s[ni][1] = v1; s[ni][2] = v2; s[ni][3] = v3;
                    tmax0 = fmaxf(tmax0, fmaxf(v0, v1));
                    tmax1 = fmaxf(tmax1, fmaxf(v2, v3));
                }
            }
            tmax0 = fmaxf(tmax0, __shfl_xor_sync(0xffffffffu, tmax0, 1));
            tmax0 = fmaxf(tmax0, __shfl_xor_sync(0xffffffffu, tmax0, 2));
            tmax1 = fmaxf(tmax1, __shfl_xor_sync(0xffffffffu, tmax1, 1));
            tmax1 = fmaxf(tmax1, __shfl_xor_sync(0xffffffffu, tmax1, 2));

            float nm0 = fmaxf(m0, tmax0), nm1 = fmaxf(m1, tmax1);
            float a0 = exp2f(m0 - nm0), a1 = exp2f(m1 - nm1);
            m0 = nm0; m1 = nm1;

            float rs0 = 0.f, rs1 = 0.f;
#pragma unroll
            for (int ni = 0; ni < 8; ni++) {
                float p0 = exp2f(s[ni][0] - nm0);
                float p1 = exp2f(s[ni][1] - nm0);
                float p2 = exp2f(s[ni][2] - nm1);
                float p3 = exp2f(s[ni][3] - nm1);
                rs0 += p0 + p1; rs1 += p2 + p3;
                s[ni][0] = p0; s[ni][1] = p1; s[ni][2] = p2; s[ni][3] = p3;
            }
            if (a0 != 1.f || a1 != 1.f) {
#pragma unroll
                for (int ni = 0; ni < 8; ni++) {
                    o[ni][0] *= a0; o[ni][1] *= a0;
                    o[ni][2] *= a1; o[ni][3] *= a1;
                }
            }
            rs0 += __shfl_xor_sync(0xffffffffu, rs0, 1);
            rs0 += __shfl_xor_sync(0xffffffffu, rs0, 2);
            rs1 += __shfl_xor_sync(0xffffffffu, rs1, 1);
            rs1 += __shfl_xor_sync(0xffffffffu, rs1, 2);
            l0 = l0 * a0 + rs0;
            l1 = l1 * a1 + rs1;

            // O += P V (register P; ldmatrix V fragments)
#pragma unroll
            for (int j = 0; j < 4; j++) {
                unsigned pa[4];
                pa[0] = packh2(s[2 * j][0], s[2 * j][1]);
                pa[1] = packh2(s[2 * j][2], s[2 * j][3]);
                pa[2] = packh2(s[2 * j + 1][0], s[2 * j + 1][1]);
                pa[3] = packh2(s[2 * j + 1][2], s[2 * j + 1][3]);
                const int kk = j * 16;
                unsigned b[8][2];
#pragma unroll
                for (int nb = 0; nb < 4; nb++)
                    ldsm4(b[2 * nb][0], b[2 * nb][1], b[2 * nb + 1][0],
                          b[2 * nb + 1][1],
                          &Vt[cur][nb * 16 + b_ro][kk + b_co]);
#pragma unroll
                for (int ni = 0; ni < 8; ni++)
                    mma_f16(o[ni], pa, b[ni]);
            }
        }

        // epilogue
        float inv0 = 1.f / l0, inv1 = 1.f / l1;
#pragma unroll
        for (int ni = 0; ni < 8; ni++) {
            int dcol = h * HD + ni * 8 + c * 2;
            float* y0 = out + ((size_t)n * LQS + row0) * DM + dcol;
            float* y1 = out + ((size_t)n * LQS + row1) * DM + dcol;
            *(float2*)y0 = make_float2(o[ni][0] * inv0, o[ni][1] * inv0);
            *(float2*)y1 = make_float2(o[ni][2] * inv1, o[ni][3] * inv1);
        }
    }
}

// ---------------------------------------------------------------------------
extern "C" void kernel_launch(void* const* d_in, const int* in_sizes, int n_in,
                              void* d_out, int out_size) {
    const float* query = (const float*)d_in[0];
    const float* key   = (const float*)d_in[1];
    const float* Wq    = (const float*)d_in[2];
    const float* Wk    = (const float*)d_in[3];
    const float* Wv    = (const float*)d_in[4];
    const int* pad     = (const int*)d_in[6];   // bool -> int32
    float* out = (float*)d_out;

    const int proj_smem = 4 * 128 * PS * 2;   // 73728 B
    cudaFuncSetAttribute(proj_mma,
                         cudaFuncAttributeMaxDynamicSharedMemorySize, proj_smem);
    const int attn_smem = SMH_TOT * 2;        // 55296 B
    cudaFuncSetAttribute(attn_mma,
                         cudaFuncAttributeMaxDynamicSharedMemorySize, attn_smem);

    dim3 cg(2048, 5);
    cvt_kernel<<<cg, 256>>>(query, key, Wq, Wk, Wv);

    dim3 pg(DM / 128, (NB * LQS) / 128, 4);  // z=3 slice does the count
    proj_mma<<<pg, 256, proj_smem>>>(pad);

    dim3 ag(8, NH, NB);  // 256 blocks, 34 K-tiles each
    attn_mma<<<ag, 256, attn_smem>>>(out);
}

// round 16
// speedup vs baseline: 7.9663x; 1.0025x over previous
#include <cuda_runtime.h>
#include <cuda_fp16.h>

#define NB 2
#define LQS 2048
#define LKS 2048
#define DM 1024
#define NH 16
#define HD 64

// fp16 copies of inputs (pre-converted once)
__device__ __half g_xq[NB * LQS * DM];
__device__ __half g_xk[NB * LKS * DM];
__device__ __half g_wqh[DM * DM];
__device__ __half g_wkh[DM * DM];
__device__ __half g_wvh[DM * DM];
// Scratch: Q/K in (n, h, l, dd) fp16; V in (n, h, dd, l) fp16 (transposed)
__device__ __half g_q[NB * NH * LQS * HD];
__device__ __half g_k[NB * NH * LKS * HD];
__device__ __half g_v[NB * NH * LKS * HD];
__device__ float g_scale[8];
__device__ int   g_len[8];

// ---- mma / ldmatrix helpers ------------------------------------------------
__device__ __forceinline__ void mma_f16(float d[4], const unsigned a[4],
                                        const unsigned b[2]) {
    asm volatile(
        "mma.sync.aligned.m16n8k16.row.col.f32.f16.f16.f32 "
        "{%0,%1,%2,%3}, {%4,%5,%6,%7}, {%8,%9}, {%0,%1,%2,%3};"
        : "+f"(d[0]), "+f"(d[1]), "+f"(d[2]), "+f"(d[3])
        : "r"(a[0]), "r"(a[1]), "r"(a[2]), "r"(a[3]), "r"(b[0]), "r"(b[1]));
}
__device__ __forceinline__ unsigned packh2(float lo, float hi) {
    __half2 h = __floats2half2_rn(lo, hi);
    return *(unsigned*)&h;
}
__device__ __forceinline__ void ldsm4(unsigned& r0, unsigned& r1,
                                      unsigned& r2, unsigned& r3,
                                      const void* p) {
    unsigned addr = (unsigned)__cvta_generic_to_shared(p);
    asm volatile(
        "ldmatrix.sync.aligned.m8n8.x4.shared.b16 {%0,%1,%2,%3}, [%4];"
        : "=r"(r0), "=r"(r1), "=r"(r2), "=r"(r3) : "r"(addr));
}
__device__ __forceinline__ void cp16(void* dst, const void* src) {
    unsigned d = (unsigned)__cvta_generic_to_shared(dst);
    asm volatile("cp.async.cg.shared.global [%0], [%1], 16;" :: "r"(d), "l"(src));
}
#define CP_COMMIT() asm volatile("cp.async.commit_group;" ::: "memory")
#define CP_WAIT_ALL() asm volatile("cp.async.wait_group 0;" ::: "memory")

// ---------------------------------------------------------------------------
// fp32 -> fp16 pre-conversion (y<5) + valid-key count (y==5).
// ---------------------------------------------------------------------------
__global__ void __launch_bounds__(256) cvt_kernel(
    const float* __restrict__ q, const float* __restrict__ k,
    const float* __restrict__ wq, const float* __restrict__ wk,
    const float* __restrict__ wv, const int* __restrict__ pad) {
    const int y = blockIdx.y;
    if (y == 5) {
        if (blockIdx.x >= NB) return;
        int n = blockIdx.x;
        __shared__ int cnt;
        if (threadIdx.x == 0) cnt = 0;
        __syncthreads();
        int c = 0;
        for (int i = threadIdx.x; i < LKS; i += 256)
            if (pad[n * LKS + i] == 0) c++;
        atomicAdd(&cnt, c);
        __syncthreads();
        if (threadIdx.x == 0) {
            g_len[n] = cnt;
            g_scale[n] = rsqrtf((float)cnt);
        }
        return;
    }
    const float* src = (y == 0) ? q : (y == 1) ? k : (y == 2) ? wq
                     : (y == 3) ? wk : wv;
    __half* dst = (y == 0) ? g_xq : (y == 1) ? g_xk : (y == 2) ? g_wqh
                : (y == 3) ? g_wkh : g_wvh;
    const int n = (y < 2) ? NB * LQS * DM : DM * DM;
    int i = (blockIdx.x * 256 + threadIdx.x) * 8;
    if (i >= n) return;
    float4 v0 = *(const float4*)(src + i);
    float4 v1 = *(const float4*)(src + i + 4);
    unsigned u0 = packh2(v0.x, v0.y), u1 = packh2(v0.z, v0.w);
    unsigned u2 = packh2(v1.x, v1.y), u3 = packh2(v1.z, v1.w);
    *(uint4*)(dst + i) = make_uint4(u0, u1, u2, u3);
}

// ---------------------------------------------------------------------------
// Fused projection GEMMs, fp16 end-to-end: fp16 smem tiles (K-depth 64),
// cp.async double buffering, ldmatrix fragment loads, fp16 mma.
// z in {0,1,2}: GEMMs.
// ---------------------------------------------------------------------------
#define PS 72   // halves per smem row
__global__ void __launch_bounds__(256) proj_mma() {
    extern __shared__ __half smp[];

    const int z = blockIdx.z;
    const int tid = threadIdx.x;

    __half (*As)[128][PS] = (__half(*)[128][PS])smp;
    __half (*Bs)[128][PS] = (__half(*)[128][PS])(smp + 2 * 128 * PS);

    const __half* X = (z == 0) ? g_xq : g_xk;
    const __half* W = (z == 0) ? g_wqh : (z == 1) ? g_wkh : g_wvh;

    const int bm = blockIdx.y * 128;
    const int bn = blockIdx.x * 128;
    const int lane = tid & 31;
    const int wid = tid >> 5;
    const int wm = (wid & 3) * 32;
    const int wn = (wid >> 2) * 64;

    float d[2][8][4];
#pragma unroll
    for (int mi = 0; mi < 2; mi++)
#pragma unroll
        for (int ni = 0; ni < 8; ni++)
#pragma unroll
            for (int q = 0; q < 4; q++) d[mi][ni][q] = 0.f;

    // prefetch tile 0
#pragma unroll
    for (int it = 0; it < 4; it++) {
        int seg = tid + it * 256;
        int row = seg >> 3, o8 = (seg & 7) * 8;
        cp16(&As[0][row][o8], &X[(size_t)(bm + row) * DM + o8]);
        cp16(&Bs[0][row][o8], &W[(size_t)(bn + row) * DM + o8]);
    }
    CP_COMMIT();

    // ldmatrix lane addressing
    const int t8 = lane & 7, g = lane >> 3;
    const int a_ro = (g & 1) * 8 + t8, a_co = (g >> 1) * 8;
    const int b_ro = (g >> 1) * 8 + t8, b_co = (g & 1) * 8;

    const int nt = DM / 64;   // 16 tiles
    for (int t = 0; t < nt; t++) {
        const int cur = t & 1;
        CP_WAIT_ALL();
        __syncthreads();
        if (t + 1 < nt) {
            const int nxt = cur ^ 1;
            const int k0 = (t + 1) * 64;
#pragma unroll
            for (int it = 0; it < 4; it++) {
                int seg = tid + it * 256;
                int row = seg >> 3, o8 = (seg & 7) * 8;
                cp16(&As[nxt][row][o8], &X[(size_t)(bm + row) * DM + k0 + o8]);
                cp16(&Bs[nxt][row][o8], &W[(size_t)(bn + row) * DM + k0 + o8]);
            }
            CP_COMMIT();
        }
#pragma unroll
        for (int j = 0; j < 4; j++) {
            const int kk = j * 16;
            unsigned a[2][4], b[8][2];
#pragma unroll
            for (int mi = 0; mi < 2; mi++)
                ldsm4(a[mi][0], a[mi][1], a[mi][2], a[mi][3],
                      &As[cur][wm + mi * 16 + a_ro][kk + a_co]);
#pragma unroll
            for (int nb = 0; nb < 4; nb++)
                ldsm4(b[2 * nb][0], b[2 * nb][1], b[2 * nb + 1][0],
                      b[2 * nb + 1][1],
                      &Bs[cur][wn + nb * 16 + b_ro][kk + b_co]);
#pragma unroll
            for (int mi = 0; mi < 2; mi++)
#pragma unroll
                for (int ni = 0; ni < 8; ni++)
                    mma_f16(d[mi][ni], a[mi], b[ni]);
        }
    }

    // epilogue: scatter to (n,h,l,dd); V (z==2) transposed (n,h,dd,l)
#pragma unroll
    for (int mi = 0; mi < 2; mi++) {
#pragma unroll
        for (int ni = 0; ni < 8; ni++) {
            int m0 = bm + wm + mi * 16 + (lane >> 2);
            int col = bn + wn + ni * 8 + (lane & 3) * 2;
            int n = m0 >> 11;
            int h = col >> 6;
            int dd = col & 63;
            int l0 = m0 & (LQS - 1);
            __half h0 = __float2half_rn(d[mi][ni][0]);
            __half h1 = __float2half_rn(d[mi][ni][1]);
            __half h2 = __float2half_rn(d[mi][ni][2]);
            __half h3 = __float2half_rn(d[mi][ni][3]);
            if (z == 2) {
                size_t base = ((size_t)(n * NH + h) * HD + dd) * LKS;
                g_v[base + l0] = h0;
                g_v[base + LKS + l0] = h1;
                g_v[base + l0 + 8] = h2;
                g_v[base + LKS + l0 + 8] = h3;
            } else {
                __half* Y = (z == 0) ? g_q : g_k;
                __half* y0 = &Y[((size_t)((n * NH + h) * LQS) + l0) * HD + dd];
                __half* y1 = &Y[((size_t)((n * NH + h) * LQS) + l0 + 8) * HD + dd];
                *(__half2*)y0 = __halves2half2(h0, h1);
                *(__half2*)y1 = __halves2half2(h2, h3);
            }
        }
    }
}

// ---------------------------------------------------------------------------
// Flash attention: fp16 mma, cp.async double-buffered K/V, register P/Q,
// ldmatrix fragments, pair-balanced blocks (bx, 15-bx), base-2 softmax.
// Q is PRE-SCALED by scale*log2e at staging time -> no per-tile S scaling.
// ---------------------------------------------------------------------------
#define HS 72
#define SMH_Q 0
#define SMH_K (SMH_Q + 128 * HS)
#define SMH_V (SMH_K + 2 * 64 * HS)
#define SMH_TOT (SMH_V + 2 * 64 * HS)
#define LOG2E 1.4426950408889634f

__global__ void __launch_bounds__(256) attn_mma(float* __restrict__ out) {
    extern __shared__ __half smh[];
    __half (*Qs)[HS] = (__half(*)[HS])(smh + SMH_Q);
    __half (*Ks)[64][HS] = (__half(*)[64][HS])(smh + SMH_K);
    __half (*Vt)[64][HS] = (__half(*)[64][HS])(smh + SMH_V);

    const int bx = blockIdx.x;
    const int h = blockIdx.y;
    const int n = blockIdx.z;
    const int tid = threadIdx.x;
    const int lane = tid & 31;
    const int w = tid >> 5;
    const int wq0 = w * 16;
    const int r = lane >> 2;
    const int c = lane & 3;
    const int t8 = lane & 7, g = lane >> 3;
    const int a_ro = (g & 1) * 8 + t8, a_co = (g >> 1) * 8;
    const int b_ro = (g >> 1) * 8 + t8, b_co = (g & 1) * 8;

    const float sc2 = g_scale[n] * LOG2E;
    const __half2 sc2h = __float2half2_rn(sc2);
    const int len = g_len[n];

    const __half* kb0 = g_k + ((size_t)(n * NH + h) * LKS) * HD;
    const __half* vb0 = g_v + ((size_t)(n * NH + h) * HD) * LKS;
    const int lr = tid >> 2;
    const int ls = (tid & 3) * 16;

#pragma unroll 1
    for (int pass = 0; pass < 2; pass++) {
        const int qt = pass == 0 ? bx : 15 - bx;
        const int ktmax = min(2 * qt + 1, (len - 1) >> 6);
        const int row0 = qt * 128 + wq0 + r;
        const int row1 = row0 + 8;
        const int wrow_min = qt * 128 + wq0;

        __syncthreads();
        const __half* qbase =
            g_q + ((size_t)(n * NH + h) * LQS + qt * 128) * HD;
#pragma unroll
        for (int it = 0; it < 4; it++) {
            int e = tid + it * 256;
            int q = e >> 3, u = e & 7;
            uint4 v = *(const uint4*)&qbase[q * HD + u * 8];
            __half2* hv = (__half2*)&v;
            hv[0] = __hmul2(hv[0], sc2h);
            hv[1] = __hmul2(hv[1], sc2h);
            hv[2] = __hmul2(hv[2], sc2h);
            hv[3] = __hmul2(hv[3], sc2h);
            *(uint4*)&Qs[q][u * 8] = v;
        }

        cp16(&Ks[0][lr][ls], &kb0[(size_t)lr * HD + ls]);
        cp16(&Ks[0][lr][ls + 8], &kb0[(size_t)lr * HD + ls + 8]);
        cp16(&Vt[0][lr][ls], &vb0[(size_t)lr * LKS + ls]);
        cp16(&Vt[0][lr][ls + 8], &vb0[(size_t)lr * LKS + ls + 8]);
        CP_COMMIT();

        __syncthreads();
        unsigned qa[4][4];
#pragma unroll
        for (int j = 0; j < 4; j++)
            ldsm4(qa[j][0], qa[j][1], qa[j][2], qa[j][3],
                  &Qs[wq0 + a_ro][j * 16 + a_co]);

        float m0 = -1e30f, m1 = -1e30f, l0 = 0.f, l1 = 0.f;
        float o[8][4];
#pragma unroll
        for (int ni = 0; ni < 8; ni++)
#pragma unroll
            for (int q = 0; q < 4; q++) o[ni][q] = 0.f;

        for (int kt = 0; kt <= ktmax; kt++) {
            const int cur = kt & 1;
            CP_WAIT_ALL();
            __syncthreads();
            if (kt + 1 <= ktmax) {
                const int nxt = cur ^ 1;
                const size_t ko = (size_t)(kt + 1) * 64;
                cp16(&Ks[nxt][lr][ls], &kb0[(ko + lr) * HD + ls]);
                cp16(&Ks[nxt][lr][ls + 8], &kb0[(ko + lr) * HD + ls + 8]);
                cp16(&Vt[nxt][lr][ls], &vb0[(size_t)lr * LKS + ko + ls]);
                cp16(&Vt[nxt][lr][ls + 8], &vb0[(size_t)lr * LKS + ko + ls + 8]);
                CP_COMMIT();
            }

            // S = Q K^T (already in base-2 logit units)
            float s[8][4];
#pragma unroll
            for (int ni = 0; ni < 8; ni++)
#pragma unroll
                for (int q = 0; q < 4; q++) s[ni][q] = 0.f;
#pragma unroll
            for (int j = 0; j < 4; j++) {
                const int kk = j * 16;
                unsigned b[8][2];
#pragma unroll
                for (int nb = 0; nb < 4; nb++)
                    ldsm4(b[2 * nb][0], b[2 * nb][1], b[2 * nb + 1][0],
                          b[2 * nb + 1][1],
                          &Ks[cur][nb * 16 + b_ro][kk + b_co]);
#pragma unroll
                for (int ni = 0; ni < 8; ni++)
                    mma_f16(s[ni], qa[j], b[ni]);
            }

            // mask + row max (no scaling needed)
            float tmax0 = -1e30f, tmax1 = -1e30f;
            const bool full = (kt * 64 + 63 <= wrow_min) && (kt * 64 + 63 < len);
            if (full) {
#pragma unroll
                for (int ni = 0; ni < 8; ni++) {
                    tmax0 = fmaxf(tmax0, fmaxf(s[ni][0], s[ni][1]));
                    tmax1 = fmaxf(tmax1, fmaxf(s[ni][2], s[ni][3]));
                }
            } else {
#pragma unroll
                for (int ni = 0; ni < 8; ni++) {
                    int kg = kt * 64 + ni * 8 + c * 2;
                    bool mA = (kg >= len);
                    bool mB = (kg + 1 >= len);
                    float v0 = (kg > row0 || mA) ? -1e30f : s[ni][0];
                    float v1 = (kg + 1 > row0 || mB) ? -1e30f : s[ni][1];
                    float v2 = (kg > row1 || mA) ? -1e30f : s[ni][2];
                    float v3 = (kg + 1 > row1 || mB) ? -1e30f : s[ni][3];
                    s[ni][0] = v0; s[ni][1] = v1; s[ni][2] = v2; s[ni][3] = v3;
                    tmax0 = fmaxf(tmax0, fmaxf(v0, v1));
                    tmax1 = fmaxf(tmax1, fmaxf(v2, v3));
                }
            }
            tmax0 = fmaxf(tmax0, __shfl_xor_sync(0xffffffffu, tmax0, 1));
            tmax0 = fmaxf(tmax0, __shfl_xor_sync(0xffffffffu, tmax0, 2));
            tmax1 = fmaxf(tmax1, __shfl_xor_sync(0xffffffffu, tmax1, 1));
            tmax1 = fmaxf(tmax1, __shfl_xor_sync(0xffffffffu, tmax1, 2));

            float nm0 = fmaxf(m0, tmax0), nm1 = fmaxf(m1, tmax1);
            float a0 = exp2f(m0 - nm0), a1 = exp2f(m1 - nm1);
            m0 = nm0; m1 = nm1;

            float rs0 = 0.f, rs1 = 0.f;
#pragma unroll
            for (int ni = 0; ni < 8; ni++) {
                float p0 = exp2f(s[ni][0] - nm0);
                float p1 = exp2f(s[ni][1] - nm0);
                float p2 = exp2f(s[ni][2] - nm1);
                float p3 = exp2f(s[ni][3] - nm1);
                rs0 += p0 + p1; rs1 += p2 + p3;
                s[ni][0] = p0; s[ni][1] = p1; s[ni][2] = p2; s[ni][3] = p3;
            }
            if (a0 != 1.f || a1 != 1.f) {
#pragma unroll
                for (int ni = 0; ni < 8; ni++) {
                    o[ni][0] *= a0; o[ni][1] *= a0;
                    o[ni][2] *= a1; o[ni][3] *= a1;
                }
            }
            rs0 += __shfl_xor_sync(0xffffffffu, rs0, 1);
            rs0 += __shfl_xor_sync(0xffffffffu, rs0, 2);
            rs1 += __shfl_xor_sync(0xffffffffu, rs1, 1);
            rs1 += __shfl_xor_sync(0xffffffffu, rs1, 2);
            l0 = l0 * a0 + rs0;
            l1 = l1 * a1 + rs1;

            // O += P V (register P; ldmatrix V fragments)
#pragma unroll
            for (int j = 0; j < 4; j++) {
                unsigned pa[4];
                pa[0] = packh2(s[2 * j][0], s[2 * j][1]);
                pa[1] = packh2(s[2 * j][2], s[2 * j][3]);
                pa[2] = packh2(s[2 * j + 1][0], s[2 * j + 1][1]);
                pa[3] = packh2(s[2 * j + 1][2], s[2 * j + 1][3]);
                const int kk = j * 16;
                unsigned b[8][2];
#pragma unroll
                for (int nb = 0; nb < 4; nb++)
                    ldsm4(b[2 * nb][0], b[2 * nb][1], b[2 * nb + 1][0],
                          b[2 * nb + 1][1],
                          &Vt[cur][nb * 16 + b_ro][kk + b_co]);
#pragma unroll
                for (int ni = 0; ni < 8; ni++)
                    mma_f16(o[ni], pa, b[ni]);
            }
        }

        // epilogue
        float inv0 = 1.f / l0, inv1 = 1.f / l1;
#pragma unroll
        for (int ni = 0; ni < 8; ni++) {
            int dcol = h * HD + ni * 8 + c * 2;
            float* y0 = out + ((size_t)n * LQS + row0) * DM + dcol;
            float* y1 = out + ((size_t)n * LQS + row1) * DM + dcol;
            *(float2*)y0 = make_float2(o[ni][0] * inv0, o[ni][1] * inv0);
            *(float2*)y1 = make_float2(o[ni][2] * inv1, o[ni][3] * inv1);
        }
    }
}

// ---------------------------------------------------------------------------
extern "C" void kernel_launch(void* const* d_in, const int* in_sizes, int n_in,
                              void* d_out, int out_size) {
    const float* query = (const float*)d_in[0];
    const float* key   = (const float*)d_in[1];
    const float* Wq    = (const float*)d_in[2];
    const float* Wk    = (const float*)d_in[3];
    const float* Wv    = (const float*)d_in[4];
    const int* pad     = (const int*)d_in[6];   // bool -> int32
    float* out = (float*)d_out;

    const int proj_smem = 4 * 128 * PS * 2;   // 73728 B
    cudaFuncSetAttribute(proj_mma,
                         cudaFuncAttributeMaxDynamicSharedMemorySize, proj_smem);
    const int attn_smem = SMH_TOT * 2;        // 55296 B
    cudaFuncSetAttribute(attn_mma,
                         cudaFuncAttributeMaxDynamicSharedMemorySize, attn_smem);

    dim3 cg(2048, 6);   // y<5: convert, y==5: count
    cvt_kernel<<<cg, 256>>>(query, key, Wq, Wk, Wv, pad);

    dim3 pg(DM / 128, (NB * LQS) / 128, 3);
    proj_mma<<<pg, 256, proj_smem>>>();

    dim3 ag(8, NH, NB);  // 256 blocks, pair-balanced
    attn_mma<<<ag, 256, attn_smem>>>(out);
}